// round 1
// baseline (speedup 1.0000x reference)
#include <cuda_runtime.h>
#include <math.h>

#define TOKENS 4096      // 2 * 2048
#define HID    1024
#define FFDIM  4096
#define SEQ    2048
#define NHEADS 16
#define DK     64

// ---------------- scratch (device globals; no allocs allowed) ----------------
__device__ float g_ln [TOKENS * HID];
__device__ float g_q  [TOKENS * HID];
__device__ float g_v  [TOKENS * HID];
__device__ float g_ctx[TOKENS * HID];
__device__ float g_x1 [TOKENS * HID];
__device__ float g_h1 [(size_t)TOKENS * FFDIM];

// ---------------- LayerNorm: one block per row ----------------
__global__ __launch_bounds__(256) void ln_kernel(
    const float* __restrict__ x, const float* __restrict__ gamma,
    const float* __restrict__ beta, float* __restrict__ out)
{
    int row = blockIdx.x;
    int t = threadIdx.x;                       // 256 threads, 4 floats each
    const float4* xr = (const float4*)(x + (size_t)row * HID);
    float4 v = xr[t];
    float s  = v.x + v.y + v.z + v.w;
    float ss = v.x*v.x + v.y*v.y + v.z*v.z + v.w*v.w;
    #pragma unroll
    for (int o = 16; o; o >>= 1) {
        s  += __shfl_xor_sync(0xffffffffu, s,  o);
        ss += __shfl_xor_sync(0xffffffffu, ss, o);
    }
    __shared__ float rs[8], rss[8];
    if ((t & 31) == 0) { rs[t >> 5] = s; rss[t >> 5] = ss; }
    __syncthreads();
    s = 0.f; ss = 0.f;
    #pragma unroll
    for (int i = 0; i < 8; i++) { s += rs[i]; ss += rss[i]; }
    float mu  = s * (1.f / HID);
    float var = ss * (1.f / HID) - mu * mu;
    float inv = rsqrtf(var + 1e-5f);
    float4 g4 = ((const float4*)gamma)[t];
    float4 b4 = ((const float4*)beta)[t];
    float4 o4;
    o4.x = (v.x - mu) * inv * g4.x + b4.x;
    o4.y = (v.y - mu) * inv * g4.y + b4.y;
    o4.z = (v.z - mu) * inv * g4.z + b4.z;
    o4.w = (v.w - mu) * inv * g4.w + b4.w;
    ((float4*)(out + (size_t)row * HID))[t] = o4;
}

// ---------------- GELU (tanh approx, matches reference) ----------------
__device__ __forceinline__ float gelu_f(float x)
{
    float u = 0.7978845608028654f * (x + 0.044715f * x * x * x);
    return 0.5f * x * (1.f + tanhf(u));
}

// ---------------- SGEMM: C = A(MxK) @ B(KxN) + bias (+res / gelu) -----------
// EPI: 0 = bias, 1 = bias + residual, 2 = gelu(bias + acc)
template <int EPI>
__global__ __launch_bounds__(256) void sgemm(
    int M, int N, int K,
    const float* __restrict__ A, const float* __restrict__ B,
    const float* __restrict__ bias, const float* __restrict__ R,
    float* __restrict__ C)
{
    const int BM = 128, BN = 128, BK = 8, TM = 8, TN = 8;
    __shared__ float As[BK][BM];
    __shared__ float Bs[BK][BN];
    int tid = threadIdx.x;
    int bx = blockIdx.x, by = blockIdx.y;
    int tx = tid & 15, ty = tid >> 4;
    int aRow = tid >> 1, aCol = (tid & 1) * 4;
    int bRow = tid >> 5, bCol = (tid & 31) * 4;
    const float* Ab = A + (size_t)by * BM * K;
    const float* Bb = B + (size_t)bx * BN;

    float acc[TM][TN] = {};
    for (int k0 = 0; k0 < K; k0 += BK) {
        float4 a4 = *(const float4*)(Ab + (size_t)aRow * K + k0 + aCol);
        As[aCol + 0][aRow] = a4.x;
        As[aCol + 1][aRow] = a4.y;
        As[aCol + 2][aRow] = a4.z;
        As[aCol + 3][aRow] = a4.w;
        *(float4*)&Bs[bRow][bCol] =
            *(const float4*)(Bb + (size_t)(k0 + bRow) * N + bCol);
        __syncthreads();
        #pragma unroll
        for (int k = 0; k < BK; k++) {
            float regM[TM], regN[TN];
            #pragma unroll
            for (int i = 0; i < TM; i += 4)
                *(float4*)&regM[i] = *(const float4*)&As[k][ty * TM + i];
            #pragma unroll
            for (int j = 0; j < TN; j += 4)
                *(float4*)&regN[j] = *(const float4*)&Bs[k][tx * TN + j];
            #pragma unroll
            for (int i = 0; i < TM; i++)
                #pragma unroll
                for (int j = 0; j < TN; j++)
                    acc[i][j] = fmaf(regM[i], regN[j], acc[i][j]);
        }
        __syncthreads();
    }

    size_t cbase = (size_t)by * BM * N + (size_t)bx * BN;
    #pragma unroll
    for (int i = 0; i < TM; i++) {
        int row = ty * TM + i;
        #pragma unroll
        for (int j = 0; j < TN; j += 4) {
            int col = tx * TN + j;
            float4 bb = *(const float4*)(bias + (size_t)bx * BN + col);
            float4 c4;
            c4.x = acc[i][j + 0] + bb.x;
            c4.y = acc[i][j + 1] + bb.y;
            c4.z = acc[i][j + 2] + bb.z;
            c4.w = acc[i][j + 3] + bb.w;
            if (EPI == 1) {
                float4 r4 = *(const float4*)(R + cbase + (size_t)row * N + col);
                c4.x += r4.x; c4.y += r4.y; c4.z += r4.z; c4.w += r4.w;
            } else if (EPI == 2) {
                c4.x = gelu_f(c4.x); c4.y = gelu_f(c4.y);
                c4.z = gelu_f(c4.z); c4.w = gelu_f(c4.w);
            }
            *(float4*)(C + cbase + (size_t)row * N + col) = c4;
        }
    }
}

// ---------------- Causal flash attention (Q doubles as K) ----------------
// grid: (SEQ/64, BS*NHEADS). block: 256 = 64 rows x 4 d-slices of 16.
__global__ __launch_bounds__(256) void attn_kernel(
    const float* __restrict__ Q, const float* __restrict__ V,
    float* __restrict__ O)
{
    int qt = blockIdx.x;           // q tile (64 rows)
    int bh = blockIdx.y;
    int b = bh / NHEADS, h = bh % NHEADS;
    int tid = threadIdx.x;
    int r = tid >> 2;              // row in tile (0..63)
    int t = tid & 3;               // d-slice (16 dims)
    int qrow = qt * 64 + r;        // global seq pos
    size_t base = (size_t)b * SEQ * HID + (size_t)h * DK;

    float qreg[16];
    {
        const float* qp = Q + base + (size_t)qrow * HID + t * 16;
        #pragma unroll
        for (int i = 0; i < 16; i += 4) {
            float4 f = *(const float4*)(qp + i);
            qreg[i] = f.x; qreg[i+1] = f.y; qreg[i+2] = f.z; qreg[i+3] = f.w;
        }
    }

    float o[16] = {};
    float m = -INFINITY, l = 0.f;
    __shared__ float Ks[64][64];
    __shared__ float Vs[64][64];

    for (int kt = 0; kt <= qt; kt++) {
        __syncthreads();
        {   // stage K/V tile: thread (r,t) loads row r, dims [t*16, t*16+16)
            const float* kp = Q + base + (size_t)(kt * 64 + r) * HID + t * 16;
            const float* vp = V + base + (size_t)(kt * 64 + r) * HID + t * 16;
            #pragma unroll
            for (int i = 0; i < 16; i += 4) {
                *(float4*)&Ks[r][t * 16 + i] = *(const float4*)(kp + i);
                *(float4*)&Vs[r][t * 16 + i] = *(const float4*)(vp + i);
            }
        }
        __syncthreads();

        // partial dot over own 16 dims, all 64 columns
        float s[64];
        #pragma unroll
        for (int c = 0; c < 64; c++) {
            float a = 0.f;
            #pragma unroll
            for (int d = 0; d < 16; d += 4) {
                float4 k4 = *(const float4*)&Ks[c][t * 16 + d];
                a = fmaf(qreg[d + 0], k4.x, a);
                a = fmaf(qreg[d + 1], k4.y, a);
                a = fmaf(qreg[d + 2], k4.z, a);
                a = fmaf(qreg[d + 3], k4.w, a);
            }
            s[c] = a;
        }
        // reduce across the 4 d-slice threads (consecutive lanes)
        #pragma unroll
        for (int c = 0; c < 64; c++) {
            s[c] += __shfl_xor_sync(0xffffffffu, s[c], 1);
            s[c] += __shfl_xor_sync(0xffffffffu, s[c], 2);
            s[c] *= 0.125f;                       // 1/sqrt(64)
        }
        if (kt == qt) {
            #pragma unroll
            for (int c = 0; c < 64; c++)
                if (c > r) s[c] = -INFINITY;       // causal mask on diagonal tile
        }
        float mt = m;
        #pragma unroll
        for (int c = 0; c < 64; c++) mt = fmaxf(mt, s[c]);
        float alpha = __expf(m - mt);
        m = mt;
        float psum = 0.f;
        #pragma unroll
        for (int c = 0; c < 64; c++) {
            float pc = __expf(s[c] - m);
            s[c] = pc;
            psum += pc;
        }
        l = l * alpha + psum;
        #pragma unroll
        for (int d = 0; d < 16; d++) o[d] *= alpha;
        #pragma unroll
        for (int c = 0; c < 64; c++) {
            float pc = s[c];
            #pragma unroll
            for (int d = 0; d < 16; d += 4) {
                float4 v4 = *(const float4*)&Vs[c][t * 16 + d];
                o[d + 0] = fmaf(pc, v4.x, o[d + 0]);
                o[d + 1] = fmaf(pc, v4.y, o[d + 1]);
                o[d + 2] = fmaf(pc, v4.z, o[d + 2]);
                o[d + 3] = fmaf(pc, v4.w, o[d + 3]);
            }
        }
    }

    float inv = 1.f / l;
    float* op = O + base + (size_t)qrow * HID + t * 16;
    #pragma unroll
    for (int d = 0; d < 16; d += 4) {
        float4 f;
        f.x = o[d + 0] * inv; f.y = o[d + 1] * inv;
        f.z = o[d + 2] * inv; f.w = o[d + 3] * inv;
        *(float4*)(op + d) = f;
    }
}

// ---------------- launch ----------------
extern "C" void kernel_launch(void* const* d_in, const int* in_sizes, int n_in,
                              void* d_out, int out_size)
{
    const float* x     = (const float*)d_in[0];
    const float* Wq    = (const float*)d_in[1];
    const float* bq    = (const float*)d_in[2];
    const float* Wv    = (const float*)d_in[3];
    const float* bv    = (const float*)d_in[4];
    const float* Wo    = (const float*)d_in[5];
    const float* bo    = (const float*)d_in[6];
    const float* W1    = (const float*)d_in[7];
    const float* b1    = (const float*)d_in[8];
    const float* W2    = (const float*)d_in[9];
    const float* b2    = (const float*)d_in[10];
    const float* g1    = (const float*)d_in[11];
    const float* beta1 = (const float*)d_in[12];
    const float* g2    = (const float*)d_in[13];
    const float* beta2 = (const float*)d_in[14];
    float* out = (float*)d_out;

    float *ln, *q, *v, *ctx, *x1, *h1;
    cudaGetSymbolAddress((void**)&ln,  g_ln);
    cudaGetSymbolAddress((void**)&q,   g_q);
    cudaGetSymbolAddress((void**)&v,   g_v);
    cudaGetSymbolAddress((void**)&ctx, g_ctx);
    cudaGetSymbolAddress((void**)&x1,  g_x1);
    cudaGetSymbolAddress((void**)&h1,  g_h1);

    dim3 blk(256);
    dim3 gHID(HID / 128, TOKENS / 128);     // (8, 32)
    dim3 gFF (FFDIM / 128, TOKENS / 128);   // (32, 32)

    // x_ln = LN(x)
    ln_kernel<<<TOKENS, blk>>>(x, g1, beta1, ln);
    // q = ln @ Wq + bq ; v = ln @ Wv + bv
    sgemm<0><<<gHID, blk>>>(TOKENS, HID, HID, ln, Wq, bq, nullptr, q);
    sgemm<0><<<gHID, blk>>>(TOKENS, HID, HID, ln, Wv, bv, nullptr, v);
    // causal attention (Q == K)
    attn_kernel<<<dim3(SEQ / 64, 2 * NHEADS), blk>>>(q, v, ctx);
    // x1 = x + ctx @ Wo + bo
    sgemm<1><<<gHID, blk>>>(TOKENS, HID, HID, ctx, Wo, bo, x, x1);
    // h = LN(x1)
    ln_kernel<<<TOKENS, blk>>>(x1, g2, beta2, ln);
    // h1 = gelu(h @ W1 + b1)
    sgemm<2><<<gFF, blk>>>(TOKENS, FFDIM, HID, ln, W1, b1, nullptr, h1);
    // out = x1 + h1 @ W2 + b2
    sgemm<1><<<gHID, blk>>>(TOKENS, HID, FFDIM, h1, W2, b2, x1, out);
}

// round 2
// speedup vs baseline: 1.3751x; 1.3751x over previous
#include <cuda_runtime.h>
#include <math.h>

#define TOKENS 4096      // 2 * 2048
#define HID    1024
#define FFDIM  4096
#define SEQ    2048
#define NHEADS 16
#define DK     64

// ---------------- scratch (device globals; no allocs allowed) ----------------
__device__ float g_ln [TOKENS * HID];
__device__ float g_q  [TOKENS * HID];
__device__ float g_v  [TOKENS * HID];
__device__ float g_ctx[TOKENS * HID];
__device__ float g_x1 [TOKENS * HID];
__device__ float g_h1 [(size_t)TOKENS * FFDIM];

// ---------------- LayerNorm: one block per row ----------------
__global__ __launch_bounds__(256) void ln_kernel(
    const float* __restrict__ x, const float* __restrict__ gamma,
    const float* __restrict__ beta, float* __restrict__ out)
{
    int row = blockIdx.x;
    int t = threadIdx.x;                       // 256 threads, 4 floats each
    const float4* xr = (const float4*)(x + (size_t)row * HID);
    float4 v = xr[t];
    float s  = v.x + v.y + v.z + v.w;
    float ss = v.x*v.x + v.y*v.y + v.z*v.z + v.w*v.w;
    #pragma unroll
    for (int o = 16; o; o >>= 1) {
        s  += __shfl_xor_sync(0xffffffffu, s,  o);
        ss += __shfl_xor_sync(0xffffffffu, ss, o);
    }
    __shared__ float rs[8], rss[8];
    if ((t & 31) == 0) { rs[t >> 5] = s; rss[t >> 5] = ss; }
    __syncthreads();
    s = 0.f; ss = 0.f;
    #pragma unroll
    for (int i = 0; i < 8; i++) { s += rs[i]; ss += rss[i]; }
    float mu  = s * (1.f / HID);
    float var = ss * (1.f / HID) - mu * mu;
    float inv = rsqrtf(var + 1e-5f);
    float4 g4 = ((const float4*)gamma)[t];
    float4 b4 = ((const float4*)beta)[t];
    float4 o4;
    o4.x = (v.x - mu) * inv * g4.x + b4.x;
    o4.y = (v.y - mu) * inv * g4.y + b4.y;
    o4.z = (v.z - mu) * inv * g4.z + b4.z;
    o4.w = (v.w - mu) * inv * g4.w + b4.w;
    ((float4*)(out + (size_t)row * HID))[t] = o4;
}

// ---------------- GELU (tanh approx, matches reference) ----------------
__device__ __forceinline__ float gelu_f(float x)
{
    float u = 0.7978845608028654f * (x + 0.044715f * x * x * x);
    return 0.5f * x * (1.f + tanhf(u));
}

// ---------------- TF32 helpers ----------------
__device__ __forceinline__ unsigned f2tf(float f)
{
    unsigned u;
    asm("cvt.rna.tf32.f32 %0, %1;" : "=r"(u) : "f"(f));
    return u;
}

__device__ __forceinline__ void mma_tf32(
    float* c, unsigned a0, unsigned a1, unsigned a2, unsigned a3,
    unsigned b0, unsigned b1)
{
    asm volatile(
        "mma.sync.aligned.m16n8k8.row.col.f32.tf32.tf32.f32 "
        "{%0,%1,%2,%3}, {%4,%5,%6,%7}, {%8,%9}, {%0,%1,%2,%3};"
        : "+f"(c[0]), "+f"(c[1]), "+f"(c[2]), "+f"(c[3])
        : "r"(a0), "r"(a1), "r"(a2), "r"(a3), "r"(b0), "r"(b1));
}

// ---------------- TF32 tensor-core GEMM ----------------
// C = A(MxK) @ B(KxN) + bias (+res / gelu).  BM=BN=128, BK=32.
// 8 warps: warp (wm 0..3, wn 0..1) computes 32x64 via 2x8 m16n8k8 atoms.
// EPI: 0 = bias, 1 = bias + residual, 2 = gelu(bias + acc)
template <int EPI>
__global__ __launch_bounds__(256, 2) void mma_gemm(
    int M, int N, int K,
    const float* __restrict__ A, const float* __restrict__ B,
    const float* __restrict__ bias, const float* __restrict__ R,
    float* __restrict__ C)
{
    const int BK = 32;
    __shared__ unsigned As[BK][128 + 1];   // [k][m], stride 129 (odd)
    __shared__ unsigned Bs[BK][128 + 4];   // [k][n], stride 132 (16B-aligned rows)

    int tid  = threadIdx.x;
    int lane = tid & 31, w = tid >> 5;
    int wm = w >> 1, wn = w & 1;
    int g = lane >> 2, tig = lane & 3;
    int bx = blockIdx.x, by = blockIdx.y;

    const float* Ab = A + (size_t)by * 128 * K;
    const float* Bb = B + (size_t)bx * 128;

    float acc[2][8][4] = {};

    for (int k0 = 0; k0 < K; k0 += BK) {
        // ---- stage loads (front-batched LDG for MLP) ----
        float4 av[4], bv[4];
        #pragma unroll
        for (int i = 0; i < 4; i++) {
            int idx = tid + i * 256;
            int row = idx >> 3, c4 = idx & 7;
            av[i] = *(const float4*)(Ab + (size_t)row * K + k0 + c4 * 4);
        }
        #pragma unroll
        for (int i = 0; i < 4; i++) {
            int idx = tid + i * 256;
            int k = idx >> 5, n4 = idx & 31;
            bv[i] = *(const float4*)(Bb + (size_t)(k0 + k) * N + n4 * 4);
        }
        __syncthreads();   // previous stage's compute done before overwrite
        #pragma unroll
        for (int i = 0; i < 4; i++) {
            int idx = tid + i * 256;
            int row = idx >> 3, c4 = idx & 7;
            As[c4 * 4 + 0][row] = f2tf(av[i].x);
            As[c4 * 4 + 1][row] = f2tf(av[i].y);
            As[c4 * 4 + 2][row] = f2tf(av[i].z);
            As[c4 * 4 + 3][row] = f2tf(av[i].w);
        }
        #pragma unroll
        for (int i = 0; i < 4; i++) {
            int idx = tid + i * 256;
            int k = idx >> 5, n4 = idx & 31;
            uint4 u;
            u.x = f2tf(bv[i].x); u.y = f2tf(bv[i].y);
            u.z = f2tf(bv[i].z); u.w = f2tf(bv[i].w);
            *(uint4*)&Bs[k][n4 * 4] = u;
        }
        __syncthreads();

        // ---- compute: 4 k-steps of 8 ----
        #pragma unroll
        for (int kk = 0; kk < BK; kk += 8) {
            unsigned a[2][4];
            #pragma unroll
            for (int i = 0; i < 2; i++) {
                int m0 = wm * 32 + i * 16;
                a[i][0] = As[kk + tig    ][m0 + g    ];
                a[i][1] = As[kk + tig    ][m0 + g + 8];
                a[i][2] = As[kk + tig + 4][m0 + g    ];
                a[i][3] = As[kk + tig + 4][m0 + g + 8];
            }
            #pragma unroll
            for (int j = 0; j < 8; j++) {
                int n0 = wn * 64 + j * 8;
                unsigned b0 = Bs[kk + tig    ][n0 + g];
                unsigned b1 = Bs[kk + tig + 4][n0 + g];
                #pragma unroll
                for (int i = 0; i < 2; i++)
                    mma_tf32(acc[i][j], a[i][0], a[i][1], a[i][2], a[i][3], b0, b1);
            }
        }
        __syncthreads();
    }

    // ---- epilogue ----
    #pragma unroll
    for (int i = 0; i < 2; i++) {
        int r0 = by * 128 + wm * 32 + i * 16 + g;
        int r1 = r0 + 8;
        #pragma unroll
        for (int j = 0; j < 8; j++) {
            int col = bx * 128 + wn * 64 + j * 8 + tig * 2;
            float2 bb = *(const float2*)(bias + col);
            float2 v0, v1;
            v0.x = acc[i][j][0] + bb.x;  v0.y = acc[i][j][1] + bb.y;
            v1.x = acc[i][j][2] + bb.x;  v1.y = acc[i][j][3] + bb.y;
            if (EPI == 1) {
                float2 q0 = *(const float2*)(R + (size_t)r0 * N + col);
                float2 q1 = *(const float2*)(R + (size_t)r1 * N + col);
                v0.x += q0.x; v0.y += q0.y;
                v1.x += q1.x; v1.y += q1.y;
            } else if (EPI == 2) {
                v0.x = gelu_f(v0.x); v0.y = gelu_f(v0.y);
                v1.x = gelu_f(v1.x); v1.y = gelu_f(v1.y);
            }
            *(float2*)(C + (size_t)r0 * N + col) = v0;
            *(float2*)(C + (size_t)r1 * N + col) = v1;
        }
    }
}

// ---------------- Causal flash attention (Q doubles as K) ----------------
// grid: (SEQ/64, BS*NHEADS). block: 256 = 64 rows x 4 d-slices of 16.
__global__ __launch_bounds__(256) void attn_kernel(
    const float* __restrict__ Q, const float* __restrict__ V,
    float* __restrict__ O)
{
    int qt = blockIdx.x;           // q tile (64 rows)
    int bh = blockIdx.y;
    int b = bh / NHEADS, h = bh % NHEADS;
    int tid = threadIdx.x;
    int r = tid >> 2;              // row in tile (0..63)
    int t = tid & 3;               // d-slice (16 dims)
    int qrow = qt * 64 + r;        // global seq pos
    size_t base = (size_t)b * SEQ * HID + (size_t)h * DK;

    float qreg[16];
    {
        const float* qp = Q + base + (size_t)qrow * HID + t * 16;
        #pragma unroll
        for (int i = 0; i < 16; i += 4) {
            float4 f = *(const float4*)(qp + i);
            qreg[i] = f.x; qreg[i+1] = f.y; qreg[i+2] = f.z; qreg[i+3] = f.w;
        }
    }

    float o[16] = {};
    float m = -INFINITY, l = 0.f;
    __shared__ float Ks[64][64];
    __shared__ float Vs[64][64];

    for (int kt = 0; kt <= qt; kt++) {
        __syncthreads();
        {   // stage K/V tile: thread (r,t) loads row r, dims [t*16, t*16+16)
            const float* kp = Q + base + (size_t)(kt * 64 + r) * HID + t * 16;
            const float* vp = V + base + (size_t)(kt * 64 + r) * HID + t * 16;
            #pragma unroll
            for (int i = 0; i < 16; i += 4) {
                *(float4*)&Ks[r][t * 16 + i] = *(const float4*)(kp + i);
                *(float4*)&Vs[r][t * 16 + i] = *(const float4*)(vp + i);
            }
        }
        __syncthreads();

        // partial dot over own 16 dims, all 64 columns
        float s[64];
        #pragma unroll
        for (int c = 0; c < 64; c++) {
            float a = 0.f;
            #pragma unroll
            for (int d = 0; d < 16; d += 4) {
                float4 k4 = *(const float4*)&Ks[c][t * 16 + d];
                a = fmaf(qreg[d + 0], k4.x, a);
                a = fmaf(qreg[d + 1], k4.y, a);
                a = fmaf(qreg[d + 2], k4.z, a);
                a = fmaf(qreg[d + 3], k4.w, a);
            }
            s[c] = a;
        }
        // reduce across the 4 d-slice threads (consecutive lanes)
        #pragma unroll
        for (int c = 0; c < 64; c++) {
            s[c] += __shfl_xor_sync(0xffffffffu, s[c], 1);
            s[c] += __shfl_xor_sync(0xffffffffu, s[c], 2);
            s[c] *= 0.125f;                       // 1/sqrt(64)
        }
        if (kt == qt) {
            #pragma unroll
            for (int c = 0; c < 64; c++)
                if (c > r) s[c] = -INFINITY;       // causal mask on diagonal tile
        }
        float mt = m;
        #pragma unroll
        for (int c = 0; c < 64; c++) mt = fmaxf(mt, s[c]);
        float alpha = __expf(m - mt);
        m = mt;
        float psum = 0.f;
        #pragma unroll
        for (int c = 0; c < 64; c++) {
            float pc = __expf(s[c] - m);
            s[c] = pc;
            psum += pc;
        }
        l = l * alpha + psum;
        #pragma unroll
        for (int d = 0; d < 16; d++) o[d] *= alpha;
        #pragma unroll
        for (int c = 0; c < 64; c++) {
            float pc = s[c];
            #pragma unroll
            for (int d = 0; d < 16; d += 4) {
                float4 v4 = *(const float4*)&Vs[c][t * 16 + d];
                o[d + 0] = fmaf(pc, v4.x, o[d + 0]);
                o[d + 1] = fmaf(pc, v4.y, o[d + 1]);
                o[d + 2] = fmaf(pc, v4.z, o[d + 2]);
                o[d + 3] = fmaf(pc, v4.w, o[d + 3]);
            }
        }
    }

    float inv = 1.f / l;
    float* op = O + base + (size_t)qrow * HID + t * 16;
    #pragma unroll
    for (int d = 0; d < 16; d += 4) {
        float4 f;
        f.x = o[d + 0] * inv; f.y = o[d + 1] * inv;
        f.z = o[d + 2] * inv; f.w = o[d + 3] * inv;
        *(float4*)(op + d) = f;
    }
}

// ---------------- launch ----------------
extern "C" void kernel_launch(void* const* d_in, const int* in_sizes, int n_in,
                              void* d_out, int out_size)
{
    const float* x     = (const float*)d_in[0];
    const float* Wq    = (const float*)d_in[1];
    const float* bq    = (const float*)d_in[2];
    const float* Wv    = (const float*)d_in[3];
    const float* bv    = (const float*)d_in[4];
    const float* Wo    = (const float*)d_in[5];
    const float* bo    = (const float*)d_in[6];
    const float* W1    = (const float*)d_in[7];
    const float* b1    = (const float*)d_in[8];
    const float* W2    = (const float*)d_in[9];
    const float* b2    = (const float*)d_in[10];
    const float* g1    = (const float*)d_in[11];
    const float* beta1 = (const float*)d_in[12];
    const float* g2    = (const float*)d_in[13];
    const float* beta2 = (const float*)d_in[14];
    float* out = (float*)d_out;

    float *ln, *q, *v, *ctx, *x1, *h1;
    cudaGetSymbolAddress((void**)&ln,  g_ln);
    cudaGetSymbolAddress((void**)&q,   g_q);
    cudaGetSymbolAddress((void**)&v,   g_v);
    cudaGetSymbolAddress((void**)&ctx, g_ctx);
    cudaGetSymbolAddress((void**)&x1,  g_x1);
    cudaGetSymbolAddress((void**)&h1,  g_h1);

    dim3 blk(256);
    dim3 gHID(HID / 128, TOKENS / 128);     // (8, 32)
    dim3 gFF (FFDIM / 128, TOKENS / 128);   // (32, 32)

    // x_ln = LN(x)
    ln_kernel<<<TOKENS, blk>>>(x, g1, beta1, ln);
    // q = ln @ Wq + bq ; v = ln @ Wv + bv
    mma_gemm<0><<<gHID, blk>>>(TOKENS, HID, HID, ln, Wq, bq, nullptr, q);
    mma_gemm<0><<<gHID, blk>>>(TOKENS, HID, HID, ln, Wv, bv, nullptr, v);
    // causal attention (Q == K)
    attn_kernel<<<dim3(SEQ / 64, 2 * NHEADS), blk>>>(q, v, ctx);
    // x1 = x + ctx @ Wo + bo
    mma_gemm<1><<<gHID, blk>>>(TOKENS, HID, HID, ctx, Wo, bo, x, x1);
    // h = LN(x1)
    ln_kernel<<<TOKENS, blk>>>(x1, g2, beta2, ln);
    // h1 = gelu(h @ W1 + b1)
    mma_gemm<2><<<gFF, blk>>>(TOKENS, FFDIM, HID, ln, W1, b1, nullptr, h1);
    // out = x1 + h1 @ W2 + b2
    mma_gemm<1><<<gHID, blk>>>(TOKENS, HID, FFDIM, h1, W2, b2, x1, out);
}

// round 3
// speedup vs baseline: 5.3562x; 3.8951x over previous
#include <cuda_runtime.h>
#include <math.h>

#define TOKENS 4096      // 2 * 2048
#define HID    1024
#define FFDIM  4096
#define SEQ    2048
#define NHEADS 16
#define DK     64

// ---------------- scratch (device globals; no allocs allowed) ----------------
__device__ float g_ln [TOKENS * HID];
__device__ float g_q  [TOKENS * HID];
__device__ float g_v  [TOKENS * HID];
__device__ float g_ctx[TOKENS * HID];
__device__ float g_x1 [TOKENS * HID];
__device__ float g_h1 [(size_t)TOKENS * FFDIM];

// ---------------- LayerNorm: one block per row ----------------
__global__ __launch_bounds__(256) void ln_kernel(
    const float* __restrict__ x, const float* __restrict__ gamma,
    const float* __restrict__ beta, float* __restrict__ out)
{
    int row = blockIdx.x;
    int t = threadIdx.x;                       // 256 threads, 4 floats each
    const float4* xr = (const float4*)(x + (size_t)row * HID);
    float4 v = xr[t];
    float s  = v.x + v.y + v.z + v.w;
    float ss = v.x*v.x + v.y*v.y + v.z*v.z + v.w*v.w;
    #pragma unroll
    for (int o = 16; o; o >>= 1) {
        s  += __shfl_xor_sync(0xffffffffu, s,  o);
        ss += __shfl_xor_sync(0xffffffffu, ss, o);
    }
    __shared__ float rs[8], rss[8];
    if ((t & 31) == 0) { rs[t >> 5] = s; rss[t >> 5] = ss; }
    __syncthreads();
    s = 0.f; ss = 0.f;
    #pragma unroll
    for (int i = 0; i < 8; i++) { s += rs[i]; ss += rss[i]; }
    float mu  = s * (1.f / HID);
    float var = ss * (1.f / HID) - mu * mu;
    float inv = rsqrtf(var + 1e-5f);
    float4 g4 = ((const float4*)gamma)[t];
    float4 b4 = ((const float4*)beta)[t];
    float4 o4;
    o4.x = (v.x - mu) * inv * g4.x + b4.x;
    o4.y = (v.y - mu) * inv * g4.y + b4.y;
    o4.z = (v.z - mu) * inv * g4.z + b4.z;
    o4.w = (v.w - mu) * inv * g4.w + b4.w;
    ((float4*)(out + (size_t)row * HID))[t] = o4;
}

// ---------------- GELU (tanh approx, matches reference) ----------------
__device__ __forceinline__ float gelu_f(float x)
{
    float u = 0.7978845608028654f * (x + 0.044715f * x * x * x);
    return 0.5f * x * (1.f + tanhf(u));
}

// ---------------- TF32 MMA (raw fp32 bits; HW truncates mantissa) ----------
__device__ __forceinline__ void mma_f(
    float* c, float a0, float a1, float a2, float a3, float b0, float b1)
{
    asm volatile(
        "mma.sync.aligned.m16n8k8.row.col.f32.tf32.tf32.f32 "
        "{%0,%1,%2,%3}, {%4,%5,%6,%7}, {%8,%9}, {%0,%1,%2,%3};"
        : "+f"(c[0]), "+f"(c[1]), "+f"(c[2]), "+f"(c[3])
        : "r"(__float_as_uint(a0)), "r"(__float_as_uint(a1)),
          "r"(__float_as_uint(a2)), "r"(__float_as_uint(a3)),
          "r"(__float_as_uint(b0)), "r"(__float_as_uint(b1)));
}

__device__ __forceinline__ void cp16(float* s, const float* g)
{
    unsigned sa = (unsigned)__cvta_generic_to_shared(s);
    asm volatile("cp.async.cg.shared.global [%0], [%1], 16;" :: "r"(sa), "l"(g));
}

// ---------------- TF32 tensor-core GEMM, cp.async double-buffered ----------
// C = A(MxK) @ B(KxN) + bias (+res / gelu).  BM=BN=128, BK=16.
// 8 warps: warp (wm 0..3, wn 0..1) computes 32x64 via 2x8 m16n8k8 atoms.
// EPI: 0 = bias, 1 = bias + residual, 2 = gelu(bias + acc)
template <int EPI>
__global__ __launch_bounds__(256, 2) void mma_gemm(
    int M, int N, int K,
    const float* __restrict__ A, const float* __restrict__ B,
    const float* __restrict__ bias, const float* __restrict__ R,
    float* __restrict__ C)
{
    __shared__ float As[2][128][20];   // [m][k], stride 20 (conflict-free frags)
    __shared__ float Bs[2][16][136];   // [k][n], stride 136 (conflict-free frags)

    int tid  = threadIdx.x;
    int lane = tid & 31, w = tid >> 5;
    int wm = w >> 1, wn = w & 1;
    int g = lane >> 2, tig = lane & 3;
    int bx = blockIdx.x, by = blockIdx.y;

    const float* Ab = A + (size_t)by * 128 * K;
    const float* Bb = B + (size_t)bx * 128;

    float acc[2][8][4] = {};
    int NT = K >> 4;

    // stage-0 prefetch
    {
        #pragma unroll
        for (int i = 0; i < 2; i++) {
            int idx = tid + i * 256;
            int r = idx >> 2, c4 = idx & 3;
            cp16(&As[0][r][c4 * 4], Ab + (size_t)r * K + c4 * 4);
        }
        #pragma unroll
        for (int i = 0; i < 2; i++) {
            int idx = tid + i * 256;
            int r = idx >> 5, n4 = idx & 31;
            cp16(&Bs[0][r][n4 * 4], Bb + (size_t)r * N + n4 * 4);
        }
        asm volatile("cp.async.commit_group;");
    }

    for (int t = 0; t < NT; t++) {
        if (t + 1 < NT) {
            int s = (t + 1) & 1, k0 = (t + 1) << 4;
            #pragma unroll
            for (int i = 0; i < 2; i++) {
                int idx = tid + i * 256;
                int r = idx >> 2, c4 = idx & 3;
                cp16(&As[s][r][c4 * 4], Ab + (size_t)r * K + k0 + c4 * 4);
            }
            #pragma unroll
            for (int i = 0; i < 2; i++) {
                int idx = tid + i * 256;
                int r = idx >> 5, n4 = idx & 31;
                cp16(&Bs[s][r][n4 * 4], Bb + (size_t)(k0 + r) * N + n4 * 4);
            }
        }
        asm volatile("cp.async.commit_group;");
        asm volatile("cp.async.wait_group 1;");
        __syncthreads();

        int s = t & 1;
        #pragma unroll
        for (int kk = 0; kk < 16; kk += 8) {
            float a[2][4];
            #pragma unroll
            for (int i = 0; i < 2; i++) {
                int r = wm * 32 + i * 16;
                a[i][0] = As[s][r + g    ][kk + tig    ];
                a[i][1] = As[s][r + g + 8][kk + tig    ];
                a[i][2] = As[s][r + g    ][kk + tig + 4];
                a[i][3] = As[s][r + g + 8][kk + tig + 4];
            }
            #pragma unroll
            for (int j = 0; j < 8; j++) {
                float b0 = Bs[s][kk + tig    ][wn * 64 + j * 8 + g];
                float b1 = Bs[s][kk + tig + 4][wn * 64 + j * 8 + g];
                #pragma unroll
                for (int i = 0; i < 2; i++)
                    mma_f(acc[i][j], a[i][0], a[i][1], a[i][2], a[i][3], b0, b1);
            }
        }
        __syncthreads();
    }

    // ---- epilogue ----
    #pragma unroll
    for (int i = 0; i < 2; i++) {
        int r0 = by * 128 + wm * 32 + i * 16 + g;
        int r1 = r0 + 8;
        #pragma unroll
        for (int j = 0; j < 8; j++) {
            int col = bx * 128 + wn * 64 + j * 8 + tig * 2;
            float2 bb = *(const float2*)(bias + col);
            float2 v0, v1;
            v0.x = acc[i][j][0] + bb.x;  v0.y = acc[i][j][1] + bb.y;
            v1.x = acc[i][j][2] + bb.x;  v1.y = acc[i][j][3] + bb.y;
            if (EPI == 1) {
                float2 q0 = *(const float2*)(R + (size_t)r0 * N + col);
                float2 q1 = *(const float2*)(R + (size_t)r1 * N + col);
                v0.x += q0.x; v0.y += q0.y;
                v1.x += q1.x; v1.y += q1.y;
            } else if (EPI == 2) {
                v0.x = gelu_f(v0.x); v0.y = gelu_f(v0.y);
                v1.x = gelu_f(v1.x); v1.y = gelu_f(v1.y);
            }
            *(float2*)(C + (size_t)r0 * N + col) = v0;
            *(float2*)(C + (size_t)r1 * N + col) = v1;
        }
    }
}

// ---------------- Tensor-core causal flash attention (Q doubles as K) -------
// Block: 128 q-rows, 8 warps (warp w owns rows w*16..w*16+15), K/V tiles of 64.
// grid: (SEQ/128, BS*NHEADS).
__global__ __launch_bounds__(256) void attn_mma(
    const float* __restrict__ Q, const float* __restrict__ V,
    float* __restrict__ O)
{
    extern __shared__ float sm[];
    const int KS = 68, VS = 72, PS = 68;
    float* Ks = sm;                 // [64][KS]   row = kcol, col = d
    float* Vs = Ks + 64 * KS;       // [64][VS]   row = kcol, col = d
    float* Ps = Vs + 64 * VS;       // [128][PS]  row = qrow (warp-private rows)

    int qt = blockIdx.x, bh = blockIdx.y;
    int b = bh >> 4, h = bh & 15;
    int tid = threadIdx.x, lane = tid & 31, w = tid >> 5;
    int g = lane >> 2, tig = lane & 3;
    int m0 = w * 16;
    size_t base = (size_t)b * SEQ * HID + (size_t)h * DK;

    // ---- stage Q tile through Ps, then load Q fragments to registers ----
    #pragma unroll
    for (int i = 0; i < 8; i++) {
        int idx = tid + i * 256;            // 128 rows x 16 float4
        int row = idx >> 4, c4 = idx & 15;
        *(float4*)&Ps[row * PS + c4 * 4] =
            *(const float4*)(Q + base + (size_t)(qt * 128 + row) * HID + c4 * 4);
    }
    __syncthreads();
    float qf[8][4];
    #pragma unroll
    for (int kd = 0; kd < 8; kd++) {
        qf[kd][0] = Ps[(m0 + g    ) * PS + kd * 8 + tig    ];
        qf[kd][1] = Ps[(m0 + g + 8) * PS + kd * 8 + tig    ];
        qf[kd][2] = Ps[(m0 + g    ) * PS + kd * 8 + tig + 4];
        qf[kd][3] = Ps[(m0 + g + 8) * PS + kd * 8 + tig + 4];
    }
    __syncwarp();   // order qf reads before this warp's later P stores

    float oacc[8][4] = {};
    float mr0 = -INFINITY, mr1 = -INFINITY, l0 = 0.f, l1 = 0.f;
    int r0g = qt * 128 + m0 + g;    // global q row for acc c0/c1
    int r1g = r0g + 8;              // global q row for acc c2/c3
    int ktmax = 2 * qt + 1;

    for (int kt = 0; kt <= ktmax; kt++) {
        __syncthreads();   // previous tile's PV reads of Vs/Ks complete
        #pragma unroll
        for (int i = 0; i < 4; i++) {
            int idx = tid + i * 256;        // 64 rows x 16 float4
            int row = idx >> 4, c4 = idx & 15;
            *(float4*)&Ks[row * KS + c4 * 4] =
                *(const float4*)(Q + base + (size_t)(kt * 64 + row) * HID + c4 * 4);
            *(float4*)&Vs[row * VS + c4 * 4] =
                *(const float4*)(V + base + (size_t)(kt * 64 + row) * HID + c4 * 4);
        }
        __syncthreads();

        // ---- S = Q K^T  (warp rows m0..m0+16, all 64 kcols) ----
        float sacc[8][4] = {};
        #pragma unroll
        for (int kd = 0; kd < 8; kd++) {
            #pragma unroll
            for (int j = 0; j < 8; j++) {
                float b0 = Ks[(j * 8 + g) * KS + kd * 8 + tig    ];
                float b1 = Ks[(j * 8 + g) * KS + kd * 8 + tig + 4];
                mma_f(sacc[j], qf[kd][0], qf[kd][1], qf[kd][2], qf[kd][3], b0, b1);
            }
        }

        // ---- scale + causal mask ----
        const float scale = 0.125f;         // 1/sqrt(64)
        if (kt >= 2 * qt) {
            #pragma unroll
            for (int j = 0; j < 8; j++) {
                int c0 = kt * 64 + j * 8 + 2 * tig;
                sacc[j][0] = (c0     > r0g) ? -INFINITY : sacc[j][0] * scale;
                sacc[j][1] = (c0 + 1 > r0g) ? -INFINITY : sacc[j][1] * scale;
                sacc[j][2] = (c0     > r1g) ? -INFINITY : sacc[j][2] * scale;
                sacc[j][3] = (c0 + 1 > r1g) ? -INFINITY : sacc[j][3] * scale;
            }
        } else {
            #pragma unroll
            for (int j = 0; j < 8; j++)
                #pragma unroll
                for (int c = 0; c < 4; c++) sacc[j][c] *= scale;
        }

        // ---- online softmax (rows r0g, r1g; quad = lanes g*4+0..3) ----
        float mt0 = mr0, mt1 = mr1;
        #pragma unroll
        for (int j = 0; j < 8; j++) {
            mt0 = fmaxf(mt0, fmaxf(sacc[j][0], sacc[j][1]));
            mt1 = fmaxf(mt1, fmaxf(sacc[j][2], sacc[j][3]));
        }
        mt0 = fmaxf(mt0, __shfl_xor_sync(0xffffffffu, mt0, 1));
        mt0 = fmaxf(mt0, __shfl_xor_sync(0xffffffffu, mt0, 2));
        mt1 = fmaxf(mt1, __shfl_xor_sync(0xffffffffu, mt1, 1));
        mt1 = fmaxf(mt1, __shfl_xor_sync(0xffffffffu, mt1, 2));
        float alpha0 = __expf(mr0 - mt0);
        float alpha1 = __expf(mr1 - mt1);
        mr0 = mt0; mr1 = mt1;
        float ps0 = 0.f, ps1 = 0.f;
        #pragma unroll
        for (int j = 0; j < 8; j++) {
            sacc[j][0] = __expf(sacc[j][0] - mt0); ps0 += sacc[j][0];
            sacc[j][1] = __expf(sacc[j][1] - mt0); ps0 += sacc[j][1];
            sacc[j][2] = __expf(sacc[j][2] - mt1); ps1 += sacc[j][2];
            sacc[j][3] = __expf(sacc[j][3] - mt1); ps1 += sacc[j][3];
        }
        ps0 += __shfl_xor_sync(0xffffffffu, ps0, 1);
        ps0 += __shfl_xor_sync(0xffffffffu, ps0, 2);
        ps1 += __shfl_xor_sync(0xffffffffu, ps1, 1);
        ps1 += __shfl_xor_sync(0xffffffffu, ps1, 2);
        l0 = l0 * alpha0 + ps0;
        l1 = l1 * alpha1 + ps1;
        #pragma unroll
        for (int j = 0; j < 8; j++) {
            oacc[j][0] *= alpha0; oacc[j][1] *= alpha0;
            oacc[j][2] *= alpha1; oacc[j][3] *= alpha1;
        }

        // ---- P to smem (warp-private rows; no block sync needed) ----
        __syncwarp();
        #pragma unroll
        for (int j = 0; j < 8; j++) {
            *(float2*)&Ps[(m0 + g    ) * PS + j * 8 + 2 * tig] =
                make_float2(sacc[j][0], sacc[j][1]);
            *(float2*)&Ps[(m0 + g + 8) * PS + j * 8 + 2 * tig] =
                make_float2(sacc[j][2], sacc[j][3]);
        }
        __syncwarp();

        // ---- O += P V ----
        #pragma unroll
        for (int kp = 0; kp < 8; kp++) {
            float a0 = Ps[(m0 + g    ) * PS + kp * 8 + tig    ];
            float a1 = Ps[(m0 + g + 8) * PS + kp * 8 + tig    ];
            float a2 = Ps[(m0 + g    ) * PS + kp * 8 + tig + 4];
            float a3 = Ps[(m0 + g + 8) * PS + kp * 8 + tig + 4];
            #pragma unroll
            for (int j = 0; j < 8; j++) {
                float b0 = Vs[(kp * 8 + tig    ) * VS + j * 8 + g];
                float b1 = Vs[(kp * 8 + tig + 4) * VS + j * 8 + g];
                mma_f(oacc[j], a0, a1, a2, a3, b0, b1);
            }
        }
    }

    // ---- normalize + write ----
    float inv0 = 1.f / l0, inv1 = 1.f / l1;
    #pragma unroll
    for (int j = 0; j < 8; j++) {
        int col = j * 8 + 2 * tig;
        float2 v0, v1;
        v0.x = oacc[j][0] * inv0; v0.y = oacc[j][1] * inv0;
        v1.x = oacc[j][2] * inv1; v1.y = oacc[j][3] * inv1;
        *(float2*)(O + base + (size_t)r0g * HID + col) = v0;
        *(float2*)(O + base + (size_t)r1g * HID + col) = v1;
    }
}

// ---------------- launch ----------------
extern "C" void kernel_launch(void* const* d_in, const int* in_sizes, int n_in,
                              void* d_out, int out_size)
{
    const float* x     = (const float*)d_in[0];
    const float* Wq    = (const float*)d_in[1];
    const float* bq    = (const float*)d_in[2];
    const float* Wv    = (const float*)d_in[3];
    const float* bv    = (const float*)d_in[4];
    const float* Wo    = (const float*)d_in[5];
    const float* bo    = (const float*)d_in[6];
    const float* W1    = (const float*)d_in[7];
    const float* b1    = (const float*)d_in[8];
    const float* W2    = (const float*)d_in[9];
    const float* b2    = (const float*)d_in[10];
    const float* g1    = (const float*)d_in[11];
    const float* beta1 = (const float*)d_in[12];
    const float* g2    = (const float*)d_in[13];
    const float* beta2 = (const float*)d_in[14];
    float* out = (float*)d_out;

    float *ln, *q, *v, *ctx, *x1, *h1;
    cudaGetSymbolAddress((void**)&ln,  g_ln);
    cudaGetSymbolAddress((void**)&q,   g_q);
    cudaGetSymbolAddress((void**)&v,   g_v);
    cudaGetSymbolAddress((void**)&ctx, g_ctx);
    cudaGetSymbolAddress((void**)&x1,  g_x1);
    cudaGetSymbolAddress((void**)&h1,  g_h1);

    const int attn_smem = (64 * 68 + 64 * 72 + 128 * 68) * 4;   // 70656 B
    cudaFuncSetAttribute(attn_mma,
                         cudaFuncAttributeMaxDynamicSharedMemorySize, attn_smem);

    dim3 blk(256);
    dim3 gHID(HID / 128, TOKENS / 128);     // (8, 32)
    dim3 gFF (FFDIM / 128, TOKENS / 128);   // (32, 32)

    // x_ln = LN(x)
    ln_kernel<<<TOKENS, blk>>>(x, g1, beta1, ln);
    // q = ln @ Wq + bq ; v = ln @ Wv + bv
    mma_gemm<0><<<gHID, blk>>>(TOKENS, HID, HID, ln, Wq, bq, nullptr, q);
    mma_gemm<0><<<gHID, blk>>>(TOKENS, HID, HID, ln, Wv, bv, nullptr, v);
    // causal attention (Q == K)
    attn_mma<<<dim3(SEQ / 128, 2 * NHEADS), blk, attn_smem>>>(q, v, ctx);
    // x1 = x + ctx @ Wo + bo
    mma_gemm<1><<<gHID, blk>>>(TOKENS, HID, HID, ctx, Wo, bo, x, x1);
    // h = LN(x1)
    ln_kernel<<<TOKENS, blk>>>(x1, g2, beta2, ln);
    // h1 = gelu(h @ W1 + b1)
    mma_gemm<2><<<gFF, blk>>>(TOKENS, FFDIM, HID, ln, W1, b1, nullptr, h1);
    // out = x1 + h1 @ W2 + b2
    mma_gemm<1><<<gHID, blk>>>(TOKENS, HID, FFDIM, h1, W2, b2, x1, out);
}

// round 6
// speedup vs baseline: 7.4226x; 1.3858x over previous
#include <cuda_runtime.h>
#include <cuda_fp16.h>
#include <math.h>
#include <stdint.h>

#define TOKENS 4096      // 2 * 2048
#define HID    1024
#define FFDIM  4096
#define SEQ    2048
#define NHEADS 16
#define DK     64

// ---------------- scratch (device globals; no allocs allowed) ----------------
__device__ float  g_q   [TOKENS * HID];
__device__ float  g_v   [TOKENS * HID];
__device__ float  g_x1  [TOKENS * HID];
__device__ __half g_ln16[TOKENS * HID];
__device__ __half g_ctx16[TOKENS * HID];
__device__ __half g_h116[(size_t)TOKENS * FFDIM];
// transposed fp16 weights, (N, K) row-major
__device__ __half g_wqt[HID * HID];
__device__ __half g_wvt[HID * HID];
__device__ __half g_wot[HID * HID];
__device__ __half g_w1t[(size_t)HID * FFDIM];
__device__ __half g_w2t[(size_t)HID * FFDIM];

// ---------------- LayerNorm: one block per row, fp16 out ----------------
__global__ __launch_bounds__(256) void ln_kernel(
    const float* __restrict__ x, const float* __restrict__ gamma,
    const float* __restrict__ beta, __half* __restrict__ out)
{
    int row = blockIdx.x;
    int t = threadIdx.x;
    const float4* xr = (const float4*)(x + (size_t)row * HID);
    float4 v = xr[t];
    float s  = v.x + v.y + v.z + v.w;
    float ss = v.x*v.x + v.y*v.y + v.z*v.z + v.w*v.w;
    #pragma unroll
    for (int o = 16; o; o >>= 1) {
        s  += __shfl_xor_sync(0xffffffffu, s,  o);
        ss += __shfl_xor_sync(0xffffffffu, ss, o);
    }
    __shared__ float rs[8], rss[8];
    if ((t & 31) == 0) { rs[t >> 5] = s; rss[t >> 5] = ss; }
    __syncthreads();
    s = 0.f; ss = 0.f;
    #pragma unroll
    for (int i = 0; i < 8; i++) { s += rs[i]; ss += rss[i]; }
    float mu  = s * (1.f / HID);
    float var = ss * (1.f / HID) - mu * mu;
    float inv = rsqrtf(var + 1e-5f);
    float4 g4 = ((const float4*)gamma)[t];
    float4 b4 = ((const float4*)beta)[t];
    __half2 pk2[2];
    pk2[0] = __floats2half2_rn((v.x - mu) * inv * g4.x + b4.x,
                               (v.y - mu) * inv * g4.y + b4.y);
    pk2[1] = __floats2half2_rn((v.z - mu) * inv * g4.z + b4.z,
                               (v.w - mu) * inv * g4.w + b4.w);
    *(uint2*)(out + (size_t)row * HID + t * 4) = *(const uint2*)pk2;
}

// ---------------- weight transpose: in (K,N) fp32 -> out (N,K) fp16 --------
__global__ __launch_bounds__(256) void transpose_k(
    const float* __restrict__ in, __half* __restrict__ out, int K, int N)
{
    __shared__ float tl[32][33];
    int tx = threadIdx.x, ty = threadIdx.y;
    int n0 = blockIdx.x * 32, k0 = blockIdx.y * 32;
    #pragma unroll
    for (int i = 0; i < 32; i += 8)
        tl[ty + i][tx] = in[(size_t)(k0 + ty + i) * N + n0 + tx];
    __syncthreads();
    #pragma unroll
    for (int i = 0; i < 32; i += 8)
        out[(size_t)(n0 + ty + i) * K + k0 + tx] = __float2half(tl[tx][ty + i]);
}

// ---------------- GELU (tanh approx, matches reference) ----------------
__device__ __forceinline__ float gelu_f(float x)
{
    float u = 0.7978845608028654f * (x + 0.044715f * x * x * x);
    return 0.5f * x * (1.f + tanhf(u));
}

// ---------------- FP16 MMA m16n8k16, fp32 accumulate ----------------
__device__ __forceinline__ void mma_h(
    float* c, uint32_t a0, uint32_t a1, uint32_t a2, uint32_t a3,
    uint32_t b0, uint32_t b1)
{
    asm volatile(
        "mma.sync.aligned.m16n8k16.row.col.f32.f16.f16.f32 "
        "{%0,%1,%2,%3}, {%4,%5,%6,%7}, {%8,%9}, {%0,%1,%2,%3};"
        : "+f"(c[0]), "+f"(c[1]), "+f"(c[2]), "+f"(c[3])
        : "r"(a0), "r"(a1), "r"(a2), "r"(a3), "r"(b0), "r"(b1));
}

__device__ __forceinline__ void cp16(void* s, const void* g)
{
    unsigned sa = (unsigned)__cvta_generic_to_shared(s);
    asm volatile("cp.async.cg.shared.global [%0], [%1], 16;" :: "r"(sa), "l"(g));
}

__device__ __forceinline__ uint32_t U32(const __half* p)
{
    return *(const uint32_t*)p;
}

// paired-store helpers (fp32 or fp16 output)
__device__ __forceinline__ void st2(float* p, float x, float y)
{
    *(float2*)p = make_float2(x, y);
}
__device__ __forceinline__ void st2(__half* p, float x, float y)
{
    *(__half2*)p = __floats2half2_rn(x, y);
}

// ---------------- FP16 tensor-core GEMM, cp.async double-buffered ----------
// C = A(MxK) @ Bt(NxK)^T + bias (+res / gelu).  BM=BN=128, BK=32.
// 8 warps: warp (wm 0..3, wn 0..1) computes 32x64 via 2x8 m16n8k16 atoms.
// EPI: 0 = bias, 1 = bias + residual, 2 = gelu(bias + acc)
template <int EPI, typename OT>
__global__ __launch_bounds__(256, 2) void hgemm(
    int M, int N, int K,
    const __half* __restrict__ A, const __half* __restrict__ Bt,
    const float* __restrict__ bias, const float* __restrict__ R,
    OT* __restrict__ C)
{
    __shared__ __half As[2][128][40];   // [m][k], 40-half rows (80 B, 16B-mult)
    __shared__ __half Bs[2][128][40];   // [n][k]

    int tid  = threadIdx.x;
    int lane = tid & 31, w = tid >> 5;
    int wm = w >> 1, wn = w & 1;
    int g = lane >> 2, tig = lane & 3;
    int bx = blockIdx.x, by = blockIdx.y;

    const __half* Ab = A  + (size_t)by * 128 * K;
    const __half* Bb = Bt + (size_t)bx * 128 * K;

    float acc[2][8][4] = {};
    int NT = K >> 5;

    // stage-0 prefetch: 128 rows x 4 chunks of 8 halves, for A and B
    {
        #pragma unroll
        for (int i = 0; i < 2; i++) {
            int idx = tid + i * 256;
            int r = idx >> 2, ch = idx & 3;
            cp16(&As[0][r][ch * 8], Ab + (size_t)r * K + ch * 8);
        }
        #pragma unroll
        for (int i = 0; i < 2; i++) {
            int idx = tid + i * 256;
            int r = idx >> 2, ch = idx & 3;
            cp16(&Bs[0][r][ch * 8], Bb + (size_t)r * K + ch * 8);
        }
        asm volatile("cp.async.commit_group;");
    }

    for (int t = 0; t < NT; t++) {
        if (t + 1 < NT) {
            int s = (t + 1) & 1, k0 = (t + 1) << 5;
            #pragma unroll
            for (int i = 0; i < 2; i++) {
                int idx = tid + i * 256;
                int r = idx >> 2, ch = idx & 3;
                cp16(&As[s][r][ch * 8], Ab + (size_t)r * K + k0 + ch * 8);
            }
            #pragma unroll
            for (int i = 0; i < 2; i++) {
                int idx = tid + i * 256;
                int r = idx >> 2, ch = idx & 3;
                cp16(&Bs[s][r][ch * 8], Bb + (size_t)r * K + k0 + ch * 8);
            }
        }
        asm volatile("cp.async.commit_group;");
        asm volatile("cp.async.wait_group 1;");
        __syncthreads();

        int s = t & 1;
        #pragma unroll
        for (int kk = 0; kk < 2; kk++) {
            int k8 = kk * 8;                  // half2 base index
            uint32_t a[2][4];
            #pragma unroll
            for (int i = 0; i < 2; i++) {
                int r0 = wm * 32 + i * 16;
                a[i][0] = U32(&As[s][r0 + g    ][2 * (k8 + tig)]);
                a[i][1] = U32(&As[s][r0 + g + 8][2 * (k8 + tig)]);
                a[i][2] = U32(&As[s][r0 + g    ][2 * (k8 + tig + 4)]);
                a[i][3] = U32(&As[s][r0 + g + 8][2 * (k8 + tig + 4)]);
            }
            #pragma unroll
            for (int j = 0; j < 8; j++) {
                int bn = wn * 64 + j * 8 + g;
                uint32_t b0 = U32(&Bs[s][bn][2 * (k8 + tig)]);
                uint32_t b1 = U32(&Bs[s][bn][2 * (k8 + tig + 4)]);
                #pragma unroll
                for (int i = 0; i < 2; i++)
                    mma_h(acc[i][j], a[i][0], a[i][1], a[i][2], a[i][3], b0, b1);
            }
        }
        __syncthreads();
    }

    // ---- epilogue ----
    #pragma unroll
    for (int i = 0; i < 2; i++) {
        int r0 = by * 128 + wm * 32 + i * 16 + g;
        int r1 = r0 + 8;
        #pragma unroll
        for (int j = 0; j < 8; j++) {
            int col = bx * 128 + wn * 64 + j * 8 + tig * 2;
            float2 bb = *(const float2*)(bias + col);
            float v00 = acc[i][j][0] + bb.x, v01 = acc[i][j][1] + bb.y;
            float v10 = acc[i][j][2] + bb.x, v11 = acc[i][j][3] + bb.y;
            if (EPI == 1) {
                float2 q0 = *(const float2*)(R + (size_t)r0 * N + col);
                float2 q1 = *(const float2*)(R + (size_t)r1 * N + col);
                v00 += q0.x; v01 += q0.y;
                v10 += q1.x; v11 += q1.y;
            } else if (EPI == 2) {
                v00 = gelu_f(v00); v01 = gelu_f(v01);
                v10 = gelu_f(v10); v11 = gelu_f(v11);
            }
            st2(C + (size_t)r0 * N + col, v00, v01);
            st2(C + (size_t)r1 * N + col, v10, v11);
        }
    }
}

// ---------------- TF32 MMA via mma.sync (attention) ----------------
__device__ __forceinline__ void mma_f(
    float* c, float a0, float a1, float a2, float a3, float b0, float b1)
{
    asm volatile(
        "mma.sync.aligned.m16n8k8.row.col.f32.tf32.tf32.f32 "
        "{%0,%1,%2,%3}, {%4,%5,%6,%7}, {%8,%9}, {%0,%1,%2,%3};"
        : "+f"(c[0]), "+f"(c[1]), "+f"(c[2]), "+f"(c[3])
        : "r"(__float_as_uint(a0)), "r"(__float_as_uint(a1)),
          "r"(__float_as_uint(a2)), "r"(__float_as_uint(a3)),
          "r"(__float_as_uint(b0)), "r"(__float_as_uint(b1)));
}

// ---------------- Tensor-core causal flash attention (Q doubles as K) -------
// Block: 128 q-rows, 8 warps; K/V tiles of 64; fp16 ctx output.
// Reversed qt mapping: longest blocks first (wave balance).
__global__ __launch_bounds__(256) void attn_mma(
    const float* __restrict__ Q, const float* __restrict__ V,
    __half* __restrict__ O)
{
    extern __shared__ float sm[];
    const int KS = 68, VS = 72, PS = 68;
    float* Ks = sm;
    float* Vs = Ks + 64 * KS;
    float* Ps = Vs + 64 * VS;

    int qt = (int)gridDim.x - 1 - (int)blockIdx.x;   // longest first
    int bh = blockIdx.y;
    int b = bh >> 4, h = bh & 15;
    int tid = threadIdx.x, lane = tid & 31, w = tid >> 5;
    int g = lane >> 2, tig = lane & 3;
    int m0 = w * 16;
    size_t base = (size_t)b * SEQ * HID + (size_t)h * DK;

    #pragma unroll
    for (int i = 0; i < 8; i++) {
        int idx = tid + i * 256;
        int row = idx >> 4, c4 = idx & 15;
        *(float4*)&Ps[row * PS + c4 * 4] =
            *(const float4*)(Q + base + (size_t)(qt * 128 + row) * HID + c4 * 4);
    }
    __syncthreads();
    float qf[8][4];
    #pragma unroll
    for (int kd = 0; kd < 8; kd++) {
        qf[kd][0] = Ps[(m0 + g    ) * PS + kd * 8 + tig    ];
        qf[kd][1] = Ps[(m0 + g + 8) * PS + kd * 8 + tig    ];
        qf[kd][2] = Ps[(m0 + g    ) * PS + kd * 8 + tig + 4];
        qf[kd][3] = Ps[(m0 + g + 8) * PS + kd * 8 + tig + 4];
    }
    __syncwarp();

    float oacc[8][4] = {};
    float mr0 = -INFINITY, mr1 = -INFINITY, l0 = 0.f, l1 = 0.f;
    int r0g = qt * 128 + m0 + g;
    int r1g = r0g + 8;
    int ktmax = 2 * qt + 1;

    for (int kt = 0; kt <= ktmax; kt++) {
        __syncthreads();
        #pragma unroll
        for (int i = 0; i < 4; i++) {
            int idx = tid + i * 256;
            int row = idx >> 4, c4 = idx & 15;
            *(float4*)&Ks[row * KS + c4 * 4] =
                *(const float4*)(Q + base + (size_t)(kt * 64 + row) * HID + c4 * 4);
            *(float4*)&Vs[row * VS + c4 * 4] =
                *(const float4*)(V + base + (size_t)(kt * 64 + row) * HID + c4 * 4);
        }
        __syncthreads();

        float sacc[8][4] = {};
        #pragma unroll
        for (int kd = 0; kd < 8; kd++) {
            #pragma unroll
            for (int j = 0; j < 8; j++) {
                float b0 = Ks[(j * 8 + g) * KS + kd * 8 + tig    ];
                float b1 = Ks[(j * 8 + g) * KS + kd * 8 + tig + 4];
                mma_f(sacc[j], qf[kd][0], qf[kd][1], qf[kd][2], qf[kd][3], b0, b1);
            }
        }

        const float scale = 0.125f;
        if (kt >= 2 * qt) {
            #pragma unroll
            for (int j = 0; j < 8; j++) {
                int c0 = kt * 64 + j * 8 + 2 * tig;
                sacc[j][0] = (c0     > r0g) ? -INFINITY : sacc[j][0] * scale;
                sacc[j][1] = (c0 + 1 > r0g) ? -INFINITY : sacc[j][1] * scale;
                sacc[j][2] = (c0     > r1g) ? -INFINITY : sacc[j][2] * scale;
                sacc[j][3] = (c0 + 1 > r1g) ? -INFINITY : sacc[j][3] * scale;
            }
        } else {
            #pragma unroll
            for (int j = 0; j < 8; j++)
                #pragma unroll
                for (int c = 0; c < 4; c++) sacc[j][c] *= scale;
        }

        float mt0 = mr0, mt1 = mr1;
        #pragma unroll
        for (int j = 0; j < 8; j++) {
            mt0 = fmaxf(mt0, fmaxf(sacc[j][0], sacc[j][1]));
            mt1 = fmaxf(mt1, fmaxf(sacc[j][2], sacc[j][3]));
        }
        mt0 = fmaxf(mt0, __shfl_xor_sync(0xffffffffu, mt0, 1));
        mt0 = fmaxf(mt0, __shfl_xor_sync(0xffffffffu, mt0, 2));
        mt1 = fmaxf(mt1, __shfl_xor_sync(0xffffffffu, mt1, 1));
        mt1 = fmaxf(mt1, __shfl_xor_sync(0xffffffffu, mt1, 2));
        float alpha0 = __expf(mr0 - mt0);
        float alpha1 = __expf(mr1 - mt1);
        mr0 = mt0; mr1 = mt1;
        float ps0 = 0.f, ps1 = 0.f;
        #pragma unroll
        for (int j = 0; j < 8; j++) {
            sacc[j][0] = __expf(sacc[j][0] - mt0); ps0 += sacc[j][0];
            sacc[j][1] = __expf(sacc[j][1] - mt0); ps0 += sacc[j][1];
            sacc[j][2] = __expf(sacc[j][2] - mt1); ps1 += sacc[j][2];
            sacc[j][3] = __expf(sacc[j][3] - mt1); ps1 += sacc[j][3];
        }
        ps0 += __shfl_xor_sync(0xffffffffu, ps0, 1);
        ps0 += __shfl_xor_sync(0xffffffffu, ps0, 2);
        ps1 += __shfl_xor_sync(0xffffffffu, ps1, 1);
        ps1 += __shfl_xor_sync(0xffffffffu, ps1, 2);
        l0 = l0 * alpha0 + ps0;
        l1 = l1 * alpha1 + ps1;
        #pragma unroll
        for (int j = 0; j < 8; j++) {
            oacc[j][0] *= alpha0; oacc[j][1] *= alpha0;
            oacc[j][2] *= alpha1; oacc[j][3] *= alpha1;
        }

        __syncwarp();
        #pragma unroll
        for (int j = 0; j < 8; j++) {
            *(float2*)&Ps[(m0 + g    ) * PS + j * 8 + 2 * tig] =
                make_float2(sacc[j][0], sacc[j][1]);
            *(float2*)&Ps[(m0 + g + 8) * PS + j * 8 + 2 * tig] =
                make_float2(sacc[j][2], sacc[j][3]);
        }
        __syncwarp();

        #pragma unroll
        for (int kp = 0; kp < 8; kp++) {
            float a0 = Ps[(m0 + g    ) * PS + kp * 8 + tig    ];
            float a1 = Ps[(m0 + g + 8) * PS + kp * 8 + tig    ];
            float a2 = Ps[(m0 + g    ) * PS + kp * 8 + tig + 4];
            float a3 = Ps[(m0 + g + 8) * PS + kp * 8 + tig + 4];
            #pragma unroll
            for (int j = 0; j < 8; j++) {
                float b0 = Vs[(kp * 8 + tig    ) * VS + j * 8 + g];
                float b1 = Vs[(kp * 8 + tig + 4) * VS + j * 8 + g];
                mma_f(oacc[j], a0, a1, a2, a3, b0, b1);
            }
        }
    }

    float inv0 = 1.f / l0, inv1 = 1.f / l1;
    #pragma unroll
    for (int j = 0; j < 8; j++) {
        int col = j * 8 + 2 * tig;
        *(__half2*)(O + base + (size_t)r0g * HID + col) =
            __floats2half2_rn(oacc[j][0] * inv0, oacc[j][1] * inv0);
        *(__half2*)(O + base + (size_t)r1g * HID + col) =
            __floats2half2_rn(oacc[j][2] * inv1, oacc[j][3] * inv1);
    }
}

// ---------------- launch ----------------
extern "C" void kernel_launch(void* const* d_in, const int* in_sizes, int n_in,
                              void* d_out, int out_size)
{
    const float* x     = (const float*)d_in[0];
    const float* Wq    = (const float*)d_in[1];
    const float* bq    = (const float*)d_in[2];
    const float* Wv    = (const float*)d_in[3];
    const float* bv    = (const float*)d_in[4];
    const float* Wo    = (const float*)d_in[5];
    const float* bo    = (const float*)d_in[6];
    const float* W1    = (const float*)d_in[7];
    const float* b1    = (const float*)d_in[8];
    const float* W2    = (const float*)d_in[9];
    const float* b2    = (const float*)d_in[10];
    const float* g1    = (const float*)d_in[11];
    const float* beta1 = (const float*)d_in[12];
    const float* g2    = (const float*)d_in[13];
    const float* beta2 = (const float*)d_in[14];
    float* out = (float*)d_out;

    float *q, *v, *x1;
    __half *ln16, *ctx16, *h116, *wqt, *wvt, *wot, *w1t, *w2t;
    cudaGetSymbolAddress((void**)&q,     g_q);
    cudaGetSymbolAddress((void**)&v,     g_v);
    cudaGetSymbolAddress((void**)&x1,    g_x1);
    cudaGetSymbolAddress((void**)&ln16,  g_ln16);
    cudaGetSymbolAddress((void**)&ctx16, g_ctx16);
    cudaGetSymbolAddress((void**)&h116,  g_h116);
    cudaGetSymbolAddress((void**)&wqt,   g_wqt);
    cudaGetSymbolAddress((void**)&wvt,   g_wvt);
    cudaGetSymbolAddress((void**)&wot,   g_wot);
    cudaGetSymbolAddress((void**)&w1t,   g_w1t);
    cudaGetSymbolAddress((void**)&w2t,   g_w2t);

    const int attn_smem = (64 * 68 + 64 * 72 + 128 * 68) * 4;   // 70656 B
    cudaFuncSetAttribute(attn_mma,
                         cudaFuncAttributeMaxDynamicSharedMemorySize, attn_smem);

    dim3 tblk(32, 8);
    transpose_k<<<dim3(HID / 32, HID / 32),   tblk>>>(Wq, wqt, HID, HID);
    transpose_k<<<dim3(HID / 32, HID / 32),   tblk>>>(Wv, wvt, HID, HID);
    transpose_k<<<dim3(HID / 32, HID / 32),   tblk>>>(Wo, wot, HID, HID);
    transpose_k<<<dim3(FFDIM / 32, HID / 32), tblk>>>(W1, w1t, HID, FFDIM);
    transpose_k<<<dim3(HID / 32, FFDIM / 32), tblk>>>(W2, w2t, FFDIM, HID);

    dim3 blk(256);
    dim3 gHID(HID / 128, TOKENS / 128);     // (8, 32)
    dim3 gFF (FFDIM / 128, TOKENS / 128);   // (32, 32)

    // ln16 = LN(x)
    ln_kernel<<<TOKENS, blk>>>(x, g1, beta1, ln16);
    // q = ln16 @ Wq + bq ; v = ln16 @ Wv + bv   (fp32 outs for attention)
    hgemm<0, float><<<gHID, blk>>>(TOKENS, HID, HID, ln16, wqt, bq, nullptr, q);
    hgemm<0, float><<<gHID, blk>>>(TOKENS, HID, HID, ln16, wvt, bv, nullptr, v);
    // causal attention (Q == K), fp16 ctx out
    attn_mma<<<dim3(SEQ / 128, 2 * NHEADS), blk, attn_smem>>>(q, v, ctx16);
    // x1 = x + ctx @ Wo + bo
    hgemm<1, float><<<gHID, blk>>>(TOKENS, HID, HID, ctx16, wot, bo, x, x1);
    // ln16 = LN(x1)
    ln_kernel<<<TOKENS, blk>>>(x1, g2, beta2, ln16);
    // h1 = gelu(ln16 @ W1 + b1), fp16 out
    hgemm<2, __half><<<gFF, blk>>>(TOKENS, FFDIM, HID, ln16, w1t, b1, nullptr, h116);
    // out = x1 + h1 @ W2 + b2
    hgemm<1, float><<<gHID, blk>>>(TOKENS, HID, FFDIM, h116, w2t, b2, x1, out);
}

// round 7
// speedup vs baseline: 8.6616x; 1.1669x over previous
#include <cuda_runtime.h>
#include <cuda_fp16.h>
#include <math.h>
#include <stdint.h>

#define TOKENS 4096      // 2 * 2048
#define HID    1024
#define FFDIM  4096
#define SEQ    2048
#define NHEADS 16
#define DK     64

// ---------------- scratch (device globals; no allocs allowed) ----------------
__device__ float  g_x1  [TOKENS * HID];
__device__ __half g_q16 [TOKENS * HID];
__device__ __half g_v16 [TOKENS * HID];
__device__ __half g_ln16[TOKENS * HID];
__device__ __half g_ctx16[TOKENS * HID];
__device__ __half g_h116[(size_t)TOKENS * FFDIM];
// transposed fp16 weights, (N, K) row-major
__device__ __half g_wqt[HID * HID];
__device__ __half g_wvt[HID * HID];
__device__ __half g_wot[HID * HID];
__device__ __half g_w1t[(size_t)HID * FFDIM];
__device__ __half g_w2t[(size_t)HID * FFDIM];

// ---------------- LayerNorm: one block per row, fp16 out ----------------
__global__ __launch_bounds__(256) void ln_kernel(
    const float* __restrict__ x, const float* __restrict__ gamma,
    const float* __restrict__ beta, __half* __restrict__ out)
{
    int row = blockIdx.x;
    int t = threadIdx.x;
    const float4* xr = (const float4*)(x + (size_t)row * HID);
    float4 v = xr[t];
    float s  = v.x + v.y + v.z + v.w;
    float ss = v.x*v.x + v.y*v.y + v.z*v.z + v.w*v.w;
    #pragma unroll
    for (int o = 16; o; o >>= 1) {
        s  += __shfl_xor_sync(0xffffffffu, s,  o);
        ss += __shfl_xor_sync(0xffffffffu, ss, o);
    }
    __shared__ float rs[8], rss[8];
    if ((t & 31) == 0) { rs[t >> 5] = s; rss[t >> 5] = ss; }
    __syncthreads();
    s = 0.f; ss = 0.f;
    #pragma unroll
    for (int i = 0; i < 8; i++) { s += rs[i]; ss += rss[i]; }
    float mu  = s * (1.f / HID);
    float var = ss * (1.f / HID) - mu * mu;
    float inv = rsqrtf(var + 1e-5f);
    float4 g4 = ((const float4*)gamma)[t];
    float4 b4 = ((const float4*)beta)[t];
    __half2 pk2[2];
    pk2[0] = __floats2half2_rn((v.x - mu) * inv * g4.x + b4.x,
                               (v.y - mu) * inv * g4.y + b4.y);
    pk2[1] = __floats2half2_rn((v.z - mu) * inv * g4.z + b4.z,
                               (v.w - mu) * inv * g4.w + b4.w);
    *(uint2*)(out + (size_t)row * HID + t * 4) = *(const uint2*)pk2;
}

// ---------------- weight transpose: in (K,N) fp32 -> out (N,K) fp16 --------
__global__ __launch_bounds__(256) void transpose_k(
    const float* __restrict__ in, __half* __restrict__ out, int K, int N)
{
    __shared__ float tl[32][33];
    int tx = threadIdx.x, ty = threadIdx.y;
    int n0 = blockIdx.x * 32, k0 = blockIdx.y * 32;
    #pragma unroll
    for (int i = 0; i < 32; i += 8)
        tl[ty + i][tx] = in[(size_t)(k0 + ty + i) * N + n0 + tx];
    __syncthreads();
    #pragma unroll
    for (int i = 0; i < 32; i += 8)
        out[(size_t)(n0 + ty + i) * K + k0 + tx] = __float2half(tl[tx][ty + i]);
}

// ---------------- GELU (tanh approx, matches reference) ----------------
__device__ __forceinline__ float gelu_f(float x)
{
    float u = 0.7978845608028654f * (x + 0.044715f * x * x * x);
    return 0.5f * x * (1.f + tanhf(u));
}

// ---------------- FP16 MMA m16n8k16, fp32 accumulate ----------------
__device__ __forceinline__ void mma_h(
    float* c, uint32_t a0, uint32_t a1, uint32_t a2, uint32_t a3,
    uint32_t b0, uint32_t b1)
{
    asm volatile(
        "mma.sync.aligned.m16n8k16.row.col.f32.f16.f16.f32 "
        "{%0,%1,%2,%3}, {%4,%5,%6,%7}, {%8,%9}, {%0,%1,%2,%3};"
        : "+f"(c[0]), "+f"(c[1]), "+f"(c[2]), "+f"(c[3])
        : "r"(a0), "r"(a1), "r"(a2), "r"(a3), "r"(b0), "r"(b1));
}

__device__ __forceinline__ void cp16(void* s, const void* g)
{
    unsigned sa = (unsigned)__cvta_generic_to_shared(s);
    asm volatile("cp.async.cg.shared.global [%0], [%1], 16;" :: "r"(sa), "l"(g));
}

__device__ __forceinline__ uint32_t U32(const __half* p)
{
    return *(const uint32_t*)p;
}

// paired-store helpers (fp32 or fp16 output)
__device__ __forceinline__ void st2(float* p, float x, float y)
{
    *(float2*)p = make_float2(x, y);
}
__device__ __forceinline__ void st2(__half* p, float x, float y)
{
    *(__half2*)p = __floats2half2_rn(x, y);
}

// ---------------- FP16 tensor-core GEMM, cp.async double-buffered ----------
// C = A(MxK) @ Bt(NxK)^T + bias (+res / gelu).  BM=BN=128, BK=32.
// EPI: 0 = bias, 1 = bias + residual, 2 = gelu(bias + acc)
template <int EPI, typename OT>
__global__ __launch_bounds__(256, 2) void hgemm(
    int M, int N, int K,
    const __half* __restrict__ A, const __half* __restrict__ Bt,
    const float* __restrict__ bias, const float* __restrict__ R,
    OT* __restrict__ C)
{
    __shared__ __half As[2][128][40];   // [m][k], 40-half rows (80 B, 16B-mult)
    __shared__ __half Bs[2][128][40];   // [n][k]

    int tid  = threadIdx.x;
    int lane = tid & 31, w = tid >> 5;
    int wm = w >> 1, wn = w & 1;
    int g = lane >> 2, tig = lane & 3;
    int bx = blockIdx.x, by = blockIdx.y;

    const __half* Ab = A  + (size_t)by * 128 * K;
    const __half* Bb = Bt + (size_t)bx * 128 * K;

    float acc[2][8][4] = {};
    int NT = K >> 5;

    {
        #pragma unroll
        for (int i = 0; i < 2; i++) {
            int idx = tid + i * 256;
            int r = idx >> 2, ch = idx & 3;
            cp16(&As[0][r][ch * 8], Ab + (size_t)r * K + ch * 8);
        }
        #pragma unroll
        for (int i = 0; i < 2; i++) {
            int idx = tid + i * 256;
            int r = idx >> 2, ch = idx & 3;
            cp16(&Bs[0][r][ch * 8], Bb + (size_t)r * K + ch * 8);
        }
        asm volatile("cp.async.commit_group;");
    }

    for (int t = 0; t < NT; t++) {
        if (t + 1 < NT) {
            int s = (t + 1) & 1, k0 = (t + 1) << 5;
            #pragma unroll
            for (int i = 0; i < 2; i++) {
                int idx = tid + i * 256;
                int r = idx >> 2, ch = idx & 3;
                cp16(&As[s][r][ch * 8], Ab + (size_t)r * K + k0 + ch * 8);
            }
            #pragma unroll
            for (int i = 0; i < 2; i++) {
                int idx = tid + i * 256;
                int r = idx >> 2, ch = idx & 3;
                cp16(&Bs[s][r][ch * 8], Bb + (size_t)r * K + k0 + ch * 8);
            }
        }
        asm volatile("cp.async.commit_group;");
        asm volatile("cp.async.wait_group 1;");
        __syncthreads();

        int s = t & 1;
        #pragma unroll
        for (int kk = 0; kk < 2; kk++) {
            int k8 = kk * 8;
            uint32_t a[2][4];
            #pragma unroll
            for (int i = 0; i < 2; i++) {
                int r0 = wm * 32 + i * 16;
                a[i][0] = U32(&As[s][r0 + g    ][2 * (k8 + tig)]);
                a[i][1] = U32(&As[s][r0 + g + 8][2 * (k8 + tig)]);
                a[i][2] = U32(&As[s][r0 + g    ][2 * (k8 + tig + 4)]);
                a[i][3] = U32(&As[s][r0 + g + 8][2 * (k8 + tig + 4)]);
            }
            #pragma unroll
            for (int j = 0; j < 8; j++) {
                int bn = wn * 64 + j * 8 + g;
                uint32_t b0 = U32(&Bs[s][bn][2 * (k8 + tig)]);
                uint32_t b1 = U32(&Bs[s][bn][2 * (k8 + tig + 4)]);
                #pragma unroll
                for (int i = 0; i < 2; i++)
                    mma_h(acc[i][j], a[i][0], a[i][1], a[i][2], a[i][3], b0, b1);
            }
        }
        __syncthreads();
    }

    #pragma unroll
    for (int i = 0; i < 2; i++) {
        int r0 = by * 128 + wm * 32 + i * 16 + g;
        int r1 = r0 + 8;
        #pragma unroll
        for (int j = 0; j < 8; j++) {
            int col = bx * 128 + wn * 64 + j * 8 + tig * 2;
            float2 bb = *(const float2*)(bias + col);
            float v00 = acc[i][j][0] + bb.x, v01 = acc[i][j][1] + bb.y;
            float v10 = acc[i][j][2] + bb.x, v11 = acc[i][j][3] + bb.y;
            if (EPI == 1) {
                float2 q0 = *(const float2*)(R + (size_t)r0 * N + col);
                float2 q1 = *(const float2*)(R + (size_t)r1 * N + col);
                v00 += q0.x; v01 += q0.y;
                v10 += q1.x; v11 += q1.y;
            } else if (EPI == 2) {
                v00 = gelu_f(v00); v01 = gelu_f(v01);
                v10 = gelu_f(v10); v11 = gelu_f(v11);
            }
            st2(C + (size_t)r0 * N + col, v00, v01);
            st2(C + (size_t)r1 * N + col, v10, v11);
        }
    }
}

// ---------------- FP16 tensor-core causal flash attention (Q doubles as K) --
// Block: 128 q-rows, 8 warps; K/V tiles of 64; fp16 in/out; fp32 softmax.
// Reversed qt mapping: longest blocks first.
#define SH 72   // smem row stride in halves (conflict-free, 16B-multiple)
__global__ __launch_bounds__(256, 2) void attn_h(
    const __half* __restrict__ Q, const __half* __restrict__ V,
    __half* __restrict__ O)
{
    __shared__ __half Ks[64][SH];
    __shared__ __half Vs[64][SH];
    __shared__ __half Ps[128][SH];      // Q staging, then P (warp-private rows)

    int qt = (int)gridDim.x - 1 - (int)blockIdx.x;
    int bh = blockIdx.y;
    int b = bh >> 4, h = bh & 15;
    int tid = threadIdx.x, lane = tid & 31, w = tid >> 5;
    int g = lane >> 2, tig = lane & 3;
    int m0 = w * 16;
    size_t base = (size_t)b * SEQ * HID + (size_t)h * DK;

    // ---- stage Q tile (128 x 64 halves), then lift fragments ----
    #pragma unroll
    for (int i = 0; i < 4; i++) {
        int idx = tid + i * 256;            // 128 rows x 8 uint4
        int row = idx >> 3, c8 = idx & 7;
        *(uint4*)&Ps[row][c8 * 8] =
            *(const uint4*)(Q + base + (size_t)(qt * 128 + row) * HID + c8 * 8);
    }
    __syncthreads();
    uint32_t qf[4][4];
    #pragma unroll
    for (int kg = 0; kg < 4; kg++) {
        qf[kg][0] = U32(&Ps[m0 + g    ][kg * 16 + 2 * tig]);
        qf[kg][1] = U32(&Ps[m0 + g + 8][kg * 16 + 2 * tig]);
        qf[kg][2] = U32(&Ps[m0 + g    ][kg * 16 + 8 + 2 * tig]);
        qf[kg][3] = U32(&Ps[m0 + g + 8][kg * 16 + 8 + 2 * tig]);
    }
    __syncwarp();

    float oacc[8][4] = {};
    float mr0 = -INFINITY, mr1 = -INFINITY, l0 = 0.f, l1 = 0.f;
    int r0g = qt * 128 + m0 + g;
    int r1g = r0g + 8;
    int ktmax = 2 * qt + 1;

    for (int kt = 0; kt <= ktmax; kt++) {
        __syncthreads();
        #pragma unroll
        for (int i = 0; i < 2; i++) {
            int idx = tid + i * 256;        // 64 rows x 8 uint4 each for K and V
            int row = idx >> 3, c8 = idx & 7;
            *(uint4*)&Ks[row][c8 * 8] =
                *(const uint4*)(Q + base + (size_t)(kt * 64 + row) * HID + c8 * 8);
            *(uint4*)&Vs[row][c8 * 8] =
                *(const uint4*)(V + base + (size_t)(kt * 64 + row) * HID + c8 * 8);
        }
        __syncthreads();

        // ---- S = Q K^T ----
        float sacc[8][4] = {};
        #pragma unroll
        for (int kg = 0; kg < 4; kg++) {
            #pragma unroll
            for (int j = 0; j < 8; j++) {
                uint32_t b0 = U32(&Ks[j * 8 + g][kg * 16 + 2 * tig]);
                uint32_t b1 = U32(&Ks[j * 8 + g][kg * 16 + 8 + 2 * tig]);
                mma_h(sacc[j], qf[kg][0], qf[kg][1], qf[kg][2], qf[kg][3], b0, b1);
            }
        }

        // ---- scale + causal mask ----
        const float scale = 0.125f;         // 1/sqrt(64)
        if (kt >= 2 * qt) {
            #pragma unroll
            for (int j = 0; j < 8; j++) {
                int c0 = kt * 64 + j * 8 + 2 * tig;
                sacc[j][0] = (c0     > r0g) ? -INFINITY : sacc[j][0] * scale;
                sacc[j][1] = (c0 + 1 > r0g) ? -INFINITY : sacc[j][1] * scale;
                sacc[j][2] = (c0     > r1g) ? -INFINITY : sacc[j][2] * scale;
                sacc[j][3] = (c0 + 1 > r1g) ? -INFINITY : sacc[j][3] * scale;
            }
        } else {
            #pragma unroll
            for (int j = 0; j < 8; j++)
                #pragma unroll
                for (int c = 0; c < 4; c++) sacc[j][c] *= scale;
        }

        // ---- online softmax (fp32) ----
        float mt0 = mr0, mt1 = mr1;
        #pragma unroll
        for (int j = 0; j < 8; j++) {
            mt0 = fmaxf(mt0, fmaxf(sacc[j][0], sacc[j][1]));
            mt1 = fmaxf(mt1, fmaxf(sacc[j][2], sacc[j][3]));
        }
        mt0 = fmaxf(mt0, __shfl_xor_sync(0xffffffffu, mt0, 1));
        mt0 = fmaxf(mt0, __shfl_xor_sync(0xffffffffu, mt0, 2));
        mt1 = fmaxf(mt1, __shfl_xor_sync(0xffffffffu, mt1, 1));
        mt1 = fmaxf(mt1, __shfl_xor_sync(0xffffffffu, mt1, 2));
        float alpha0 = __expf(mr0 - mt0);
        float alpha1 = __expf(mr1 - mt1);
        mr0 = mt0; mr1 = mt1;
        float ps0 = 0.f, ps1 = 0.f;
        #pragma unroll
        for (int j = 0; j < 8; j++) {
            sacc[j][0] = __expf(sacc[j][0] - mt0); ps0 += sacc[j][0];
            sacc[j][1] = __expf(sacc[j][1] - mt0); ps0 += sacc[j][1];
            sacc[j][2] = __expf(sacc[j][2] - mt1); ps1 += sacc[j][2];
            sacc[j][3] = __expf(sacc[j][3] - mt1); ps1 += sacc[j][3];
        }
        ps0 += __shfl_xor_sync(0xffffffffu, ps0, 1);
        ps0 += __shfl_xor_sync(0xffffffffu, ps0, 2);
        ps1 += __shfl_xor_sync(0xffffffffu, ps1, 1);
        ps1 += __shfl_xor_sync(0xffffffffu, ps1, 2);
        l0 = l0 * alpha0 + ps0;
        l1 = l1 * alpha1 + ps1;
        #pragma unroll
        for (int j = 0; j < 8; j++) {
            oacc[j][0] *= alpha0; oacc[j][1] *= alpha0;
            oacc[j][2] *= alpha1; oacc[j][3] *= alpha1;
        }

        // ---- P -> smem fp16 (warp-private rows) ----
        __syncwarp();
        #pragma unroll
        for (int j = 0; j < 8; j++) {
            *(__half2*)&Ps[m0 + g    ][j * 8 + 2 * tig] =
                __floats2half2_rn(sacc[j][0], sacc[j][1]);
            *(__half2*)&Ps[m0 + g + 8][j * 8 + 2 * tig] =
                __floats2half2_rn(sacc[j][2], sacc[j][3]);
        }
        __syncwarp();

        // ---- O += P V  (V B-fragments via ldmatrix.trans) ----
        #pragma unroll
        for (int kp = 0; kp < 4; kp++) {
            uint32_t a0 = U32(&Ps[m0 + g    ][kp * 16 + 2 * tig]);
            uint32_t a1 = U32(&Ps[m0 + g + 8][kp * 16 + 2 * tig]);
            uint32_t a2 = U32(&Ps[m0 + g    ][kp * 16 + 8 + 2 * tig]);
            uint32_t a3 = U32(&Ps[m0 + g + 8][kp * 16 + 8 + 2 * tig]);
            unsigned vrow = (unsigned)__cvta_generic_to_shared(
                &Vs[kp * 16 + (lane & 15)][0]);
            #pragma unroll
            for (int j = 0; j < 8; j++) {
                uint32_t b0, b1;
                asm volatile(
                    "ldmatrix.sync.aligned.m8n8.x2.trans.shared.b16 {%0,%1}, [%2];"
                    : "=r"(b0), "=r"(b1) : "r"(vrow + j * 16));
                mma_h(oacc[j], a0, a1, a2, a3, b0, b1);
            }
        }
    }

    // ---- normalize + write fp16 ----
    float inv0 = 1.f / l0, inv1 = 1.f / l1;
    #pragma unroll
    for (int j = 0; j < 8; j++) {
        int col = j * 8 + 2 * tig;
        *(__half2*)(O + base + (size_t)r0g * HID + col) =
            __floats2half2_rn(oacc[j][0] * inv0, oacc[j][1] * inv0);
        *(__half2*)(O + base + (size_t)r1g * HID + col) =
            __floats2half2_rn(oacc[j][2] * inv1, oacc[j][3] * inv1);
    }
}

// ---------------- launch ----------------
extern "C" void kernel_launch(void* const* d_in, const int* in_sizes, int n_in,
                              void* d_out, int out_size)
{
    const float* x     = (const float*)d_in[0];
    const float* Wq    = (const float*)d_in[1];
    const float* bq    = (const float*)d_in[2];
    const float* Wv    = (const float*)d_in[3];
    const float* bv    = (const float*)d_in[4];
    const float* Wo    = (const float*)d_in[5];
    const float* bo    = (const float*)d_in[6];
    const float* W1    = (const float*)d_in[7];
    const float* b1    = (const float*)d_in[8];
    const float* W2    = (const float*)d_in[9];
    const float* b2    = (const float*)d_in[10];
    const float* g1    = (const float*)d_in[11];
    const float* beta1 = (const float*)d_in[12];
    const float* g2    = (const float*)d_in[13];
    const float* beta2 = (const float*)d_in[14];
    float* out = (float*)d_out;

    float *x1;
    __half *q16, *v16, *ln16, *ctx16, *h116, *wqt, *wvt, *wot, *w1t, *w2t;
    cudaGetSymbolAddress((void**)&x1,    g_x1);
    cudaGetSymbolAddress((void**)&q16,   g_q16);
    cudaGetSymbolAddress((void**)&v16,   g_v16);
    cudaGetSymbolAddress((void**)&ln16,  g_ln16);
    cudaGetSymbolAddress((void**)&ctx16, g_ctx16);
    cudaGetSymbolAddress((void**)&h116,  g_h116);
    cudaGetSymbolAddress((void**)&wqt,   g_wqt);
    cudaGetSymbolAddress((void**)&wvt,   g_wvt);
    cudaGetSymbolAddress((void**)&wot,   g_wot);
    cudaGetSymbolAddress((void**)&w1t,   g_w1t);
    cudaGetSymbolAddress((void**)&w2t,   g_w2t);

    dim3 tblk(32, 8);
    transpose_k<<<dim3(HID / 32, HID / 32),   tblk>>>(Wq, wqt, HID, HID);
    transpose_k<<<dim3(HID / 32, HID / 32),   tblk>>>(Wv, wvt, HID, HID);
    transpose_k<<<dim3(HID / 32, HID / 32),   tblk>>>(Wo, wot, HID, HID);
    transpose_k<<<dim3(FFDIM / 32, HID / 32), tblk>>>(W1, w1t, HID, FFDIM);
    transpose_k<<<dim3(HID / 32, FFDIM / 32), tblk>>>(W2, w2t, FFDIM, HID);

    dim3 blk(256);
    dim3 gHID(HID / 128, TOKENS / 128);     // (8, 32)
    dim3 gFF (FFDIM / 128, TOKENS / 128);   // (32, 32)

    // ln16 = LN(x)
    ln_kernel<<<TOKENS, blk>>>(x, g1, beta1, ln16);
    // q = ln16 @ Wq + bq ; v = ln16 @ Wv + bv   (fp16 outs)
    hgemm<0, __half><<<gHID, blk>>>(TOKENS, HID, HID, ln16, wqt, bq, nullptr, q16);
    hgemm<0, __half><<<gHID, blk>>>(TOKENS, HID, HID, ln16, wvt, bv, nullptr, v16);
    // causal attention (Q == K), all fp16 operands
    attn_h<<<dim3(SEQ / 128, 2 * NHEADS), blk>>>(q16, v16, ctx16);
    // x1 = x + ctx @ Wo + bo
    hgemm<1, float><<<gHID, blk>>>(TOKENS, HID, HID, ctx16, wot, bo, x, x1);
    // ln16 = LN(x1)
    ln_kernel<<<TOKENS, blk>>>(x1, g2, beta2, ln16);
    // h1 = gelu(ln16 @ W1 + b1), fp16 out
    hgemm<2, __half><<<gFF, blk>>>(TOKENS, FFDIM, HID, ln16, w1t, b1, nullptr, h116);
    // out = x1 + h1 @ W2 + b2
    hgemm<1, float><<<gHID, blk>>>(TOKENS, HID, FFDIM, h116, w2t, b2, x1, out);
}

// round 9
// speedup vs baseline: 9.4888x; 1.0955x over previous
#include <cuda_runtime.h>
#include <cuda_fp16.h>
#include <math.h>
#include <stdint.h>

#define TOKENS 4096      // 2 * 2048
#define HID    1024
#define FFDIM  4096
#define SEQ    2048
#define NHEADS 16
#define DK     64

// ---------------- scratch (device globals; no allocs allowed) ----------------
__device__ float  g_x1  [TOKENS * HID];
__device__ __half g_q16 [TOKENS * HID];
__device__ __half g_v16 [TOKENS * HID];
__device__ __half g_ln16[TOKENS * HID];
__device__ __half g_ctx16[TOKENS * HID];
__device__ __half g_h116[(size_t)TOKENS * FFDIM];
// fp16 weights, SAME (K, N) row-major layout as the fp32 originals
__device__ __half g_wq16[HID * HID];
__device__ __half g_wv16[HID * HID];
__device__ __half g_wo16[HID * HID];
__device__ __half g_w116[(size_t)HID * FFDIM];
__device__ __half g_w216[(size_t)HID * FFDIM];

// ---------------- elementwise fp32 -> fp16 convert ----------------
__global__ __launch_bounds__(256) void cvt16(
    const float* __restrict__ in, __half* __restrict__ out, int n)
{
    int i = (blockIdx.x * 256 + threadIdx.x) * 4;
    if (i < n) {
        float4 v = *(const float4*)(in + i);
        __half2 pk2[2];
        pk2[0] = __floats2half2_rn(v.x, v.y);
        pk2[1] = __floats2half2_rn(v.z, v.w);
        *(uint2*)(out + i) = *(const uint2*)pk2;
    }
}

// ---------------- LayerNorm: one block per row, fp16 out ----------------
__global__ __launch_bounds__(256) void ln_kernel(
    const float* __restrict__ x, const float* __restrict__ gamma,
    const float* __restrict__ beta, __half* __restrict__ out)
{
    int row = blockIdx.x;
    int t = threadIdx.x;
    const float4* xr = (const float4*)(x + (size_t)row * HID);
    float4 v = xr[t];
    float s  = v.x + v.y + v.z + v.w;
    float ss = v.x*v.x + v.y*v.y + v.z*v.z + v.w*v.w;
    #pragma unroll
    for (int o = 16; o; o >>= 1) {
        s  += __shfl_xor_sync(0xffffffffu, s,  o);
        ss += __shfl_xor_sync(0xffffffffu, ss, o);
    }
    __shared__ float rs[8], rss[8];
    if ((t & 31) == 0) { rs[t >> 5] = s; rss[t >> 5] = ss; }
    __syncthreads();
    s = 0.f; ss = 0.f;
    #pragma unroll
    for (int i = 0; i < 8; i++) { s += rs[i]; ss += rss[i]; }
    float mu  = s * (1.f / HID);
    float var = ss * (1.f / HID) - mu * mu;
    float inv = rsqrtf(var + 1e-5f);
    float4 g4 = ((const float4*)gamma)[t];
    float4 b4 = ((const float4*)beta)[t];
    __half2 pk2[2];
    pk2[0] = __floats2half2_rn((v.x - mu) * inv * g4.x + b4.x,
                               (v.y - mu) * inv * g4.y + b4.y);
    pk2[1] = __floats2half2_rn((v.z - mu) * inv * g4.z + b4.z,
                               (v.w - mu) * inv * g4.w + b4.w);
    *(uint2*)(out + (size_t)row * HID + t * 4) = *(const uint2*)pk2;
}

// ---------------- GELU (tanh approx, matches reference) ----------------
__device__ __forceinline__ float gelu_f(float x)
{
    float u = 0.7978845608028654f * (x + 0.044715f * x * x * x);
    return 0.5f * x * (1.f + tanhf(u));
}

// ---------------- FP16 MMA m16n8k16, fp32 accumulate ----------------
__device__ __forceinline__ void mma_h(
    float* c, uint32_t a0, uint32_t a1, uint32_t a2, uint32_t a3,
    uint32_t b0, uint32_t b1)
{
    asm volatile(
        "mma.sync.aligned.m16n8k16.row.col.f32.f16.f16.f32 "
        "{%0,%1,%2,%3}, {%4,%5,%6,%7}, {%8,%9}, {%0,%1,%2,%3};"
        : "+f"(c[0]), "+f"(c[1]), "+f"(c[2]), "+f"(c[3])
        : "r"(a0), "r"(a1), "r"(a2), "r"(a3), "r"(b0), "r"(b1));
}

__device__ __forceinline__ void cp16(void* s, const void* g)
{
    unsigned sa = (unsigned)__cvta_generic_to_shared(s);
    asm volatile("cp.async.cg.shared.global [%0], [%1], 16;" :: "r"(sa), "l"(g));
}

__device__ __forceinline__ void ldm_x4(
    uint32_t* r, const __half* p)
{
    unsigned a = (unsigned)__cvta_generic_to_shared(p);
    asm volatile(
        "ldmatrix.sync.aligned.m8n8.x4.shared.b16 {%0,%1,%2,%3}, [%4];"
        : "=r"(r[0]), "=r"(r[1]), "=r"(r[2]), "=r"(r[3]) : "r"(a));
}

__device__ __forceinline__ void ldm_x4t(
    uint32_t* r, const __half* p)
{
    unsigned a = (unsigned)__cvta_generic_to_shared(p);
    asm volatile(
        "ldmatrix.sync.aligned.m8n8.x4.trans.shared.b16 {%0,%1,%2,%3}, [%4];"
        : "=r"(r[0]), "=r"(r[1]), "=r"(r[2]), "=r"(r[3]) : "r"(a));
}

__device__ __forceinline__ uint32_t U32(const __half* p)
{
    return *(const uint32_t*)p;
}

__device__ __forceinline__ void st2(float* p, float x, float y)
{
    *(float2*)p = make_float2(x, y);
}
__device__ __forceinline__ void st2(__half* p, float x, float y)
{
    *(__half2*)p = __floats2half2_rn(x, y);
}

// ---------------- FP16 GEMM: C = A(MxK) @ W(KxN) + bias (+res / gelu) ------
// W in native (K,N) row-major. BM=BN=128, BK=32, 3-stage cp.async pipeline.
// A smem [m][k] stride 40; B smem [k][n] stride 136. ldmatrix fragments.
// EPI: 0 = bias, 1 = bias + residual, 2 = gelu(bias + acc)
#define AS_H  (128 * 40)        // halves per A stage
#define BS_H  (32 * 136)        // halves per B stage
#define STG_H (AS_H + BS_H)     // halves per stage
#define HG_SMEM (3 * STG_H * 2) // bytes (56832)
template <int EPI, typename OT>
__global__ __launch_bounds__(256) void hgemm(
    int M, int N, int K,
    const __half* __restrict__ A, const __half* __restrict__ W,
    const float* __restrict__ bias, const float* __restrict__ R,
    OT* __restrict__ C)
{
    extern __shared__ __half hs[];

    int tid  = threadIdx.x;
    int lane = tid & 31, w = tid >> 5;
    int wm = w >> 1, wn = w & 1;
    int g = lane >> 2, tig = lane & 3;
    int bx = blockIdx.x, by = blockIdx.y;

    const __half* Ab = A + (size_t)by * 128 * K;
    const __half* Wb = W + bx * 128;

    // cp.async index precompute
    // A tile: 128 rows x 4 chunks of 8 halves = 512 chunks, 2 per thread
    int ar = tid >> 2, ac = (tid & 3) * 8;   // rows ar and ar+64
    // B tile: 32 rows x 16 chunks of 8 halves = 512 chunks, 2 per thread
    int br = tid >> 4, bc = (tid & 15) * 8;  // rows br and br+16

    auto stage_in = [&](int s, int t) {
        __half* As = hs + s * STG_H;
        __half* Bs = As + AS_H;
        int k0 = t << 5;
        cp16(As + ar * 40 + ac,        Ab + (size_t)ar * K + k0 + ac);
        cp16(As + (ar + 64) * 40 + ac, Ab + (size_t)(ar + 64) * K + k0 + ac);
        cp16(Bs + br * 136 + bc,       Wb + (size_t)(k0 + br) * N + bc);
        cp16(Bs + (br + 16) * 136 + bc,
             Wb + (size_t)(k0 + br + 16) * N + bc);
        asm volatile("cp.async.commit_group;");
    };

    float acc[2][8][4] = {};
    int NT = K >> 5;

    stage_in(0, 0);
    stage_in(1, 1);

    int s = 0;
    for (int t = 0; t < NT; t++) {
        asm volatile("cp.async.wait_group 1;");
        __syncthreads();

        if (t + 2 < NT) stage_in((s + 2) % 3, t + 2);
        else            asm volatile("cp.async.commit_group;");

        __half* As = hs + s * STG_H;
        __half* Bs = As + AS_H;

        #pragma unroll
        for (int kk = 0; kk < 2; kk++) {
            int k8 = kk * 16;               // halves base within 32-half row
            uint32_t a[2][4];
            #pragma unroll
            for (int i = 0; i < 2; i++)
                ldm_x4(a[i], As + (wm * 32 + i * 16 + (lane & 15)) * 40
                               + k8 + (lane >> 4) * 8);
            #pragma unroll
            for (int jp = 0; jp < 4; jp++) {
                uint32_t b[4];
                ldm_x4t(b, Bs + (k8 + (lane & 15)) * 136
                             + wn * 64 + jp * 16 + (lane >> 4) * 8);
                #pragma unroll
                for (int i = 0; i < 2; i++) {
                    mma_h(acc[i][2 * jp    ], a[i][0], a[i][1], a[i][2], a[i][3],
                          b[0], b[1]);
                    mma_h(acc[i][2 * jp + 1], a[i][0], a[i][1], a[i][2], a[i][3],
                          b[2], b[3]);
                }
            }
        }
        s = (s + 1) % 3;
    }

    // ---- epilogue ----
    #pragma unroll
    for (int i = 0; i < 2; i++) {
        int r0 = by * 128 + wm * 32 + i * 16 + g;
        int r1 = r0 + 8;
        #pragma unroll
        for (int j = 0; j < 8; j++) {
            int col = bx * 128 + wn * 64 + j * 8 + tig * 2;
            float2 bb = *(const float2*)(bias + col);
            float v00 = acc[i][j][0] + bb.x, v01 = acc[i][j][1] + bb.y;
            float v10 = acc[i][j][2] + bb.x, v11 = acc[i][j][3] + bb.y;
            if (EPI == 1) {
                float2 q0 = *(const float2*)(R + (size_t)r0 * N + col);
                float2 q1 = *(const float2*)(R + (size_t)r1 * N + col);
                v00 += q0.x; v01 += q0.y;
                v10 += q1.x; v11 += q1.y;
            } else if (EPI == 2) {
                v00 = gelu_f(v00); v01 = gelu_f(v01);
                v10 = gelu_f(v10); v11 = gelu_f(v11);
            }
            st2(C + (size_t)r0 * N + col, v00, v01);
            st2(C + (size_t)r1 * N + col, v10, v11);
        }
    }
}

// ---------------- FP16 tensor-core causal flash attention (Q doubles as K) --
#define SH 72
__global__ __launch_bounds__(256, 2) void attn_h(
    const __half* __restrict__ Q, const __half* __restrict__ V,
    __half* __restrict__ O)
{
    __shared__ __half Ks[64][SH];
    __shared__ __half Vs[64][SH];
    __shared__ __half Ps[128][SH];

    int qt = (int)gridDim.x - 1 - (int)blockIdx.x;
    int bh = blockIdx.y;
    int b = bh >> 4, h = bh & 15;
    int tid = threadIdx.x, lane = tid & 31, w = tid >> 5;
    int g = lane >> 2, tig = lane & 3;
    int m0 = w * 16;
    size_t base = (size_t)b * SEQ * HID + (size_t)h * DK;

    #pragma unroll
    for (int i = 0; i < 4; i++) {
        int idx = tid + i * 256;
        int row = idx >> 3, c8 = idx & 7;
        *(uint4*)&Ps[row][c8 * 8] =
            *(const uint4*)(Q + base + (size_t)(qt * 128 + row) * HID + c8 * 8);
    }
    __syncthreads();
    uint32_t qf[4][4];
    #pragma unroll
    for (int kg = 0; kg < 4; kg++) {
        qf[kg][0] = U32(&Ps[m0 + g    ][kg * 16 + 2 * tig]);
        qf[kg][1] = U32(&Ps[m0 + g + 8][kg * 16 + 2 * tig]);
        qf[kg][2] = U32(&Ps[m0 + g    ][kg * 16 + 8 + 2 * tig]);
        qf[kg][3] = U32(&Ps[m0 + g + 8][kg * 16 + 8 + 2 * tig]);
    }
    __syncwarp();

    float oacc[8][4] = {};
    float mr0 = -INFINITY, mr1 = -INFINITY, l0 = 0.f, l1 = 0.f;
    int r0g = qt * 128 + m0 + g;
    int r1g = r0g + 8;
    int ktmax = 2 * qt + 1;

    for (int kt = 0; kt <= ktmax; kt++) {
        __syncthreads();
        #pragma unroll
        for (int i = 0; i < 2; i++) {
            int idx = tid + i * 256;
            int row = idx >> 3, c8 = idx & 7;
            *(uint4*)&Ks[row][c8 * 8] =
                *(const uint4*)(Q + base + (size_t)(kt * 64 + row) * HID + c8 * 8);
            *(uint4*)&Vs[row][c8 * 8] =
                *(const uint4*)(V + base + (size_t)(kt * 64 + row) * HID + c8 * 8);
        }
        __syncthreads();

        float sacc[8][4] = {};
        #pragma unroll
        for (int kg = 0; kg < 4; kg++) {
            #pragma unroll
            for (int j = 0; j < 8; j++) {
                uint32_t b0 = U32(&Ks[j * 8 + g][kg * 16 + 2 * tig]);
                uint32_t b1 = U32(&Ks[j * 8 + g][kg * 16 + 8 + 2 * tig]);
                mma_h(sacc[j], qf[kg][0], qf[kg][1], qf[kg][2], qf[kg][3], b0, b1);
            }
        }

        const float scale = 0.125f;
        if (kt >= 2 * qt) {
            #pragma unroll
            for (int j = 0; j < 8; j++) {
                int c0 = kt * 64 + j * 8 + 2 * tig;
                sacc[j][0] = (c0     > r0g) ? -INFINITY : sacc[j][0] * scale;
                sacc[j][1] = (c0 + 1 > r0g) ? -INFINITY : sacc[j][1] * scale;
                sacc[j][2] = (c0     > r1g) ? -INFINITY : sacc[j][2] * scale;
                sacc[j][3] = (c0 + 1 > r1g) ? -INFINITY : sacc[j][3] * scale;
            }
        } else {
            #pragma unroll
            for (int j = 0; j < 8; j++)
                #pragma unroll
                for (int c = 0; c < 4; c++) sacc[j][c] *= scale;
        }

        float mt0 = mr0, mt1 = mr1;
        #pragma unroll
        for (int j = 0; j < 8; j++) {
            mt0 = fmaxf(mt0, fmaxf(sacc[j][0], sacc[j][1]));
            mt1 = fmaxf(mt1, fmaxf(sacc[j][2], sacc[j][3]));
        }
        mt0 = fmaxf(mt0, __shfl_xor_sync(0xffffffffu, mt0, 1));
        mt0 = fmaxf(mt0, __shfl_xor_sync(0xffffffffu, mt0, 2));
        mt1 = fmaxf(mt1, __shfl_xor_sync(0xffffffffu, mt1, 1));
        mt1 = fmaxf(mt1, __shfl_xor_sync(0xffffffffu, mt1, 2));
        float alpha0 = __expf(mr0 - mt0);
        float alpha1 = __expf(mr1 - mt1);
        mr0 = mt0; mr1 = mt1;
        float ps0 = 0.f, ps1 = 0.f;
        #pragma unroll
        for (int j = 0; j < 8; j++) {
            sacc[j][0] = __expf(sacc[j][0] - mt0); ps0 += sacc[j][0];
            sacc[j][1] = __expf(sacc[j][1] - mt0); ps0 += sacc[j][1];
            sacc[j][2] = __expf(sacc[j][2] - mt1); ps1 += sacc[j][2];
            sacc[j][3] = __expf(sacc[j][3] - mt1); ps1 += sacc[j][3];
        }
        ps0 += __shfl_xor_sync(0xffffffffu, ps0, 1);
        ps0 += __shfl_xor_sync(0xffffffffu, ps0, 2);
        ps1 += __shfl_xor_sync(0xffffffffu, ps1, 1);
        ps1 += __shfl_xor_sync(0xffffffffu, ps1, 2);
        l0 = l0 * alpha0 + ps0;
        l1 = l1 * alpha1 + ps1;
        #pragma unroll
        for (int j = 0; j < 8; j++) {
            oacc[j][0] *= alpha0; oacc[j][1] *= alpha0;
            oacc[j][2] *= alpha1; oacc[j][3] *= alpha1;
        }

        __syncwarp();
        #pragma unroll
        for (int j = 0; j < 8; j++) {
            *(__half2*)&Ps[m0 + g    ][j * 8 + 2 * tig] =
                __floats2half2_rn(sacc[j][0], sacc[j][1]);
            *(__half2*)&Ps[m0 + g + 8][j * 8 + 2 * tig] =
                __floats2half2_rn(sacc[j][2], sacc[j][3]);
        }
        __syncwarp();

        #pragma unroll
        for (int kp = 0; kp < 4; kp++) {
            uint32_t a0 = U32(&Ps[m0 + g    ][kp * 16 + 2 * tig]);
            uint32_t a1 = U32(&Ps[m0 + g + 8][kp * 16 + 2 * tig]);
            uint32_t a2 = U32(&Ps[m0 + g    ][kp * 16 + 8 + 2 * tig]);
            uint32_t a3 = U32(&Ps[m0 + g + 8][kp * 16 + 8 + 2 * tig]);
            unsigned vrow = (unsigned)__cvta_generic_to_shared(
                &Vs[kp * 16 + (lane & 15)][0]);
            #pragma unroll
            for (int j = 0; j < 8; j++) {
                uint32_t b0, b1;
                asm volatile(
                    "ldmatrix.sync.aligned.m8n8.x2.trans.shared.b16 {%0,%1}, [%2];"
                    : "=r"(b0), "=r"(b1) : "r"(vrow + j * 16));
                mma_h(oacc[j], a0, a1, a2, a3, b0, b1);
            }
        }
    }

    float inv0 = 1.f / l0, inv1 = 1.f / l1;
    #pragma unroll
    for (int j = 0; j < 8; j++) {
        int col = j * 8 + 2 * tig;
        *(__half2*)(O + base + (size_t)r0g * HID + col) =
            __floats2half2_rn(oacc[j][0] * inv0, oacc[j][1] * inv0);
        *(__half2*)(O + base + (size_t)r1g * HID + col) =
            __floats2half2_rn(oacc[j][2] * inv1, oacc[j][3] * inv1);
    }
}

// ---------------- launch ----------------
extern "C" void kernel_launch(void* const* d_in, const int* in_sizes, int n_in,
                              void* d_out, int out_size)
{
    const float* x     = (const float*)d_in[0];
    const float* Wq    = (const float*)d_in[1];
    const float* bq    = (const float*)d_in[2];
    const float* Wv    = (const float*)d_in[3];
    const float* bv    = (const float*)d_in[4];
    const float* Wo    = (const float*)d_in[5];
    const float* bo    = (const float*)d_in[6];
    const float* W1    = (const float*)d_in[7];
    const float* b1    = (const float*)d_in[8];
    const float* W2    = (const float*)d_in[9];
    const float* b2    = (const float*)d_in[10];
    const float* g1    = (const float*)d_in[11];
    const float* beta1 = (const float*)d_in[12];
    const float* g2    = (const float*)d_in[13];
    const float* beta2 = (const float*)d_in[14];
    float* out = (float*)d_out;

    float *x1;
    __half *q16, *v16, *ln16, *ctx16, *h116, *wq16, *wv16, *wo16, *w116, *w216;
    cudaGetSymbolAddress((void**)&x1,    g_x1);
    cudaGetSymbolAddress((void**)&q16,   g_q16);
    cudaGetSymbolAddress((void**)&v16,   g_v16);
    cudaGetSymbolAddress((void**)&ln16,  g_ln16);
    cudaGetSymbolAddress((void**)&ctx16, g_ctx16);
    cudaGetSymbolAddress((void**)&h116,  g_h116);
    cudaGetSymbolAddress((void**)&wq16,  g_wq16);
    cudaGetSymbolAddress((void**)&wv16,  g_wv16);
    cudaGetSymbolAddress((void**)&wo16,  g_wo16);
    cudaGetSymbolAddress((void**)&w116,  g_w116);
    cudaGetSymbolAddress((void**)&w216,  g_w216);

    cudaFuncSetAttribute(hgemm<0, __half>,
        cudaFuncAttributeMaxDynamicSharedMemorySize, HG_SMEM);
    cudaFuncSetAttribute(hgemm<1, float>,
        cudaFuncAttributeMaxDynamicSharedMemorySize, HG_SMEM);
    cudaFuncSetAttribute(hgemm<2, __half>,
        cudaFuncAttributeMaxDynamicSharedMemorySize, HG_SMEM);

    // weights: fp32 -> fp16, layout preserved
    int nh = HID * HID, nf = HID * FFDIM;
    cvt16<<<nh / 1024, 256>>>(Wq, wq16, nh);
    cvt16<<<nh / 1024, 256>>>(Wv, wv16, nh);
    cvt16<<<nh / 1024, 256>>>(Wo, wo16, nh);
    cvt16<<<nf / 1024, 256>>>(W1, w116, nf);
    cvt16<<<nf / 1024, 256>>>(W2, w216, nf);

    dim3 blk(256);
    dim3 gHID(HID / 128, TOKENS / 128);     // (8, 32)
    dim3 gFF (FFDIM / 128, TOKENS / 128);   // (32, 32)

    // ln16 = LN(x)
    ln_kernel<<<TOKENS, blk>>>(x, g1, beta1, ln16);
    // q = ln16 @ Wq + bq ; v = ln16 @ Wv + bv   (fp16 outs)
    hgemm<0, __half><<<gHID, blk, HG_SMEM>>>(TOKENS, HID, HID, ln16, wq16, bq, nullptr, q16);
    hgemm<0, __half><<<gHID, blk, HG_SMEM>>>(TOKENS, HID, HID, ln16, wv16, bv, nullptr, v16);
    // causal attention (Q == K)
    attn_h<<<dim3(SEQ / 128, 2 * NHEADS), blk>>>(q16, v16, ctx16);
    // x1 = x + ctx @ Wo + bo
    hgemm<1, float><<<gHID, blk, HG_SMEM>>>(TOKENS, HID, HID, ctx16, wo16, bo, x, x1);
    // ln16 = LN(x1)
    ln_kernel<<<TOKENS, blk>>>(x1, g2, beta2, ln16);
    // h1 = gelu(ln16 @ W1 + b1), fp16 out
    hgemm<2, __half><<<gFF, blk, HG_SMEM>>>(TOKENS, FFDIM, HID, ln16, w116, b1, nullptr, h116);
    // out = x1 + h1 @ W2 + b2
    hgemm<1, float><<<gHID, blk, HG_SMEM>>>(TOKENS, HID, FFDIM, h116, w216, b2, x1, out);
}

// round 10
// speedup vs baseline: 10.1067x; 1.0651x over previous
#include <cuda_runtime.h>
#include <cuda_fp16.h>
#include <math.h>
#include <stdint.h>

#define TOKENS 4096      // 2 * 2048
#define HID    1024
#define FFDIM  4096
#define SEQ    2048
#define NHEADS 16
#define DK     64
#define QVN    2048      // fused Q|V projection width

// ---------------- scratch (device globals; no allocs allowed) ----------------
__device__ float  g_x1  [TOKENS * HID];
__device__ __half g_qv16[(size_t)TOKENS * QVN];
__device__ __half g_ln16[TOKENS * HID];
__device__ __half g_ctx16[TOKENS * HID];
__device__ __half g_h116[(size_t)TOKENS * FFDIM];
// fp16 weights
__device__ __half g_wqv16[(size_t)HID * QVN];   // [k][ Wq | Wv ]
__device__ __half g_wo16[HID * HID];
__device__ __half g_w116[(size_t)HID * FFDIM];
__device__ __half g_w216[(size_t)HID * FFDIM];
__device__ float  g_bqv [QVN];

// ---------------- fp32 -> fp16 convert, 4x ILP ----------------
__global__ __launch_bounds__(256) void cvt16(
    const float* __restrict__ in, __half* __restrict__ out, int n)
{
    int i = (blockIdx.x * 256 + threadIdx.x) * 16;
    if (i < n) {
        #pragma unroll
        for (int u = 0; u < 4; u++) {
            float4 v = *(const float4*)(in + i + u * 4);
            __half2 pk2[2];
            pk2[0] = __floats2half2_rn(v.x, v.y);
            pk2[1] = __floats2half2_rn(v.z, v.w);
            *(uint2*)(out + i + u * 4) = *(const uint2*)pk2;
        }
    }
}

// ---------------- Wq|Wv concat convert: out[k][0:1024]=Wq, [1024:2048]=Wv ----
__global__ __launch_bounds__(256) void cvt_qv(
    const float* __restrict__ Wq, const float* __restrict__ Wv,
    const float* __restrict__ bq, const float* __restrict__ bv,
    __half* __restrict__ out, float* __restrict__ bqv)
{
    int i = (blockIdx.x * 256 + threadIdx.x) * 4;   // over HID*HID
    int k = i >> 10, n = i & 1023;
    float4 q = *(const float4*)(Wq + i);
    float4 v = *(const float4*)(Wv + i);
    __half2 pq[2], pv[2];
    pq[0] = __floats2half2_rn(q.x, q.y); pq[1] = __floats2half2_rn(q.z, q.w);
    pv[0] = __floats2half2_rn(v.x, v.y); pv[1] = __floats2half2_rn(v.z, v.w);
    *(uint2*)(out + (size_t)k * QVN + n)        = *(const uint2*)pq;
    *(uint2*)(out + (size_t)k * QVN + 1024 + n) = *(const uint2*)pv;
    if (i < 1024) {     // first 256 threads also copy biases (4 each)
        *(float4*)(bqv + i)        = *(const float4*)(bq + i);
        *(float4*)(bqv + 1024 + i) = *(const float4*)(bv + i);
    }
}

// ---------------- LayerNorm: one block per row, fp16 out ----------------
__global__ __launch_bounds__(256) void ln_kernel(
    const float* __restrict__ x, const float* __restrict__ gamma,
    const float* __restrict__ beta, __half* __restrict__ out)
{
    int row = blockIdx.x;
    int t = threadIdx.x;
    const float4* xr = (const float4*)(x + (size_t)row * HID);
    float4 v = xr[t];
    float s  = v.x + v.y + v.z + v.w;
    float ss = v.x*v.x + v.y*v.y + v.z*v.z + v.w*v.w;
    #pragma unroll
    for (int o = 16; o; o >>= 1) {
        s  += __shfl_xor_sync(0xffffffffu, s,  o);
        ss += __shfl_xor_sync(0xffffffffu, ss, o);
    }
    __shared__ float rs[8], rss[8];
    if ((t & 31) == 0) { rs[t >> 5] = s; rss[t >> 5] = ss; }
    __syncthreads();
    s = 0.f; ss = 0.f;
    #pragma unroll
    for (int i = 0; i < 8; i++) { s += rs[i]; ss += rss[i]; }
    float mu  = s * (1.f / HID);
    float var = ss * (1.f / HID) - mu * mu;
    float inv = rsqrtf(var + 1e-5f);
    float4 g4 = ((const float4*)gamma)[t];
    float4 b4 = ((const float4*)beta)[t];
    __half2 pk2[2];
    pk2[0] = __floats2half2_rn((v.x - mu) * inv * g4.x + b4.x,
                               (v.y - mu) * inv * g4.y + b4.y);
    pk2[1] = __floats2half2_rn((v.z - mu) * inv * g4.z + b4.z,
                               (v.w - mu) * inv * g4.w + b4.w);
    *(uint2*)(out + (size_t)row * HID + t * 4) = *(const uint2*)pk2;
}

// ---------------- GELU (tanh approx, matches reference) ----------------
__device__ __forceinline__ float gelu_f(float x)
{
    float u = 0.7978845608028654f * (x + 0.044715f * x * x * x);
    return 0.5f * x * (1.f + tanhf(u));
}

// ---------------- FP16 MMA m16n8k16, fp32 accumulate ----------------
__device__ __forceinline__ void mma_h(
    float* c, uint32_t a0, uint32_t a1, uint32_t a2, uint32_t a3,
    uint32_t b0, uint32_t b1)
{
    asm volatile(
        "mma.sync.aligned.m16n8k16.row.col.f32.f16.f16.f32 "
        "{%0,%1,%2,%3}, {%4,%5,%6,%7}, {%8,%9}, {%0,%1,%2,%3};"
        : "+f"(c[0]), "+f"(c[1]), "+f"(c[2]), "+f"(c[3])
        : "r"(a0), "r"(a1), "r"(a2), "r"(a3), "r"(b0), "r"(b1));
}

__device__ __forceinline__ void cp16(void* s, const void* g)
{
    unsigned sa = (unsigned)__cvta_generic_to_shared(s);
    asm volatile("cp.async.cg.shared.global [%0], [%1], 16;" :: "r"(sa), "l"(g));
}

__device__ __forceinline__ void ldm_x4(uint32_t* r, const __half* p)
{
    unsigned a = (unsigned)__cvta_generic_to_shared(p);
    asm volatile(
        "ldmatrix.sync.aligned.m8n8.x4.shared.b16 {%0,%1,%2,%3}, [%4];"
        : "=r"(r[0]), "=r"(r[1]), "=r"(r[2]), "=r"(r[3]) : "r"(a));
}

__device__ __forceinline__ void ldm_x4t(uint32_t* r, const __half* p)
{
    unsigned a = (unsigned)__cvta_generic_to_shared(p);
    asm volatile(
        "ldmatrix.sync.aligned.m8n8.x4.trans.shared.b16 {%0,%1,%2,%3}, [%4];"
        : "=r"(r[0]), "=r"(r[1]), "=r"(r[2]), "=r"(r[3]) : "r"(a));
}

__device__ __forceinline__ uint32_t U32(const __half* p)
{
    return *(const uint32_t*)p;
}

__device__ __forceinline__ void st2(float* p, float x, float y)
{
    *(float2*)p = make_float2(x, y);
}
__device__ __forceinline__ void st2(__half* p, float x, float y)
{
    *(__half2*)p = __floats2half2_rn(x, y);
}

// ---------------- FP16 GEMM: C = A(MxK) @ W(KxN) + bias (+res / gelu) ------
// W in native (K,N) row-major. BM=BN=128, BK=64, 3-stage cp.async pipeline.
// A smem [m][k] stride 72; B smem [k][n] stride 136. ldmatrix fragments.
// EPI: 0 = bias, 1 = bias + residual, 2 = gelu(bias + acc)
#define AS_H  (128 * 72)        // halves per A stage
#define BS_H  (64 * 136)        // halves per B stage
#define STG_H (AS_H + BS_H)     // halves per stage (17920)
#define HG_SMEM (3 * STG_H * 2) // bytes (107520)
template <int EPI, typename OT>
__global__ __launch_bounds__(256) void hgemm(
    int M, int N, int K,
    const __half* __restrict__ A, const __half* __restrict__ W,
    const float* __restrict__ bias, const float* __restrict__ R,
    OT* __restrict__ C)
{
    extern __shared__ __half hs[];

    int tid  = threadIdx.x;
    int lane = tid & 31, w = tid >> 5;
    int wm = w >> 1, wn = w & 1;
    int g = lane >> 2, tig = lane & 3;
    int bx = blockIdx.x, by = blockIdx.y;

    const __half* Ab = A + (size_t)by * 128 * K;
    const __half* Wb = W + bx * 128;

    auto stage_in = [&](int s, int t) {
        __half* As = hs + s * STG_H;
        __half* Bs = As + AS_H;
        int k0 = t << 6;
        // A: 128 rows x 8 chunks of 8 halves = 1024 chunks, 4 per thread
        #pragma unroll
        for (int i = 0; i < 4; i++) {
            int c = tid + i * 256;
            int r = c >> 3, col = (c & 7) * 8;
            cp16(As + r * 72 + col, Ab + (size_t)r * K + k0 + col);
        }
        // B: 64 rows x 16 chunks of 8 halves = 1024 chunks, 4 per thread
        #pragma unroll
        for (int i = 0; i < 4; i++) {
            int c = tid + i * 256;
            int r = c >> 4, col = (c & 15) * 8;
            cp16(Bs + r * 136 + col, Wb + (size_t)(k0 + r) * N + col);
        }
        asm volatile("cp.async.commit_group;");
    };

    float acc[2][8][4] = {};
    int NT = K >> 6;

    stage_in(0, 0);
    stage_in(1, 1);

    int s = 0;
    for (int t = 0; t < NT; t++) {
        asm volatile("cp.async.wait_group 1;");
        __syncthreads();

        if (t + 2 < NT) stage_in((s + 2) % 3, t + 2);
        else            asm volatile("cp.async.commit_group;");

        __half* As = hs + s * STG_H;
        __half* Bs = As + AS_H;

        #pragma unroll
        for (int kk = 0; kk < 4; kk++) {
            int k8 = kk * 16;               // halves base within 64-half row
            uint32_t a[2][4];
            #pragma unroll
            for (int i = 0; i < 2; i++)
                ldm_x4(a[i], As + (wm * 32 + i * 16 + (lane & 15)) * 72
                               + k8 + (lane >> 4) * 8);
            #pragma unroll
            for (int jp = 0; jp < 4; jp++) {
                uint32_t b[4];
                ldm_x4t(b, Bs + (k8 + (lane & 15)) * 136
                             + wn * 64 + jp * 16 + (lane >> 4) * 8);
                #pragma unroll
                for (int i = 0; i < 2; i++) {
                    mma_h(acc[i][2 * jp    ], a[i][0], a[i][1], a[i][2], a[i][3],
                          b[0], b[1]);
                    mma_h(acc[i][2 * jp + 1], a[i][0], a[i][1], a[i][2], a[i][3],
                          b[2], b[3]);
                }
            }
        }
        s = (s + 1) % 3;
    }

    // ---- epilogue ----
    #pragma unroll
    for (int i = 0; i < 2; i++) {
        int r0 = by * 128 + wm * 32 + i * 16 + g;
        int r1 = r0 + 8;
        #pragma unroll
        for (int j = 0; j < 8; j++) {
            int col = bx * 128 + wn * 64 + j * 8 + tig * 2;
            float2 bb = *(const float2*)(bias + col);
            float v00 = acc[i][j][0] + bb.x, v01 = acc[i][j][1] + bb.y;
            float v10 = acc[i][j][2] + bb.x, v11 = acc[i][j][3] + bb.y;
            if (EPI == 1) {
                float2 q0 = *(const float2*)(R + (size_t)r0 * N + col);
                float2 q1 = *(const float2*)(R + (size_t)r1 * N + col);
                v00 += q0.x; v01 += q0.y;
                v10 += q1.x; v11 += q1.y;
            } else if (EPI == 2) {
                v00 = gelu_f(v00); v01 = gelu_f(v01);
                v10 = gelu_f(v10); v11 = gelu_f(v11);
            }
            st2(C + (size_t)r0 * N + col, v00, v01);
            st2(C + (size_t)r1 * N + col, v10, v11);
        }
    }
}

// ---------------- FP16 tensor-core causal flash attention --------------------
// Q/K at row-stride QVN (cols 0:1024 of qv buffer), V at +1024 offset.
#define SH 72
__global__ __launch_bounds__(256, 2) void attn_h(
    const __half* __restrict__ QV, __half* __restrict__ O)
{
    __shared__ __half Ks[64][SH];
    __shared__ __half Vs[64][SH];
    __shared__ __half Ps[128][SH];

    int qt = (int)gridDim.x - 1 - (int)blockIdx.x;
    int bh = blockIdx.y;
    int b = bh >> 4, h = bh & 15;
    int tid = threadIdx.x, lane = tid & 31, w = tid >> 5;
    int g = lane >> 2, tig = lane & 3;
    int m0 = w * 16;
    const __half* Qh = QV + (size_t)b * SEQ * QVN + h * DK;
    const __half* Vh = Qh + 1024;
    size_t obase = (size_t)b * SEQ * HID + (size_t)h * DK;

    #pragma unroll
    for (int i = 0; i < 4; i++) {
        int idx = tid + i * 256;
        int row = idx >> 3, c8 = idx & 7;
        *(uint4*)&Ps[row][c8 * 8] =
            *(const uint4*)(Qh + (size_t)(qt * 128 + row) * QVN + c8 * 8);
    }
    __syncthreads();
    uint32_t qf[4][4];
    #pragma unroll
    for (int kg = 0; kg < 4; kg++) {
        qf[kg][0] = U32(&Ps[m0 + g    ][kg * 16 + 2 * tig]);
        qf[kg][1] = U32(&Ps[m0 + g + 8][kg * 16 + 2 * tig]);
        qf[kg][2] = U32(&Ps[m0 + g    ][kg * 16 + 8 + 2 * tig]);
        qf[kg][3] = U32(&Ps[m0 + g + 8][kg * 16 + 8 + 2 * tig]);
    }
    __syncwarp();

    float oacc[8][4] = {};
    float mr0 = -INFINITY, mr1 = -INFINITY, l0 = 0.f, l1 = 0.f;
    int r0g = qt * 128 + m0 + g;
    int r1g = r0g + 8;
    int ktmax = 2 * qt + 1;

    for (int kt = 0; kt <= ktmax; kt++) {
        __syncthreads();
        #pragma unroll
        for (int i = 0; i < 2; i++) {
            int idx = tid + i * 256;
            int row = idx >> 3, c8 = idx & 7;
            *(uint4*)&Ks[row][c8 * 8] =
                *(const uint4*)(Qh + (size_t)(kt * 64 + row) * QVN + c8 * 8);
            *(uint4*)&Vs[row][c8 * 8] =
                *(const uint4*)(Vh + (size_t)(kt * 64 + row) * QVN + c8 * 8);
        }
        __syncthreads();

        float sacc[8][4] = {};
        #pragma unroll
        for (int kg = 0; kg < 4; kg++) {
            #pragma unroll
            for (int j = 0; j < 8; j++) {
                uint32_t b0 = U32(&Ks[j * 8 + g][kg * 16 + 2 * tig]);
                uint32_t b1 = U32(&Ks[j * 8 + g][kg * 16 + 8 + 2 * tig]);
                mma_h(sacc[j], qf[kg][0], qf[kg][1], qf[kg][2], qf[kg][3], b0, b1);
            }
        }

        const float scale = 0.125f;
        if (kt >= 2 * qt) {
            #pragma unroll
            for (int j = 0; j < 8; j++) {
                int c0 = kt * 64 + j * 8 + 2 * tig;
                sacc[j][0] = (c0     > r0g) ? -INFINITY : sacc[j][0] * scale;
                sacc[j][1] = (c0 + 1 > r0g) ? -INFINITY : sacc[j][1] * scale;
                sacc[j][2] = (c0     > r1g) ? -INFINITY : sacc[j][2] * scale;
                sacc[j][3] = (c0 + 1 > r1g) ? -INFINITY : sacc[j][3] * scale;
            }
        } else {
            #pragma unroll
            for (int j = 0; j < 8; j++)
                #pragma unroll
                for (int c = 0; c < 4; c++) sacc[j][c] *= scale;
        }

        float mt0 = mr0, mt1 = mr1;
        #pragma unroll
        for (int j = 0; j < 8; j++) {
            mt0 = fmaxf(mt0, fmaxf(sacc[j][0], sacc[j][1]));
            mt1 = fmaxf(mt1, fmaxf(sacc[j][2], sacc[j][3]));
        }
        mt0 = fmaxf(mt0, __shfl_xor_sync(0xffffffffu, mt0, 1));
        mt0 = fmaxf(mt0, __shfl_xor_sync(0xffffffffu, mt0, 2));
        mt1 = fmaxf(mt1, __shfl_xor_sync(0xffffffffu, mt1, 1));
        mt1 = fmaxf(mt1, __shfl_xor_sync(0xffffffffu, mt1, 2));
        float alpha0 = __expf(mr0 - mt0);
        float alpha1 = __expf(mr1 - mt1);
        mr0 = mt0; mr1 = mt1;
        float ps0 = 0.f, ps1 = 0.f;
        #pragma unroll
        for (int j = 0; j < 8; j++) {
            sacc[j][0] = __expf(sacc[j][0] - mt0); ps0 += sacc[j][0];
            sacc[j][1] = __expf(sacc[j][1] - mt0); ps0 += sacc[j][1];
            sacc[j][2] = __expf(sacc[j][2] - mt1); ps1 += sacc[j][2];
            sacc[j][3] = __expf(sacc[j][3] - mt1); ps1 += sacc[j][3];
        }
        ps0 += __shfl_xor_sync(0xffffffffu, ps0, 1);
        ps0 += __shfl_xor_sync(0xffffffffu, ps0, 2);
        ps1 += __shfl_xor_sync(0xffffffffu, ps1, 1);
        ps1 += __shfl_xor_sync(0xffffffffu, ps1, 2);
        l0 = l0 * alpha0 + ps0;
        l1 = l1 * alpha1 + ps1;
        #pragma unroll
        for (int j = 0; j < 8; j++) {
            oacc[j][0] *= alpha0; oacc[j][1] *= alpha0;
            oacc[j][2] *= alpha1; oacc[j][3] *= alpha1;
        }

        __syncwarp();
        #pragma unroll
        for (int j = 0; j < 8; j++) {
            *(__half2*)&Ps[m0 + g    ][j * 8 + 2 * tig] =
                __floats2half2_rn(sacc[j][0], sacc[j][1]);
            *(__half2*)&Ps[m0 + g + 8][j * 8 + 2 * tig] =
                __floats2half2_rn(sacc[j][2], sacc[j][3]);
        }
        __syncwarp();

        #pragma unroll
        for (int kp = 0; kp < 4; kp++) {
            uint32_t a0 = U32(&Ps[m0 + g    ][kp * 16 + 2 * tig]);
            uint32_t a1 = U32(&Ps[m0 + g + 8][kp * 16 + 2 * tig]);
            uint32_t a2 = U32(&Ps[m0 + g    ][kp * 16 + 8 + 2 * tig]);
            uint32_t a3 = U32(&Ps[m0 + g + 8][kp * 16 + 8 + 2 * tig]);
            unsigned vrow = (unsigned)__cvta_generic_to_shared(
                &Vs[kp * 16 + (lane & 15)][0]);
            #pragma unroll
            for (int j = 0; j < 8; j++) {
                uint32_t b0, b1;
                asm volatile(
                    "ldmatrix.sync.aligned.m8n8.x2.trans.shared.b16 {%0,%1}, [%2];"
                    : "=r"(b0), "=r"(b1) : "r"(vrow + j * 16));
                mma_h(oacc[j], a0, a1, a2, a3, b0, b1);
            }
        }
    }

    float inv0 = 1.f / l0, inv1 = 1.f / l1;
    #pragma unroll
    for (int j = 0; j < 8; j++) {
        int col = j * 8 + 2 * tig;
        *(__half2*)(O + obase + (size_t)r0g * HID + col) =
            __floats2half2_rn(oacc[j][0] * inv0, oacc[j][1] * inv0);
        *(__half2*)(O + obase + (size_t)r1g * HID + col) =
            __floats2half2_rn(oacc[j][2] * inv1, oacc[j][3] * inv1);
    }
}

// ---------------- launch ----------------
extern "C" void kernel_launch(void* const* d_in, const int* in_sizes, int n_in,
                              void* d_out, int out_size)
{
    const float* x     = (const float*)d_in[0];
    const float* Wq    = (const float*)d_in[1];
    const float* bq    = (const float*)d_in[2];
    const float* Wv    = (const float*)d_in[3];
    const float* bv    = (const float*)d_in[4];
    const float* Wo    = (const float*)d_in[5];
    const float* bo    = (const float*)d_in[6];
    const float* W1    = (const float*)d_in[7];
    const float* b1    = (const float*)d_in[8];
    const float* W2    = (const float*)d_in[9];
    const float* b2    = (const float*)d_in[10];
    const float* g1    = (const float*)d_in[11];
    const float* beta1 = (const float*)d_in[12];
    const float* g2    = (const float*)d_in[13];
    const float* beta2 = (const float*)d_in[14];
    float* out = (float*)d_out;

    float *x1, *bqv;
    __half *qv16, *ln16, *ctx16, *h116, *wqv16, *wo16, *w116, *w216;
    cudaGetSymbolAddress((void**)&x1,    g_x1);
    cudaGetSymbolAddress((void**)&bqv,   g_bqv);
    cudaGetSymbolAddress((void**)&qv16,  g_qv16);
    cudaGetSymbolAddress((void**)&ln16,  g_ln16);
    cudaGetSymbolAddress((void**)&ctx16, g_ctx16);
    cudaGetSymbolAddress((void**)&h116,  g_h116);
    cudaGetSymbolAddress((void**)&wqv16, g_wqv16);
    cudaGetSymbolAddress((void**)&wo16,  g_wo16);
    cudaGetSymbolAddress((void**)&w116,  g_w116);
    cudaGetSymbolAddress((void**)&w216,  g_w216);

    cudaFuncSetAttribute(hgemm<0, __half>,
        cudaFuncAttributeMaxDynamicSharedMemorySize, HG_SMEM);
    cudaFuncSetAttribute(hgemm<1, float>,
        cudaFuncAttributeMaxDynamicSharedMemorySize, HG_SMEM);
    cudaFuncSetAttribute(hgemm<2, __half>,
        cudaFuncAttributeMaxDynamicSharedMemorySize, HG_SMEM);

    // weights: fp32 -> fp16 (Wq|Wv concatenated)
    int nh = HID * HID, nf = HID * FFDIM;
    cvt_qv<<<nh / 1024, 256>>>(Wq, Wv, bq, bv, wqv16, bqv);
    cvt16<<<nh / 4096, 256>>>(Wo, wo16, nh);
    cvt16<<<nf / 4096, 256>>>(W1, w116, nf);
    cvt16<<<nf / 4096, 256>>>(W2, w216, nf);

    dim3 blk(256);
    dim3 gHID(HID / 128, TOKENS / 128);     // (8, 32)
    dim3 gQV (QVN / 128, TOKENS / 128);     // (16, 32)
    dim3 gFF (FFDIM / 128, TOKENS / 128);   // (32, 32)

    // ln16 = LN(x)
    ln_kernel<<<TOKENS, blk>>>(x, g1, beta1, ln16);
    // qv = ln16 @ [Wq|Wv] + [bq|bv]
    hgemm<0, __half><<<gQV, blk, HG_SMEM>>>(TOKENS, QVN, HID, ln16, wqv16, bqv, nullptr, qv16);
    // causal attention (Q == K)
    attn_h<<<dim3(SEQ / 128, 2 * NHEADS), blk>>>(qv16, ctx16);
    // x1 = x + ctx @ Wo + bo
    hgemm<1, float><<<gHID, blk, HG_SMEM>>>(TOKENS, HID, HID, ctx16, wo16, bo, x, x1);
    // ln16 = LN(x1)
    ln_kernel<<<TOKENS, blk>>>(x1, g2, beta2, ln16);
    // h1 = gelu(ln16 @ W1 + b1), fp16 out
    hgemm<2, __half><<<gFF, blk, HG_SMEM>>>(TOKENS, FFDIM, HID, ln16, w116, b1, nullptr, h116);
    // out = x1 + h1 @ W2 + b2
    hgemm<1, float><<<gHID, blk, HG_SMEM>>>(TOKENS, HID, FFDIM, h116, w216, b2, x1, out);
}

// round 11
// speedup vs baseline: 10.2376x; 1.0129x over previous
#include <cuda_runtime.h>
#include <cuda_fp16.h>
#include <math.h>
#include <stdint.h>

#define TOKENS 4096      // 2 * 2048
#define HID    1024
#define FFDIM  4096
#define SEQ    2048
#define NHEADS 16
#define DK     64
#define QVN    2048      // fused Q|V projection width

// ---------------- scratch (device globals; no allocs allowed) ----------------
__device__ float  g_x1  [TOKENS * HID];
__device__ __half g_qv16[(size_t)TOKENS * QVN];
__device__ __half g_ln16[TOKENS * HID];
__device__ __half g_ctx16[TOKENS * HID];
__device__ __half g_h116[(size_t)TOKENS * FFDIM];
// fp16 weights
__device__ __half g_wqv16[(size_t)HID * QVN];   // [k][ Wq | Wv ]
__device__ __half g_wo16[HID * HID];
__device__ __half g_w116[(size_t)HID * FFDIM];
__device__ __half g_w216[(size_t)HID * FFDIM];
__device__ float  g_bqv [QVN];

// ---------------- fp32 -> fp16 convert (4 elems/thread — measured fastest) --
__global__ __launch_bounds__(256) void cvt16(
    const float* __restrict__ in, __half* __restrict__ out, int n)
{
    int i = (blockIdx.x * 256 + threadIdx.x) * 4;
    if (i < n) {
        float4 v = *(const float4*)(in + i);
        __half2 pk2[2];
        pk2[0] = __floats2half2_rn(v.x, v.y);
        pk2[1] = __floats2half2_rn(v.z, v.w);
        *(uint2*)(out + i) = *(const uint2*)pk2;
    }
}

// ---------------- Wq|Wv concat convert: out[k][0:1024]=Wq, [1024:2048]=Wv ----
__global__ __launch_bounds__(256) void cvt_qv(
    const float* __restrict__ Wq, const float* __restrict__ Wv,
    const float* __restrict__ bq, const float* __restrict__ bv,
    __half* __restrict__ out, float* __restrict__ bqv)
{
    int i = (blockIdx.x * 256 + threadIdx.x) * 4;   // over HID*HID
    int k = i >> 10, n = i & 1023;
    float4 q = *(const float4*)(Wq + i);
    float4 v = *(const float4*)(Wv + i);
    __half2 pq[2], pv[2];
    pq[0] = __floats2half2_rn(q.x, q.y); pq[1] = __floats2half2_rn(q.z, q.w);
    pv[0] = __floats2half2_rn(v.x, v.y); pv[1] = __floats2half2_rn(v.z, v.w);
    *(uint2*)(out + (size_t)k * QVN + n)        = *(const uint2*)pq;
    *(uint2*)(out + (size_t)k * QVN + 1024 + n) = *(const uint2*)pv;
    if (i < 1024) {     // first 256 threads also copy biases (4 each)
        *(float4*)(bqv + i)        = *(const float4*)(bq + i);
        *(float4*)(bqv + 1024 + i) = *(const float4*)(bv + i);
    }
}

// ---------------- LayerNorm: one block per row, fp16 out ----------------
__global__ __launch_bounds__(256) void ln_kernel(
    const float* __restrict__ x, const float* __restrict__ gamma,
    const float* __restrict__ beta, __half* __restrict__ out)
{
    int row = blockIdx.x;
    int t = threadIdx.x;
    const float4* xr = (const float4*)(x + (size_t)row * HID);
    float4 v = xr[t];
    float s  = v.x + v.y + v.z + v.w;
    float ss = v.x*v.x + v.y*v.y + v.z*v.z + v.w*v.w;
    #pragma unroll
    for (int o = 16; o; o >>= 1) {
        s  += __shfl_xor_sync(0xffffffffu, s,  o);
        ss += __shfl_xor_sync(0xffffffffu, ss, o);
    }
    __shared__ float rs[8], rss[8];
    if ((t & 31) == 0) { rs[t >> 5] = s; rss[t >> 5] = ss; }
    __syncthreads();
    s = 0.f; ss = 0.f;
    #pragma unroll
    for (int i = 0; i < 8; i++) { s += rs[i]; ss += rss[i]; }
    float mu  = s * (1.f / HID);
    float var = ss * (1.f / HID) - mu * mu;
    float inv = rsqrtf(var + 1e-5f);
    float4 g4 = ((const float4*)gamma)[t];
    float4 b4 = ((const float4*)beta)[t];
    __half2 pk2[2];
    pk2[0] = __floats2half2_rn((v.x - mu) * inv * g4.x + b4.x,
                               (v.y - mu) * inv * g4.y + b4.y);
    pk2[1] = __floats2half2_rn((v.z - mu) * inv * g4.z + b4.z,
                               (v.w - mu) * inv * g4.w + b4.w);
    *(uint2*)(out + (size_t)row * HID + t * 4) = *(const uint2*)pk2;
}

// ---------------- GELU (tanh approx, matches reference) ----------------
__device__ __forceinline__ float gelu_f(float x)
{
    float u = 0.7978845608028654f * (x + 0.044715f * x * x * x);
    return 0.5f * x * (1.f + tanhf(u));
}

// ---------------- FP16 MMA m16n8k16, fp32 accumulate ----------------
__device__ __forceinline__ void mma_h(
    float* c, uint32_t a0, uint32_t a1, uint32_t a2, uint32_t a3,
    uint32_t b0, uint32_t b1)
{
    asm volatile(
        "mma.sync.aligned.m16n8k16.row.col.f32.f16.f16.f32 "
        "{%0,%1,%2,%3}, {%4,%5,%6,%7}, {%8,%9}, {%0,%1,%2,%3};"
        : "+f"(c[0]), "+f"(c[1]), "+f"(c[2]), "+f"(c[3])
        : "r"(a0), "r"(a1), "r"(a2), "r"(a3), "r"(b0), "r"(b1));
}

__device__ __forceinline__ void cp16(void* s, const void* g)
{
    unsigned sa = (unsigned)__cvta_generic_to_shared(s);
    asm volatile("cp.async.cg.shared.global [%0], [%1], 16;" :: "r"(sa), "l"(g));
}

__device__ __forceinline__ void ldm_x4(uint32_t* r, const __half* p)
{
    unsigned a = (unsigned)__cvta_generic_to_shared(p);
    asm volatile(
        "ldmatrix.sync.aligned.m8n8.x4.shared.b16 {%0,%1,%2,%3}, [%4];"
        : "=r"(r[0]), "=r"(r[1]), "=r"(r[2]), "=r"(r[3]) : "r"(a));
}

__device__ __forceinline__ void ldm_x4t(uint32_t* r, const __half* p)
{
    unsigned a = (unsigned)__cvta_generic_to_shared(p);
    asm volatile(
        "ldmatrix.sync.aligned.m8n8.x4.trans.shared.b16 {%0,%1,%2,%3}, [%4];"
        : "=r"(r[0]), "=r"(r[1]), "=r"(r[2]), "=r"(r[3]) : "r"(a));
}

__device__ __forceinline__ uint32_t U32(const __half* p)
{
    return *(const uint32_t*)p;
}

__device__ __forceinline__ void st2(float* p, float x, float y)
{
    *(float2*)p = make_float2(x, y);
}
__device__ __forceinline__ void st2(__half* p, float x, float y)
{
    *(__half2*)p = __floats2half2_rn(x, y);
}

// ---------------- FP16 GEMM: C = A(MxK) @ W(KxN) + bias (+res / gelu) ------
// W in native (K,N) row-major. BM=BN=128, BK=64, 3-stage cp.async pipeline.
// A smem [m][k] stride 72; B smem [k][n] stride 136. ldmatrix fragments.
// EPI: 0 = bias, 1 = bias + residual, 2 = gelu(bias + acc)
#define AS_H  (128 * 72)        // halves per A stage
#define BS_H  (64 * 136)        // halves per B stage
#define STG_H (AS_H + BS_H)     // halves per stage (17920)
#define HG_SMEM (3 * STG_H * 2) // bytes (107520)
template <int EPI, typename OT>
__global__ __launch_bounds__(256) void hgemm(
    int M, int N, int K,
    const __half* __restrict__ A, const __half* __restrict__ W,
    const float* __restrict__ bias, const float* __restrict__ R,
    OT* __restrict__ C)
{
    extern __shared__ __half hs[];

    int tid  = threadIdx.x;
    int lane = tid & 31, w = tid >> 5;
    int wm = w >> 1, wn = w & 1;
    int g = lane >> 2, tig = lane & 3;
    int bx = blockIdx.x, by = blockIdx.y;

    const __half* Ab = A + (size_t)by * 128 * K;
    const __half* Wb = W + bx * 128;

    auto stage_in = [&](int s, int t) {
        __half* As = hs + s * STG_H;
        __half* Bs = As + AS_H;
        int k0 = t << 6;
        #pragma unroll
        for (int i = 0; i < 4; i++) {
            int c = tid + i * 256;
            int r = c >> 3, col = (c & 7) * 8;
            cp16(As + r * 72 + col, Ab + (size_t)r * K + k0 + col);
        }
        #pragma unroll
        for (int i = 0; i < 4; i++) {
            int c = tid + i * 256;
            int r = c >> 4, col = (c & 15) * 8;
            cp16(Bs + r * 136 + col, Wb + (size_t)(k0 + r) * N + col);
        }
        asm volatile("cp.async.commit_group;");
    };

    float acc[2][8][4] = {};
    int NT = K >> 6;

    stage_in(0, 0);
    stage_in(1, 1);

    int s = 0;
    for (int t = 0; t < NT; t++) {
        asm volatile("cp.async.wait_group 1;");
        __syncthreads();

        if (t + 2 < NT) stage_in((s + 2) % 3, t + 2);
        else            asm volatile("cp.async.commit_group;");

        __half* As = hs + s * STG_H;
        __half* Bs = As + AS_H;

        #pragma unroll
        for (int kk = 0; kk < 4; kk++) {
            int k8 = kk * 16;
            uint32_t a[2][4];
            #pragma unroll
            for (int i = 0; i < 2; i++)
                ldm_x4(a[i], As + (wm * 32 + i * 16 + (lane & 15)) * 72
                               + k8 + (lane >> 4) * 8);
            #pragma unroll
            for (int jp = 0; jp < 4; jp++) {
                uint32_t b[4];
                ldm_x4t(b, Bs + (k8 + (lane & 15)) * 136
                             + wn * 64 + jp * 16 + (lane >> 4) * 8);
                #pragma unroll
                for (int i = 0; i < 2; i++) {
                    mma_h(acc[i][2 * jp    ], a[i][0], a[i][1], a[i][2], a[i][3],
                          b[0], b[1]);
                    mma_h(acc[i][2 * jp + 1], a[i][0], a[i][1], a[i][2], a[i][3],
                          b[2], b[3]);
                }
            }
        }
        s = (s + 1) % 3;
    }

    // ---- epilogue ----
    #pragma unroll
    for (int i = 0; i < 2; i++) {
        int r0 = by * 128 + wm * 32 + i * 16 + g;
        int r1 = r0 + 8;
        #pragma unroll
        for (int j = 0; j < 8; j++) {
            int col = bx * 128 + wn * 64 + j * 8 + tig * 2;
            float2 bb = *(const float2*)(bias + col);
            float v00 = acc[i][j][0] + bb.x, v01 = acc[i][j][1] + bb.y;
            float v10 = acc[i][j][2] + bb.x, v11 = acc[i][j][3] + bb.y;
            if (EPI == 1) {
                float2 q0 = *(const float2*)(R + (size_t)r0 * N + col);
                float2 q1 = *(const float2*)(R + (size_t)r1 * N + col);
                v00 += q0.x; v01 += q0.y;
                v10 += q1.x; v11 += q1.y;
            } else if (EPI == 2) {
                v00 = gelu_f(v00); v01 = gelu_f(v01);
                v10 = gelu_f(v10); v11 = gelu_f(v11);
            }
            st2(C + (size_t)r0 * N + col, v00, v01);
            st2(C + (size_t)r1 * N + col, v10, v11);
        }
    }
}

// ---------------- FP16 causal flash attention, cp.async K/V pipeline --------
// Q/K at row-stride QVN (cols 0:1024 of qv buffer), V at +1024 offset.
// Double-buffered K/V tiles (64 rows), prefetched one k-tile ahead.
#define SH 72
#define AT_KV   (64 * SH)                      // halves per K or V buffer
#define AT_SMEM ((4 * AT_KV + 128 * SH) * 2)   // bytes (55296)
__global__ __launch_bounds__(256, 2) void attn_h(
    const __half* __restrict__ QV, __half* __restrict__ O)
{
    extern __shared__ __half sm[];
    __half* KsB = sm;                   // [2][64][SH]
    __half* VsB = sm + 2 * AT_KV;       // [2][64][SH]
    __half* Ps  = sm + 4 * AT_KV;       // [128][SH]  Q staging, then P

    int qt = (int)gridDim.x - 1 - (int)blockIdx.x;   // longest first
    int bh = blockIdx.y;
    int b = bh >> 4, h = bh & 15;
    int tid = threadIdx.x, lane = tid & 31, w = tid >> 5;
    int g = lane >> 2, tig = lane & 3;
    int m0 = w * 16;
    const __half* Qh = QV + (size_t)b * SEQ * QVN + h * DK;
    const __half* Vh = Qh + 1024;
    size_t obase = (size_t)b * SEQ * HID + (size_t)h * DK;

    auto stage_kv = [&](int s, int kt) {
        #pragma unroll
        for (int i = 0; i < 2; i++) {
            int idx = tid + i * 256;            // 64 rows x 8 chunks
            int row = idx >> 3, c8 = (idx & 7) * 8;
            cp16(KsB + s * AT_KV + row * SH + c8,
                 Qh + (size_t)(kt * 64 + row) * QVN + c8);
            cp16(VsB + s * AT_KV + row * SH + c8,
                 Vh + (size_t)(kt * 64 + row) * QVN + c8);
        }
        asm volatile("cp.async.commit_group;");
    };

    // ---- stage Q tile, prefetch k-tile 0, lift Q fragments ----
    #pragma unroll
    for (int i = 0; i < 4; i++) {
        int idx = tid + i * 256;
        int row = idx >> 3, c8 = (idx & 7) * 8;
        *(uint4*)&Ps[row * SH + c8] =
            *(const uint4*)(Qh + (size_t)(qt * 128 + row) * QVN + c8);
    }
    stage_kv(0, 0);
    __syncthreads();
    uint32_t qf[4][4];
    #pragma unroll
    for (int kg = 0; kg < 4; kg++) {
        qf[kg][0] = U32(&Ps[(m0 + g    ) * SH + kg * 16 + 2 * tig]);
        qf[kg][1] = U32(&Ps[(m0 + g + 8) * SH + kg * 16 + 2 * tig]);
        qf[kg][2] = U32(&Ps[(m0 + g    ) * SH + kg * 16 + 8 + 2 * tig]);
        qf[kg][3] = U32(&Ps[(m0 + g + 8) * SH + kg * 16 + 8 + 2 * tig]);
    }
    __syncwarp();

    float oacc[8][4] = {};
    float mr0 = -INFINITY, mr1 = -INFINITY, l0 = 0.f, l1 = 0.f;
    int r0g = qt * 128 + m0 + g;
    int r1g = r0g + 8;
    int ktmax = 2 * qt + 1;

    for (int kt = 0; kt <= ktmax; kt++) {
        __syncthreads();    // all readers of buffer (kt+1)&1 (iter kt-1) done
        if (kt + 1 <= ktmax) stage_kv((kt + 1) & 1, kt + 1);
        else asm volatile("cp.async.commit_group;");
        asm volatile("cp.async.wait_group 1;");     // tile kt ready
        __syncthreads();

        const __half* Ks = KsB + (kt & 1) * AT_KV;
        const __half* Vs = VsB + (kt & 1) * AT_KV;

        // ---- S = Q K^T ----
        float sacc[8][4] = {};
        #pragma unroll
        for (int kg = 0; kg < 4; kg++) {
            #pragma unroll
            for (int j = 0; j < 8; j++) {
                uint32_t b0 = U32(&Ks[(j * 8 + g) * SH + kg * 16 + 2 * tig]);
                uint32_t b1 = U32(&Ks[(j * 8 + g) * SH + kg * 16 + 8 + 2 * tig]);
                mma_h(sacc[j], qf[kg][0], qf[kg][1], qf[kg][2], qf[kg][3], b0, b1);
            }
        }

        // ---- scale + causal mask ----
        const float scale = 0.125f;
        if (kt >= 2 * qt) {
            #pragma unroll
            for (int j = 0; j < 8; j++) {
                int c0 = kt * 64 + j * 8 + 2 * tig;
                sacc[j][0] = (c0     > r0g) ? -INFINITY : sacc[j][0] * scale;
                sacc[j][1] = (c0 + 1 > r0g) ? -INFINITY : sacc[j][1] * scale;
                sacc[j][2] = (c0     > r1g) ? -INFINITY : sacc[j][2] * scale;
                sacc[j][3] = (c0 + 1 > r1g) ? -INFINITY : sacc[j][3] * scale;
            }
        } else {
            #pragma unroll
            for (int j = 0; j < 8; j++)
                #pragma unroll
                for (int c = 0; c < 4; c++) sacc[j][c] *= scale;
        }

        // ---- online softmax (fp32) ----
        float mt0 = mr0, mt1 = mr1;
        #pragma unroll
        for (int j = 0; j < 8; j++) {
            mt0 = fmaxf(mt0, fmaxf(sacc[j][0], sacc[j][1]));
            mt1 = fmaxf(mt1, fmaxf(sacc[j][2], sacc[j][3]));
        }
        mt0 = fmaxf(mt0, __shfl_xor_sync(0xffffffffu, mt0, 1));
        mt0 = fmaxf(mt0, __shfl_xor_sync(0xffffffffu, mt0, 2));
        mt1 = fmaxf(mt1, __shfl_xor_sync(0xffffffffu, mt1, 1));
        mt1 = fmaxf(mt1, __shfl_xor_sync(0xffffffffu, mt1, 2));
        float alpha0 = __expf(mr0 - mt0);
        float alpha1 = __expf(mr1 - mt1);
        mr0 = mt0; mr1 = mt1;
        float ps0 = 0.f, ps1 = 0.f;
        #pragma unroll
        for (int j = 0; j < 8; j++) {
            sacc[j][0] = __expf(sacc[j][0] - mt0); ps0 += sacc[j][0];
            sacc[j][1] = __expf(sacc[j][1] - mt0); ps0 += sacc[j][1];
            sacc[j][2] = __expf(sacc[j][2] - mt1); ps1 += sacc[j][2];
            sacc[j][3] = __expf(sacc[j][3] - mt1); ps1 += sacc[j][3];
        }
        ps0 += __shfl_xor_sync(0xffffffffu, ps0, 1);
        ps0 += __shfl_xor_sync(0xffffffffu, ps0, 2);
        ps1 += __shfl_xor_sync(0xffffffffu, ps1, 1);
        ps1 += __shfl_xor_sync(0xffffffffu, ps1, 2);
        l0 = l0 * alpha0 + ps0;
        l1 = l1 * alpha1 + ps1;
        #pragma unroll
        for (int j = 0; j < 8; j++) {
            oacc[j][0] *= alpha0; oacc[j][1] *= alpha0;
            oacc[j][2] *= alpha1; oacc[j][3] *= alpha1;
        }

        // ---- P -> smem fp16 (warp-private rows) ----
        __syncwarp();
        #pragma unroll
        for (int j = 0; j < 8; j++) {
            *(__half2*)&Ps[(m0 + g    ) * SH + j * 8 + 2 * tig] =
                __floats2half2_rn(sacc[j][0], sacc[j][1]);
            *(__half2*)&Ps[(m0 + g + 8) * SH + j * 8 + 2 * tig] =
                __floats2half2_rn(sacc[j][2], sacc[j][3]);
        }
        __syncwarp();

        // ---- O += P V  (V B-fragments via ldmatrix.trans) ----
        #pragma unroll
        for (int kp = 0; kp < 4; kp++) {
            uint32_t a0 = U32(&Ps[(m0 + g    ) * SH + kp * 16 + 2 * tig]);
            uint32_t a1 = U32(&Ps[(m0 + g + 8) * SH + kp * 16 + 2 * tig]);
            uint32_t a2 = U32(&Ps[(m0 + g    ) * SH + kp * 16 + 8 + 2 * tig]);
            uint32_t a3 = U32(&Ps[(m0 + g + 8) * SH + kp * 16 + 8 + 2 * tig]);
            unsigned vrow = (unsigned)__cvta_generic_to_shared(
                Vs + (kp * 16 + (lane & 15)) * SH);
            #pragma unroll
            for (int j = 0; j < 8; j++) {
                uint32_t b0, b1;
                asm volatile(
                    "ldmatrix.sync.aligned.m8n8.x2.trans.shared.b16 {%0,%1}, [%2];"
                    : "=r"(b0), "=r"(b1) : "r"(vrow + j * 16));
                mma_h(oacc[j], a0, a1, a2, a3, b0, b1);
            }
        }
    }

    // ---- normalize + write fp16 ----
    float inv0 = 1.f / l0, inv1 = 1.f / l1;
    #pragma unroll
    for (int j = 0; j < 8; j++) {
        int col = j * 8 + 2 * tig;
        *(__half2*)(O + obase + (size_t)r0g * HID + col) =
            __floats2half2_rn(oacc[j][0] * inv0, oacc[j][1] * inv0);
        *(__half2*)(O + obase + (size_t)r1g * HID + col) =
            __floats2half2_rn(oacc[j][2] * inv1, oacc[j][3] * inv1);
    }
}

// ---------------- launch ----------------
extern "C" void kernel_launch(void* const* d_in, const int* in_sizes, int n_in,
                              void* d_out, int out_size)
{
    const float* x     = (const float*)d_in[0];
    const float* Wq    = (const float*)d_in[1];
    const float* bq    = (const float*)d_in[2];
    const float* Wv    = (const float*)d_in[3];
    const float* bv    = (const float*)d_in[4];
    const float* Wo    = (const float*)d_in[5];
    const float* bo    = (const float*)d_in[6];
    const float* W1    = (const float*)d_in[7];
    const float* b1    = (const float*)d_in[8];
    const float* W2    = (const float*)d_in[9];
    const float* b2    = (const float*)d_in[10];
    const float* g1    = (const float*)d_in[11];
    const float* beta1 = (const float*)d_in[12];
    const float* g2    = (const float*)d_in[13];
    const float* beta2 = (const float*)d_in[14];
    float* out = (float*)d_out;

    float *x1, *bqv;
    __half *qv16, *ln16, *ctx16, *h116, *wqv16, *wo16, *w116, *w216;
    cudaGetSymbolAddress((void**)&x1,    g_x1);
    cudaGetSymbolAddress((void**)&bqv,   g_bqv);
    cudaGetSymbolAddress((void**)&qv16,  g_qv16);
    cudaGetSymbolAddress((void**)&ln16,  g_ln16);
    cudaGetSymbolAddress((void**)&ctx16, g_ctx16);
    cudaGetSymbolAddress((void**)&h116,  g_h116);
    cudaGetSymbolAddress((void**)&wqv16, g_wqv16);
    cudaGetSymbolAddress((void**)&wo16,  g_wo16);
    cudaGetSymbolAddress((void**)&w116,  g_w116);
    cudaGetSymbolAddress((void**)&w216,  g_w216);

    cudaFuncSetAttribute(hgemm<0, __half>,
        cudaFuncAttributeMaxDynamicSharedMemorySize, HG_SMEM);
    cudaFuncSetAttribute(hgemm<1, float>,
        cudaFuncAttributeMaxDynamicSharedMemorySize, HG_SMEM);
    cudaFuncSetAttribute(hgemm<2, __half>,
        cudaFuncAttributeMaxDynamicSharedMemorySize, HG_SMEM);
    cudaFuncSetAttribute(attn_h,
        cudaFuncAttributeMaxDynamicSharedMemorySize, AT_SMEM);

    // weights: fp32 -> fp16 (Wq|Wv concatenated)
    int nh = HID * HID, nf = HID * FFDIM;
    cvt_qv<<<nh / 1024, 256>>>(Wq, Wv, bq, bv, wqv16, bqv);
    cvt16<<<nh / 1024, 256>>>(Wo, wo16, nh);
    cvt16<<<nf / 1024, 256>>>(W1, w116, nf);
    cvt16<<<nf / 1024, 256>>>(W2, w216, nf);

    dim3 blk(256);
    dim3 gHID(HID / 128, TOKENS / 128);     // (8, 32)
    dim3 gQV (QVN / 128, TOKENS / 128);     // (16, 32)
    dim3 gFF (FFDIM / 128, TOKENS / 128);   // (32, 32)

    // ln16 = LN(x)
    ln_kernel<<<TOKENS, blk>>>(x, g1, beta1, ln16);
    // qv = ln16 @ [Wq|Wv] + [bq|bv]
    hgemm<0, __half><<<gQV, blk, HG_SMEM>>>(TOKENS, QVN, HID, ln16, wqv16, bqv, nullptr, qv16);
    // causal attention (Q == K)
    attn_h<<<dim3(SEQ / 128, 2 * NHEADS), blk, AT_SMEM>>>(qv16, ctx16);
    // x1 = x + ctx @ Wo + bo
    hgemm<1, float><<<gHID, blk, HG_SMEM>>>(TOKENS, HID, HID, ctx16, wo16, bo, x, x1);
    // ln16 = LN(x1)
    ln_kernel<<<TOKENS, blk>>>(x1, g2, beta2, ln16);
    // h1 = gelu(ln16 @ W1 + b1), fp16 out
    hgemm<2, __half><<<gFF, blk, HG_SMEM>>>(TOKENS, FFDIM, HID, ln16, w116, b1, nullptr, h116);
    // out = x1 + h1 @ W2 + b2
    hgemm<1, float><<<gHID, blk, HG_SMEM>>>(TOKENS, HID, FFDIM, h116, w216, b2, x1, out);
}

// round 12
// speedup vs baseline: 10.6114x; 1.0365x over previous
#include <cuda_runtime.h>
#include <cuda_fp16.h>
#include <math.h>
#include <stdint.h>

#define TOKENS 4096      // 2 * 2048
#define HID    1024
#define FFDIM  4096
#define SEQ    2048
#define NHEADS 16
#define DK     64
#define QVN    2048      // fused Q|V projection width

// ---------------- scratch (device globals; no allocs allowed) ----------------
__device__ float  g_x1  [TOKENS * HID];
__device__ __half g_qv16[(size_t)TOKENS * QVN];
__device__ __half g_ln16[TOKENS * HID];
__device__ __half g_ctx16[TOKENS * HID];
__device__ __half g_h116[(size_t)TOKENS * FFDIM];
// fp16 weights
__device__ __half g_wqv16[(size_t)HID * QVN];   // [k][ Wq | Wv ]
__device__ __half g_wo16[HID * HID];
__device__ __half g_w116[(size_t)HID * FFDIM];
__device__ __half g_w216[(size_t)HID * FFDIM];
__device__ float  g_bqv [QVN];

// ---------------- fp32 -> fp16 convert (4 elems/thread — measured fastest) --
__global__ __launch_bounds__(256) void cvt16(
    const float* __restrict__ in, __half* __restrict__ out, int n)
{
    int i = (blockIdx.x * 256 + threadIdx.x) * 4;
    if (i < n) {
        float4 v = *(const float4*)(in + i);
        __half2 pk2[2];
        pk2[0] = __floats2half2_rn(v.x, v.y);
        pk2[1] = __floats2half2_rn(v.z, v.w);
        *(uint2*)(out + i) = *(const uint2*)pk2;
    }
}

// ---------------- Wq|Wv concat convert: out[k][0:1024]=Wq, [1024:2048]=Wv ----
__global__ __launch_bounds__(256) void cvt_qv(
    const float* __restrict__ Wq, const float* __restrict__ Wv,
    const float* __restrict__ bq, const float* __restrict__ bv,
    __half* __restrict__ out, float* __restrict__ bqv)
{
    int i = (blockIdx.x * 256 + threadIdx.x) * 4;   // over HID*HID
    int k = i >> 10, n = i & 1023;
    float4 q = *(const float4*)(Wq + i);
    float4 v = *(const float4*)(Wv + i);
    __half2 pq[2], pv[2];
    pq[0] = __floats2half2_rn(q.x, q.y); pq[1] = __floats2half2_rn(q.z, q.w);
    pv[0] = __floats2half2_rn(v.x, v.y); pv[1] = __floats2half2_rn(v.z, v.w);
    *(uint2*)(out + (size_t)k * QVN + n)        = *(const uint2*)pq;
    *(uint2*)(out + (size_t)k * QVN + 1024 + n) = *(const uint2*)pv;
    if (i < 1024) {     // first 256 threads also copy biases (4 each)
        *(float4*)(bqv + i)        = *(const float4*)(bq + i);
        *(float4*)(bqv + 1024 + i) = *(const float4*)(bv + i);
    }
}

// ---------------- LayerNorm: one block per row, fp16 out ----------------
__global__ __launch_bounds__(256) void ln_kernel(
    const float* __restrict__ x, const float* __restrict__ gamma,
    const float* __restrict__ beta, __half* __restrict__ out)
{
    int row = blockIdx.x;
    int t = threadIdx.x;
    const float4* xr = (const float4*)(x + (size_t)row * HID);
    float4 v = xr[t];
    float s  = v.x + v.y + v.z + v.w;
    float ss = v.x*v.x + v.y*v.y + v.z*v.z + v.w*v.w;
    #pragma unroll
    for (int o = 16; o; o >>= 1) {
        s  += __shfl_xor_sync(0xffffffffu, s,  o);
        ss += __shfl_xor_sync(0xffffffffu, ss, o);
    }
    __shared__ float rs[8], rss[8];
    if ((t & 31) == 0) { rs[t >> 5] = s; rss[t >> 5] = ss; }
    __syncthreads();
    s = 0.f; ss = 0.f;
    #pragma unroll
    for (int i = 0; i < 8; i++) { s += rs[i]; ss += rss[i]; }
    float mu  = s * (1.f / HID);
    float var = ss * (1.f / HID) - mu * mu;
    float inv = rsqrtf(var + 1e-5f);
    float4 g4 = ((const float4*)gamma)[t];
    float4 b4 = ((const float4*)beta)[t];
    __half2 pk2[2];
    pk2[0] = __floats2half2_rn((v.x - mu) * inv * g4.x + b4.x,
                               (v.y - mu) * inv * g4.y + b4.y);
    pk2[1] = __floats2half2_rn((v.z - mu) * inv * g4.z + b4.z,
                               (v.w - mu) * inv * g4.w + b4.w);
    *(uint2*)(out + (size_t)row * HID + t * 4) = *(const uint2*)pk2;
}

// ---------------- GELU (tanh approx, matches reference) ----------------
__device__ __forceinline__ float gelu_f(float x)
{
    float u = 0.7978845608028654f * (x + 0.044715f * x * x * x);
    return 0.5f * x * (1.f + tanhf(u));
}

// ---------------- FP16 MMA m16n8k16, fp32 accumulate ----------------
__device__ __forceinline__ void mma_h(
    float* c, uint32_t a0, uint32_t a1, uint32_t a2, uint32_t a3,
    uint32_t b0, uint32_t b1)
{
    asm volatile(
        "mma.sync.aligned.m16n8k16.row.col.f32.f16.f16.f32 "
        "{%0,%1,%2,%3}, {%4,%5,%6,%7}, {%8,%9}, {%0,%1,%2,%3};"
        : "+f"(c[0]), "+f"(c[1]), "+f"(c[2]), "+f"(c[3])
        : "r"(a0), "r"(a1), "r"(a2), "r"(a3), "r"(b0), "r"(b1));
}

__device__ __forceinline__ void cp16(void* s, const void* g)
{
    unsigned sa = (unsigned)__cvta_generic_to_shared(s);
    asm volatile("cp.async.cg.shared.global [%0], [%1], 16;" :: "r"(sa), "l"(g));
}

__device__ __forceinline__ void ldm_x4(uint32_t* r, const __half* p)
{
    unsigned a = (unsigned)__cvta_generic_to_shared(p);
    asm volatile(
        "ldmatrix.sync.aligned.m8n8.x4.shared.b16 {%0,%1,%2,%3}, [%4];"
        : "=r"(r[0]), "=r"(r[1]), "=r"(r[2]), "=r"(r[3]) : "r"(a));
}

__device__ __forceinline__ void ldm_x4t(uint32_t* r, const __half* p)
{
    unsigned a = (unsigned)__cvta_generic_to_shared(p);
    asm volatile(
        "ldmatrix.sync.aligned.m8n8.x4.trans.shared.b16 {%0,%1,%2,%3}, [%4];"
        : "=r"(r[0]), "=r"(r[1]), "=r"(r[2]), "=r"(r[3]) : "r"(a));
}

__device__ __forceinline__ uint32_t U32(const __half* p)
{
    return *(const uint32_t*)p;
}

__device__ __forceinline__ uint32_t pack_h2(float x, float y)
{
    __half2 h = __floats2half2_rn(x, y);
    return *(const uint32_t*)&h;
}

__device__ __forceinline__ void st2(float* p, float x, float y)
{
    *(float2*)p = make_float2(x, y);
}
__device__ __forceinline__ void st2(__half* p, float x, float y)
{
    *(__half2*)p = __floats2half2_rn(x, y);
}

// ---------------- FP16 GEMM: C = A(MxK) @ W(KxN) + bias (+res / gelu) ------
// W in native (K,N) row-major. BM=BN=128, BK=64, 3-stage cp.async pipeline.
// A smem [m][k] stride 72; B smem [k][n] stride 136. ldmatrix fragments.
// EPI: 0 = bias, 1 = bias + residual, 2 = gelu(bias + acc)
#define AS_H  (128 * 72)        // halves per A stage
#define BS_H  (64 * 136)        // halves per B stage
#define STG_H (AS_H + BS_H)     // halves per stage (17920)
#define HG_SMEM (3 * STG_H * 2) // bytes (107520)
template <int EPI, typename OT>
__global__ __launch_bounds__(256, 2) void hgemm(
    int M, int N, int K,
    const __half* __restrict__ A, const __half* __restrict__ W,
    const float* __restrict__ bias, const float* __restrict__ R,
    OT* __restrict__ C)
{
    extern __shared__ __half hs[];

    int tid  = threadIdx.x;
    int lane = tid & 31, w = tid >> 5;
    int wm = w >> 1, wn = w & 1;
    int g = lane >> 2, tig = lane & 3;
    int bx = blockIdx.x, by = blockIdx.y;

    const __half* Ab = A + (size_t)by * 128 * K;
    const __half* Wb = W + bx * 128;

    auto stage_in = [&](int s, int t) {
        __half* As = hs + s * STG_H;
        __half* Bs = As + AS_H;
        int k0 = t << 6;
        #pragma unroll
        for (int i = 0; i < 4; i++) {
            int c = tid + i * 256;
            int r = c >> 3, col = (c & 7) * 8;
            cp16(As + r * 72 + col, Ab + (size_t)r * K + k0 + col);
        }
        #pragma unroll
        for (int i = 0; i < 4; i++) {
            int c = tid + i * 256;
            int r = c >> 4, col = (c & 15) * 8;
            cp16(Bs + r * 136 + col, Wb + (size_t)(k0 + r) * N + col);
        }
        asm volatile("cp.async.commit_group;");
    };

    float acc[2][8][4] = {};
    int NT = K >> 6;

    stage_in(0, 0);
    stage_in(1, 1);

    int s = 0;
    for (int t = 0; t < NT; t++) {
        asm volatile("cp.async.wait_group 1;");
        __syncthreads();

        if (t + 2 < NT) stage_in((s + 2) % 3, t + 2);
        else            asm volatile("cp.async.commit_group;");

        __half* As = hs + s * STG_H;
        __half* Bs = As + AS_H;

        #pragma unroll
        for (int kk = 0; kk < 4; kk++) {
            int k8 = kk * 16;
            uint32_t a[2][4];
            #pragma unroll
            for (int i = 0; i < 2; i++)
                ldm_x4(a[i], As + (wm * 32 + i * 16 + (lane & 15)) * 72
                               + k8 + (lane >> 4) * 8);
            #pragma unroll
            for (int jp = 0; jp < 4; jp++) {
                uint32_t b[4];
                ldm_x4t(b, Bs + (k8 + (lane & 15)) * 136
                             + wn * 64 + jp * 16 + (lane >> 4) * 8);
                #pragma unroll
                for (int i = 0; i < 2; i++) {
                    mma_h(acc[i][2 * jp    ], a[i][0], a[i][1], a[i][2], a[i][3],
                          b[0], b[1]);
                    mma_h(acc[i][2 * jp + 1], a[i][0], a[i][1], a[i][2], a[i][3],
                          b[2], b[3]);
                }
            }
        }
        s = (s + 1) % 3;
    }

    // ---- epilogue ----
    #pragma unroll
    for (int i = 0; i < 2; i++) {
        int r0 = by * 128 + wm * 32 + i * 16 + g;
        int r1 = r0 + 8;
        #pragma unroll
        for (int j = 0; j < 8; j++) {
            int col = bx * 128 + wn * 64 + j * 8 + tig * 2;
            float2 bb = *(const float2*)(bias + col);
            float v00 = acc[i][j][0] + bb.x, v01 = acc[i][j][1] + bb.y;
            float v10 = acc[i][j][2] + bb.x, v11 = acc[i][j][3] + bb.y;
            if (EPI == 1) {
                float2 q0 = *(const float2*)(R + (size_t)r0 * N + col);
                float2 q1 = *(const float2*)(R + (size_t)r1 * N + col);
                v00 += q0.x; v01 += q0.y;
                v10 += q1.x; v11 += q1.y;
            } else if (EPI == 2) {
                v00 = gelu_f(v00); v01 = gelu_f(v01);
                v10 = gelu_f(v10); v11 = gelu_f(v11);
            }
            st2(C + (size_t)r0 * N + col, v00, v01);
            st2(C + (size_t)r1 * N + col, v10, v11);
        }
    }
}

// ---------------- FP16 causal flash attention ---------------------------------
// Register-held P (S-acc fragments map directly onto PV A-fragments).
// 3-buffer K/V cp.async pipeline, ONE __syncthreads per tile iteration.
#define SH 72
#define AT_KV   (64 * SH)                      // halves per K or V buffer
#define AT_SMEM ((6 * AT_KV + 128 * SH) * 2)   // bytes (73728)
__global__ __launch_bounds__(256, 2) void attn_h(
    const __half* __restrict__ QV, __half* __restrict__ O)
{
    extern __shared__ __half sm[];
    __half* KsB = sm;                   // [3][64][SH]
    __half* VsB = sm + 3 * AT_KV;       // [3][64][SH]
    __half* Ps  = sm + 6 * AT_KV;       // [128][SH]  Q staging only

    int qt = (int)gridDim.x - 1 - (int)blockIdx.x;   // longest first
    int bh = blockIdx.y;
    int b = bh >> 4, h = bh & 15;
    int tid = threadIdx.x, lane = tid & 31, w = tid >> 5;
    int g = lane >> 2, tig = lane & 3;
    int m0 = w * 16;
    const __half* Qh = QV + (size_t)b * SEQ * QVN + h * DK;
    const __half* Vh = Qh + 1024;
    size_t obase = (size_t)b * SEQ * HID + (size_t)h * DK;

    auto stage_kv = [&](int s, int kt) {
        #pragma unroll
        for (int i = 0; i < 2; i++) {
            int idx = tid + i * 256;            // 64 rows x 8 chunks
            int row = idx >> 3, c8 = (idx & 7) * 8;
            cp16(KsB + s * AT_KV + row * SH + c8,
                 Qh + (size_t)(kt * 64 + row) * QVN + c8);
            cp16(VsB + s * AT_KV + row * SH + c8,
                 Vh + (size_t)(kt * 64 + row) * QVN + c8);
        }
        asm volatile("cp.async.commit_group;");
    };

    int ktmax = 2 * qt + 1;

    // ---- stage Q tile, prefetch k-tiles 0 and 1, lift Q fragments ----
    #pragma unroll
    for (int i = 0; i < 4; i++) {
        int idx = tid + i * 256;
        int row = idx >> 3, c8 = (idx & 7) * 8;
        *(uint4*)&Ps[row * SH + c8] =
            *(const uint4*)(Qh + (size_t)(qt * 128 + row) * QVN + c8);
    }
    stage_kv(0, 0);
    if (1 <= ktmax) stage_kv(1, 1);
    else asm volatile("cp.async.commit_group;");
    __syncthreads();
    uint32_t qf[4][4];
    #pragma unroll
    for (int kg = 0; kg < 4; kg++) {
        qf[kg][0] = U32(&Ps[(m0 + g    ) * SH + kg * 16 + 2 * tig]);
        qf[kg][1] = U32(&Ps[(m0 + g + 8) * SH + kg * 16 + 2 * tig]);
        qf[kg][2] = U32(&Ps[(m0 + g    ) * SH + kg * 16 + 8 + 2 * tig]);
        qf[kg][3] = U32(&Ps[(m0 + g + 8) * SH + kg * 16 + 8 + 2 * tig]);
    }

    float oacc[8][4] = {};
    float mr0 = -INFINITY, mr1 = -INFINITY, l0 = 0.f, l1 = 0.f;
    int r0g = qt * 128 + m0 + g;
    int r1g = r0g + 8;

    for (int kt = 0; kt <= ktmax; kt++) {
        asm volatile("cp.async.wait_group 1;");     // tile kt ready
        __syncthreads();                            // visible; iter kt-1 done
        if (kt + 2 <= ktmax) stage_kv((kt + 2) % 3, kt + 2);
        else asm volatile("cp.async.commit_group;");

        const __half* Ks = KsB + (kt % 3) * AT_KV;
        const __half* Vs = VsB + (kt % 3) * AT_KV;

        // ---- S = Q K^T ----
        float sacc[8][4] = {};
        #pragma unroll
        for (int kg = 0; kg < 4; kg++) {
            #pragma unroll
            for (int j = 0; j < 8; j++) {
                uint32_t b0 = U32(&Ks[(j * 8 + g) * SH + kg * 16 + 2 * tig]);
                uint32_t b1 = U32(&Ks[(j * 8 + g) * SH + kg * 16 + 8 + 2 * tig]);
                mma_h(sacc[j], qf[kg][0], qf[kg][1], qf[kg][2], qf[kg][3], b0, b1);
            }
        }

        // ---- scale + causal mask ----
        const float scale = 0.125f;
        if (kt >= 2 * qt) {
            #pragma unroll
            for (int j = 0; j < 8; j++) {
                int c0 = kt * 64 + j * 8 + 2 * tig;
                sacc[j][0] = (c0     > r0g) ? -INFINITY : sacc[j][0] * scale;
                sacc[j][1] = (c0 + 1 > r0g) ? -INFINITY : sacc[j][1] * scale;
                sacc[j][2] = (c0     > r1g) ? -INFINITY : sacc[j][2] * scale;
                sacc[j][3] = (c0 + 1 > r1g) ? -INFINITY : sacc[j][3] * scale;
            }
        } else {
            #pragma unroll
            for (int j = 0; j < 8; j++)
                #pragma unroll
                for (int c = 0; c < 4; c++) sacc[j][c] *= scale;
        }

        // ---- online softmax (fp32) ----
        float mt0 = mr0, mt1 = mr1;
        #pragma unroll
        for (int j = 0; j < 8; j++) {
            mt0 = fmaxf(mt0, fmaxf(sacc[j][0], sacc[j][1]));
            mt1 = fmaxf(mt1, fmaxf(sacc[j][2], sacc[j][3]));
        }
        mt0 = fmaxf(mt0, __shfl_xor_sync(0xffffffffu, mt0, 1));
        mt0 = fmaxf(mt0, __shfl_xor_sync(0xffffffffu, mt0, 2));
        mt1 = fmaxf(mt1, __shfl_xor_sync(0xffffffffu, mt1, 1));
        mt1 = fmaxf(mt1, __shfl_xor_sync(0xffffffffu, mt1, 2));
        float alpha0 = __expf(mr0 - mt0);
        float alpha1 = __expf(mr1 - mt1);
        mr0 = mt0; mr1 = mt1;
        float ps0 = 0.f, ps1 = 0.f;
        #pragma unroll
        for (int j = 0; j < 8; j++) {
            sacc[j][0] = __expf(sacc[j][0] - mt0); ps0 += sacc[j][0];
            sacc[j][1] = __expf(sacc[j][1] - mt0); ps0 += sacc[j][1];
            sacc[j][2] = __expf(sacc[j][2] - mt1); ps1 += sacc[j][2];
            sacc[j][3] = __expf(sacc[j][3] - mt1); ps1 += sacc[j][3];
        }
        ps0 += __shfl_xor_sync(0xffffffffu, ps0, 1);
        ps0 += __shfl_xor_sync(0xffffffffu, ps0, 2);
        ps1 += __shfl_xor_sync(0xffffffffu, ps1, 1);
        ps1 += __shfl_xor_sync(0xffffffffu, ps1, 2);
        l0 = l0 * alpha0 + ps0;
        l1 = l1 * alpha1 + ps1;
        #pragma unroll
        for (int j = 0; j < 8; j++) {
            oacc[j][0] *= alpha0; oacc[j][1] *= alpha0;
            oacc[j][2] *= alpha1; oacc[j][3] *= alpha1;
        }

        // ---- O += P V : P stays in registers (S-acc == PV A-fragment map) --
        #pragma unroll
        for (int kp = 0; kp < 4; kp++) {
            uint32_t a0 = pack_h2(sacc[2 * kp    ][0], sacc[2 * kp    ][1]);
            uint32_t a1 = pack_h2(sacc[2 * kp    ][2], sacc[2 * kp    ][3]);
            uint32_t a2 = pack_h2(sacc[2 * kp + 1][0], sacc[2 * kp + 1][1]);
            uint32_t a3 = pack_h2(sacc[2 * kp + 1][2], sacc[2 * kp + 1][3]);
            unsigned vrow = (unsigned)__cvta_generic_to_shared(
                Vs + (kp * 16 + (lane & 15)) * SH);
            #pragma unroll
            for (int j = 0; j < 8; j++) {
                uint32_t b0, b1;
                asm volatile(
                    "ldmatrix.sync.aligned.m8n8.x2.trans.shared.b16 {%0,%1}, [%2];"
                    : "=r"(b0), "=r"(b1) : "r"(vrow + j * 16));
                mma_h(oacc[j], a0, a1, a2, a3, b0, b1);
            }
        }
    }

    // ---- normalize + write fp16 ----
    float inv0 = 1.f / l0, inv1 = 1.f / l1;
    #pragma unroll
    for (int j = 0; j < 8; j++) {
        int col = j * 8 + 2 * tig;
        *(__half2*)(O + obase + (size_t)r0g * HID + col) =
            __floats2half2_rn(oacc[j][0] * inv0, oacc[j][1] * inv0);
        *(__half2*)(O + obase + (size_t)r1g * HID + col) =
            __floats2half2_rn(oacc[j][2] * inv1, oacc[j][3] * inv1);
    }
}

// ---------------- launch ----------------
extern "C" void kernel_launch(void* const* d_in, const int* in_sizes, int n_in,
                              void* d_out, int out_size)
{
    const float* x     = (const float*)d_in[0];
    const float* Wq    = (const float*)d_in[1];
    const float* bq    = (const float*)d_in[2];
    const float* Wv    = (const float*)d_in[3];
    const float* bv    = (const float*)d_in[4];
    const float* Wo    = (const float*)d_in[5];
    const float* bo    = (const float*)d_in[6];
    const float* W1    = (const float*)d_in[7];
    const float* b1    = (const float*)d_in[8];
    const float* W2    = (const float*)d_in[9];
    const float* b2    = (const float*)d_in[10];
    const float* g1    = (const float*)d_in[11];
    const float* beta1 = (const float*)d_in[12];
    const float* g2    = (const float*)d_in[13];
    const float* beta2 = (const float*)d_in[14];
    float* out = (float*)d_out;

    float *x1, *bqv;
    __half *qv16, *ln16, *ctx16, *h116, *wqv16, *wo16, *w116, *w216;
    cudaGetSymbolAddress((void**)&x1,    g_x1);
    cudaGetSymbolAddress((void**)&bqv,   g_bqv);
    cudaGetSymbolAddress((void**)&qv16,  g_qv16);
    cudaGetSymbolAddress((void**)&ln16,  g_ln16);
    cudaGetSymbolAddress((void**)&ctx16, g_ctx16);
    cudaGetSymbolAddress((void**)&h116,  g_h116);
    cudaGetSymbolAddress((void**)&wqv16, g_wqv16);
    cudaGetSymbolAddress((void**)&wo16,  g_wo16);
    cudaGetSymbolAddress((void**)&w116,  g_w116);
    cudaGetSymbolAddress((void**)&w216,  g_w216);

    cudaFuncSetAttribute(hgemm<0, __half>,
        cudaFuncAttributeMaxDynamicSharedMemorySize, HG_SMEM);
    cudaFuncSetAttribute(hgemm<1, float>,
        cudaFuncAttributeMaxDynamicSharedMemorySize, HG_SMEM);
    cudaFuncSetAttribute(hgemm<2, __half>,
        cudaFuncAttributeMaxDynamicSharedMemorySize, HG_SMEM);
    cudaFuncSetAttribute(attn_h,
        cudaFuncAttributeMaxDynamicSharedMemorySize, AT_SMEM);

    // weights: fp32 -> fp16 (Wq|Wv concatenated)
    int nh = HID * HID, nf = HID * FFDIM;
    cvt_qv<<<nh / 1024, 256>>>(Wq, Wv, bq, bv, wqv16, bqv);
    cvt16<<<nh / 1024, 256>>>(Wo, wo16, nh);
    cvt16<<<nf / 1024, 256>>>(W1, w116, nf);
    cvt16<<<nf / 1024, 256>>>(W2, w216, nf);

    dim3 blk(256);
    dim3 gHID(HID / 128, TOKENS / 128);     // (8, 32)
    dim3 gQV (QVN / 128, TOKENS / 128);     // (16, 32)
    dim3 gFF (FFDIM / 128, TOKENS / 128);   // (32, 32)

    // ln16 = LN(x)
    ln_kernel<<<TOKENS, blk>>>(x, g1, beta1, ln16);
    // qv = ln16 @ [Wq|Wv] + [bq|bv]
    hgemm<0, __half><<<gQV, blk, HG_SMEM>>>(TOKENS, QVN, HID, ln16, wqv16, bqv, nullptr, qv16);
    // causal attention (Q == K)
    attn_h<<<dim3(SEQ / 128, 2 * NHEADS), blk, AT_SMEM>>>(qv16, ctx16);
    // x1 = x + ctx @ Wo + bo
    hgemm<1, float><<<gHID, blk, HG_SMEM>>>(TOKENS, HID, HID, ctx16, wo16, bo, x, x1);
    // ln16 = LN(x1)
    ln_kernel<<<TOKENS, blk>>>(x1, g2, beta2, ln16);
    // h1 = gelu(ln16 @ W1 + b1), fp16 out
    hgemm<2, __half><<<gFF, blk, HG_SMEM>>>(TOKENS, FFDIM, HID, ln16, w116, b1, nullptr, h116);
    // out = x1 + h1 @ W2 + b2
    hgemm<1, float><<<gHID, blk, HG_SMEM>>>(TOKENS, HID, FFDIM, h116, w216, b2, x1, out);
}

// round 13
// speedup vs baseline: 10.8154x; 1.0192x over previous
#include <cuda_runtime.h>
#include <cuda_fp16.h>
#include <math.h>
#include <stdint.h>

#define TOKENS 4096      // 2 * 2048
#define HID    1024
#define FFDIM  4096
#define SEQ    2048
#define NHEADS 16
#define DK     64
#define QVN    2048      // fused Q|V projection width

// ---------------- scratch (device globals; no allocs allowed) ----------------
__device__ float  g_x1  [TOKENS * HID];
__device__ __half g_qv16[(size_t)TOKENS * QVN];
__device__ __half g_ln16[TOKENS * HID];
__device__ __half g_ctx16[TOKENS * HID];
__device__ __half g_h116[(size_t)TOKENS * FFDIM];
// fp16 weights
__device__ __half g_wqv16[(size_t)HID * QVN];   // [k][ Wq | Wv ]
__device__ __half g_wo16[HID * HID];
__device__ __half g_w116[(size_t)HID * FFDIM];
__device__ __half g_w216[(size_t)HID * FFDIM];
__device__ float  g_bqv [QVN];

// ---------------- fp32 -> fp16 convert, block-strided MLP=4, coalesced ------
__global__ __launch_bounds__(256) void cvt16(
    const float* __restrict__ in, __half* __restrict__ out, int n)
{
    int i0 = (blockIdx.x * 256 + threadIdx.x) * 4;
    int stride = gridDim.x * 1024;
    #pragma unroll
    for (int c = 0; c < 4; c++) {
        int i = i0 + c * stride;
        if (i < n) {
            float4 v = *(const float4*)(in + i);
            __half2 pk2[2];
            pk2[0] = __floats2half2_rn(v.x, v.y);
            pk2[1] = __floats2half2_rn(v.z, v.w);
            *(uint2*)(out + i) = *(const uint2*)pk2;
        }
    }
}

// ---------------- Wq|Wv concat convert: out[k][0:1024]=Wq, [1024:2048]=Wv ----
__global__ __launch_bounds__(256) void cvt_qv(
    const float* __restrict__ Wq, const float* __restrict__ Wv,
    const float* __restrict__ bq, const float* __restrict__ bv,
    __half* __restrict__ out, float* __restrict__ bqv)
{
    int i = (blockIdx.x * 256 + threadIdx.x) * 4;   // over HID*HID
    int k = i >> 10, n = i & 1023;
    float4 q = *(const float4*)(Wq + i);
    float4 v = *(const float4*)(Wv + i);
    __half2 pq[2], pv[2];
    pq[0] = __floats2half2_rn(q.x, q.y); pq[1] = __floats2half2_rn(q.z, q.w);
    pv[0] = __floats2half2_rn(v.x, v.y); pv[1] = __floats2half2_rn(v.z, v.w);
    *(uint2*)(out + (size_t)k * QVN + n)        = *(const uint2*)pq;
    *(uint2*)(out + (size_t)k * QVN + 1024 + n) = *(const uint2*)pv;
    if (i < 1024) {     // first 256 threads also copy biases (4 each)
        *(float4*)(bqv + i)        = *(const float4*)(bq + i);
        *(float4*)(bqv + 1024 + i) = *(const float4*)(bv + i);
    }
}

// ---------------- LayerNorm: one block per row, fp16 out ----------------
__global__ __launch_bounds__(256) void ln_kernel(
    const float* __restrict__ x, const float* __restrict__ gamma,
    const float* __restrict__ beta, __half* __restrict__ out)
{
    int row = blockIdx.x;
    int t = threadIdx.x;
    const float4* xr = (const float4*)(x + (size_t)row * HID);
    float4 v = xr[t];
    float s  = v.x + v.y + v.z + v.w;
    float ss = v.x*v.x + v.y*v.y + v.z*v.z + v.w*v.w;
    #pragma unroll
    for (int o = 16; o; o >>= 1) {
        s  += __shfl_xor_sync(0xffffffffu, s,  o);
        ss += __shfl_xor_sync(0xffffffffu, ss, o);
    }
    __shared__ float rs[8], rss[8];
    if ((t & 31) == 0) { rs[t >> 5] = s; rss[t >> 5] = ss; }
    __syncthreads();
    s = 0.f; ss = 0.f;
    #pragma unroll
    for (int i = 0; i < 8; i++) { s += rs[i]; ss += rss[i]; }
    float mu  = s * (1.f / HID);
    float var = ss * (1.f / HID) - mu * mu;
    float inv = rsqrtf(var + 1e-5f);
    float4 g4 = ((const float4*)gamma)[t];
    float4 b4 = ((const float4*)beta)[t];
    __half2 pk2[2];
    pk2[0] = __floats2half2_rn((v.x - mu) * inv * g4.x + b4.x,
                               (v.y - mu) * inv * g4.y + b4.y);
    pk2[1] = __floats2half2_rn((v.z - mu) * inv * g4.z + b4.z,
                               (v.w - mu) * inv * g4.w + b4.w);
    *(uint2*)(out + (size_t)row * HID + t * 4) = *(const uint2*)pk2;
}

// ---------------- GELU (tanh approx, matches reference) ----------------
__device__ __forceinline__ float gelu_f(float x)
{
    float u = 0.7978845608028654f * (x + 0.044715f * x * x * x);
    return 0.5f * x * (1.f + tanhf(u));
}

// ---------------- FP16 MMA m16n8k16, fp32 accumulate ----------------
__device__ __forceinline__ void mma_h(
    float* c, uint32_t a0, uint32_t a1, uint32_t a2, uint32_t a3,
    uint32_t b0, uint32_t b1)
{
    asm volatile(
        "mma.sync.aligned.m16n8k16.row.col.f32.f16.f16.f32 "
        "{%0,%1,%2,%3}, {%4,%5,%6,%7}, {%8,%9}, {%0,%1,%2,%3};"
        : "+f"(c[0]), "+f"(c[1]), "+f"(c[2]), "+f"(c[3])
        : "r"(a0), "r"(a1), "r"(a2), "r"(a3), "r"(b0), "r"(b1));
}

__device__ __forceinline__ void cp16(void* s, const void* g)
{
    unsigned sa = (unsigned)__cvta_generic_to_shared(s);
    asm volatile("cp.async.cg.shared.global [%0], [%1], 16;" :: "r"(sa), "l"(g));
}

__device__ __forceinline__ void ldm_x4(uint32_t* r, const __half* p)
{
    unsigned a = (unsigned)__cvta_generic_to_shared(p);
    asm volatile(
        "ldmatrix.sync.aligned.m8n8.x4.shared.b16 {%0,%1,%2,%3}, [%4];"
        : "=r"(r[0]), "=r"(r[1]), "=r"(r[2]), "=r"(r[3]) : "r"(a));
}

__device__ __forceinline__ void ldm_x4t(uint32_t* r, const __half* p)
{
    unsigned a = (unsigned)__cvta_generic_to_shared(p);
    asm volatile(
        "ldmatrix.sync.aligned.m8n8.x4.trans.shared.b16 {%0,%1,%2,%3}, [%4];"
        : "=r"(r[0]), "=r"(r[1]), "=r"(r[2]), "=r"(r[3]) : "r"(a));
}

__device__ __forceinline__ uint32_t U32(const __half* p)
{
    return *(const uint32_t*)p;
}

__device__ __forceinline__ uint32_t pack_h2(float x, float y)
{
    __half2 h = __floats2half2_rn(x, y);
    return *(const uint32_t*)&h;
}

__device__ __forceinline__ void st2(float* p, float x, float y)
{
    *(float2*)p = make_float2(x, y);
}
__device__ __forceinline__ void st2(__half* p, float x, float y)
{
    *(__half2*)p = __floats2half2_rn(x, y);
}

// ---------------- FP16 GEMM: C = A(MxK) @ W(KxN) + bias (+res / gelu) ------
// W in native (K,N) row-major. BM=BN=128, BK=64, 3-stage cp.async pipeline.
// A smem [m][k] stride 72; B smem [k][n] stride 136. ldmatrix fragments.
// EPI: 0 = bias, 1 = bias + residual, 2 = gelu(bias + acc)
#define AS_H  (128 * 72)        // halves per A stage
#define BS_H  (64 * 136)        // halves per B stage
#define STG_H (AS_H + BS_H)     // halves per stage (17920)
#define HG_SMEM (3 * STG_H * 2) // bytes (107520)
template <int EPI, typename OT>
__global__ __launch_bounds__(256, 2) void hgemm(
    int M, int N, int K,
    const __half* __restrict__ A, const __half* __restrict__ W,
    const float* __restrict__ bias, const float* __restrict__ R,
    OT* __restrict__ C)
{
    extern __shared__ __half hs[];

    int tid  = threadIdx.x;
    int lane = tid & 31, w = tid >> 5;
    int wm = w >> 1, wn = w & 1;
    int g = lane >> 2, tig = lane & 3;
    int bx = blockIdx.x, by = blockIdx.y;

    const __half* Ab = A + (size_t)by * 128 * K;
    const __half* Wb = W + bx * 128;

    auto stage_in = [&](int s, int t) {
        __half* As = hs + s * STG_H;
        __half* Bs = As + AS_H;
        int k0 = t << 6;
        #pragma unroll
        for (int i = 0; i < 4; i++) {
            int c = tid + i * 256;
            int r = c >> 3, col = (c & 7) * 8;
            cp16(As + r * 72 + col, Ab + (size_t)r * K + k0 + col);
        }
        #pragma unroll
        for (int i = 0; i < 4; i++) {
            int c = tid + i * 256;
            int r = c >> 4, col = (c & 15) * 8;
            cp16(Bs + r * 136 + col, Wb + (size_t)(k0 + r) * N + col);
        }
        asm volatile("cp.async.commit_group;");
    };

    float acc[2][8][4] = {};
    int NT = K >> 6;

    stage_in(0, 0);
    stage_in(1, 1);

    int s = 0;
    for (int t = 0; t < NT; t++) {
        asm volatile("cp.async.wait_group 1;");
        __syncthreads();

        if (t + 2 < NT) stage_in((s + 2) % 3, t + 2);
        else            asm volatile("cp.async.commit_group;");

        __half* As = hs + s * STG_H;
        __half* Bs = As + AS_H;

        #pragma unroll
        for (int kk = 0; kk < 4; kk++) {
            int k8 = kk * 16;
            uint32_t a[2][4];
            #pragma unroll
            for (int i = 0; i < 2; i++)
                ldm_x4(a[i], As + (wm * 32 + i * 16 + (lane & 15)) * 72
                               + k8 + (lane >> 4) * 8);
            #pragma unroll
            for (int jp = 0; jp < 4; jp++) {
                uint32_t b[4];
                ldm_x4t(b, Bs + (k8 + (lane & 15)) * 136
                             + wn * 64 + jp * 16 + (lane >> 4) * 8);
                #pragma unroll
                for (int i = 0; i < 2; i++) {
                    mma_h(acc[i][2 * jp    ], a[i][0], a[i][1], a[i][2], a[i][3],
                          b[0], b[1]);
                    mma_h(acc[i][2 * jp + 1], a[i][0], a[i][1], a[i][2], a[i][3],
                          b[2], b[3]);
                }
            }
        }
        s = (s + 1) % 3;
    }

    // ---- epilogue ----
    #pragma unroll
    for (int i = 0; i < 2; i++) {
        int r0 = by * 128 + wm * 32 + i * 16 + g;
        int r1 = r0 + 8;
        #pragma unroll
        for (int j = 0; j < 8; j++) {
            int col = bx * 128 + wn * 64 + j * 8 + tig * 2;
            float2 bb = *(const float2*)(bias + col);
            float v00 = acc[i][j][0] + bb.x, v01 = acc[i][j][1] + bb.y;
            float v10 = acc[i][j][2] + bb.x, v11 = acc[i][j][3] + bb.y;
            if (EPI == 1) {
                float2 q0 = *(const float2*)(R + (size_t)r0 * N + col);
                float2 q1 = *(const float2*)(R + (size_t)r1 * N + col);
                v00 += q0.x; v01 += q0.y;
                v10 += q1.x; v11 += q1.y;
            } else if (EPI == 2) {
                v00 = gelu_f(v00); v01 = gelu_f(v01);
                v10 = gelu_f(v10); v11 = gelu_f(v11);
            }
            st2(C + (size_t)r0 * N + col, v00, v01);
            st2(C + (size_t)r1 * N + col, v10, v11);
        }
    }
}

// ---------------- FP16 causal flash attention ---------------------------------
// Register-held P; ldmatrix.x4 K and V fragments; 3-buffer cp.async K/V
// pipeline with ONE __syncthreads per tile iteration.
#define SH 72
#define AT_KV   (64 * SH)                      // halves per K or V buffer
#define AT_SMEM ((6 * AT_KV + 128 * SH) * 2)   // bytes (73728)
__global__ __launch_bounds__(256, 2) void attn_h(
    const __half* __restrict__ QV, __half* __restrict__ O)
{
    extern __shared__ __half sm[];
    __half* KsB = sm;                   // [3][64][SH]
    __half* VsB = sm + 3 * AT_KV;       // [3][64][SH]
    __half* Ps  = sm + 6 * AT_KV;       // [128][SH]  Q staging only

    int qt = (int)gridDim.x - 1 - (int)blockIdx.x;   // longest first
    int bh = blockIdx.y;
    int b = bh >> 4, h = bh & 15;
    int tid = threadIdx.x, lane = tid & 31, w = tid >> 5;
    int g = lane >> 2, tig = lane & 3;
    int m0 = w * 16;
    int lm  = lane >> 3, lmr = lane & 7;    // ldmatrix x4 lane decomposition
    const __half* Qh = QV + (size_t)b * SEQ * QVN + h * DK;
    const __half* Vh = Qh + 1024;
    size_t obase = (size_t)b * SEQ * HID + (size_t)h * DK;

    auto stage_kv = [&](int s, int kt) {
        #pragma unroll
        for (int i = 0; i < 2; i++) {
            int idx = tid + i * 256;            // 64 rows x 8 chunks
            int row = idx >> 3, c8 = (idx & 7) * 8;
            cp16(KsB + s * AT_KV + row * SH + c8,
                 Qh + (size_t)(kt * 64 + row) * QVN + c8);
            cp16(VsB + s * AT_KV + row * SH + c8,
                 Vh + (size_t)(kt * 64 + row) * QVN + c8);
        }
        asm volatile("cp.async.commit_group;");
    };

    int ktmax = 2 * qt + 1;

    // ---- stage Q tile, prefetch k-tiles 0 and 1, lift Q fragments ----
    #pragma unroll
    for (int i = 0; i < 4; i++) {
        int idx = tid + i * 256;
        int row = idx >> 3, c8 = (idx & 7) * 8;
        *(uint4*)&Ps[row * SH + c8] =
            *(const uint4*)(Qh + (size_t)(qt * 128 + row) * QVN + c8);
    }
    stage_kv(0, 0);
    if (1 <= ktmax) stage_kv(1, 1);
    else asm volatile("cp.async.commit_group;");
    __syncthreads();
    uint32_t qf[4][4];
    #pragma unroll
    for (int kg = 0; kg < 4; kg++) {
        qf[kg][0] = U32(&Ps[(m0 + g    ) * SH + kg * 16 + 2 * tig]);
        qf[kg][1] = U32(&Ps[(m0 + g + 8) * SH + kg * 16 + 2 * tig]);
        qf[kg][2] = U32(&Ps[(m0 + g    ) * SH + kg * 16 + 8 + 2 * tig]);
        qf[kg][3] = U32(&Ps[(m0 + g + 8) * SH + kg * 16 + 8 + 2 * tig]);
    }

    float oacc[8][4] = {};
    float mr0 = -INFINITY, mr1 = -INFINITY, l0 = 0.f, l1 = 0.f;
    int r0g = qt * 128 + m0 + g;
    int r1g = r0g + 8;

    for (int kt = 0; kt <= ktmax; kt++) {
        asm volatile("cp.async.wait_group 1;");     // tile kt ready
        __syncthreads();                            // visible; iter kt-1 done
        if (kt + 2 <= ktmax) stage_kv((kt + 2) % 3, kt + 2);
        else asm volatile("cp.async.commit_group;");

        const __half* Ks = KsB + (kt % 3) * AT_KV;
        const __half* Vs = VsB + (kt % 3) * AT_KV;

        // ---- S = Q K^T : K B-fragments via ldmatrix.x4 (j pairs) ----
        float sacc[8][4] = {};
        #pragma unroll
        for (int kg = 0; kg < 4; kg++) {
            #pragma unroll
            for (int jp = 0; jp < 4; jp++) {
                uint32_t bf[4];
                ldm_x4(bf, Ks + (jp * 16 + (lm >> 1) * 8 + lmr) * SH
                             + kg * 16 + (lm & 1) * 8);
                mma_h(sacc[2 * jp    ], qf[kg][0], qf[kg][1], qf[kg][2],
                      qf[kg][3], bf[0], bf[1]);
                mma_h(sacc[2 * jp + 1], qf[kg][0], qf[kg][1], qf[kg][2],
                      qf[kg][3], bf[2], bf[3]);
            }
        }

        // ---- scale + causal mask ----
        const float scale = 0.125f;
        if (kt >= 2 * qt) {
            #pragma unroll
            for (int j = 0; j < 8; j++) {
                int c0 = kt * 64 + j * 8 + 2 * tig;
                sacc[j][0] = (c0     > r0g) ? -INFINITY : sacc[j][0] * scale;
                sacc[j][1] = (c0 + 1 > r0g) ? -INFINITY : sacc[j][1] * scale;
                sacc[j][2] = (c0     > r1g) ? -INFINITY : sacc[j][2] * scale;
                sacc[j][3] = (c0 + 1 > r1g) ? -INFINITY : sacc[j][3] * scale;
            }
        } else {
            #pragma unroll
            for (int j = 0; j < 8; j++)
                #pragma unroll
                for (int c = 0; c < 4; c++) sacc[j][c] *= scale;
        }

        // ---- online softmax (fp32) ----
        float mt0 = mr0, mt1 = mr1;
        #pragma unroll
        for (int j = 0; j < 8; j++) {
            mt0 = fmaxf(mt0, fmaxf(sacc[j][0], sacc[j][1]));
            mt1 = fmaxf(mt1, fmaxf(sacc[j][2], sacc[j][3]));
        }
        mt0 = fmaxf(mt0, __shfl_xor_sync(0xffffffffu, mt0, 1));
        mt0 = fmaxf(mt0, __shfl_xor_sync(0xffffffffu, mt0, 2));
        mt1 = fmaxf(mt1, __shfl_xor_sync(0xffffffffu, mt1, 1));
        mt1 = fmaxf(mt1, __shfl_xor_sync(0xffffffffu, mt1, 2));
        float alpha0 = __expf(mr0 - mt0);
        float alpha1 = __expf(mr1 - mt1);
        mr0 = mt0; mr1 = mt1;
        float ps0 = 0.f, ps1 = 0.f;
        #pragma unroll
        for (int j = 0; j < 8; j++) {
            sacc[j][0] = __expf(sacc[j][0] - mt0); ps0 += sacc[j][0];
            sacc[j][1] = __expf(sacc[j][1] - mt0); ps0 += sacc[j][1];
            sacc[j][2] = __expf(sacc[j][2] - mt1); ps1 += sacc[j][2];
            sacc[j][3] = __expf(sacc[j][3] - mt1); ps1 += sacc[j][3];
        }
        ps0 += __shfl_xor_sync(0xffffffffu, ps0, 1);
        ps0 += __shfl_xor_sync(0xffffffffu, ps0, 2);
        ps1 += __shfl_xor_sync(0xffffffffu, ps1, 1);
        ps1 += __shfl_xor_sync(0xffffffffu, ps1, 2);
        l0 = l0 * alpha0 + ps0;
        l1 = l1 * alpha1 + ps1;
        #pragma unroll
        for (int j = 0; j < 8; j++) {
            oacc[j][0] *= alpha0; oacc[j][1] *= alpha0;
            oacc[j][2] *= alpha1; oacc[j][3] *= alpha1;
        }

        // ---- O += P V : register P, V fragments via ldmatrix.x4.trans ------
        #pragma unroll
        for (int kp = 0; kp < 4; kp++) {
            uint32_t a0 = pack_h2(sacc[2 * kp    ][0], sacc[2 * kp    ][1]);
            uint32_t a1 = pack_h2(sacc[2 * kp    ][2], sacc[2 * kp    ][3]);
            uint32_t a2 = pack_h2(sacc[2 * kp + 1][0], sacc[2 * kp + 1][1]);
            uint32_t a3 = pack_h2(sacc[2 * kp + 1][2], sacc[2 * kp + 1][3]);
            #pragma unroll
            for (int jp = 0; jp < 4; jp++) {
                uint32_t bf[4];
                ldm_x4t(bf, Vs + (kp * 16 + (lm & 1) * 8 + lmr) * SH
                              + (2 * jp + (lm >> 1)) * 8);
                mma_h(oacc[2 * jp    ], a0, a1, a2, a3, bf[0], bf[1]);
                mma_h(oacc[2 * jp + 1], a0, a1, a2, a3, bf[2], bf[3]);
            }
        }
    }

    // ---- normalize + write fp16 ----
    float inv0 = 1.f / l0, inv1 = 1.f / l1;
    #pragma unroll
    for (int j = 0; j < 8; j++) {
        int col = j * 8 + 2 * tig;
        *(__half2*)(O + obase + (size_t)r0g * HID + col) =
            __floats2half2_rn(oacc[j][0] * inv0, oacc[j][1] * inv0);
        *(__half2*)(O + obase + (size_t)r1g * HID + col) =
            __floats2half2_rn(oacc[j][2] * inv1, oacc[j][3] * inv1);
    }
}

// ---------------- launch ----------------
extern "C" void kernel_launch(void* const* d_in, const int* in_sizes, int n_in,
                              void* d_out, int out_size)
{
    const float* x     = (const float*)d_in[0];
    const float* Wq    = (const float*)d_in[1];
    const float* bq    = (const float*)d_in[2];
    const float* Wv    = (const float*)d_in[3];
    const float* bv    = (const float*)d_in[4];
    const float* Wo    = (const float*)d_in[5];
    const float* bo    = (const float*)d_in[6];
    const float* W1    = (const float*)d_in[7];
    const float* b1    = (const float*)d_in[8];
    const float* W2    = (const float*)d_in[9];
    const float* b2    = (const float*)d_in[10];
    const float* g1    = (const float*)d_in[11];
    const float* beta1 = (const float*)d_in[12];
    const float* g2    = (const float*)d_in[13];
    const float* beta2 = (const float*)d_in[14];
    float* out = (float*)d_out;

    float *x1, *bqv;
    __half *qv16, *ln16, *ctx16, *h116, *wqv16, *wo16, *w116, *w216;
    cudaGetSymbolAddress((void**)&x1,    g_x1);
    cudaGetSymbolAddress((void**)&bqv,   g_bqv);
    cudaGetSymbolAddress((void**)&qv16,  g_qv16);
    cudaGetSymbolAddress((void**)&ln16,  g_ln16);
    cudaGetSymbolAddress((void**)&ctx16, g_ctx16);
    cudaGetSymbolAddress((void**)&h116,  g_h116);
    cudaGetSymbolAddress((void**)&wqv16, g_wqv16);
    cudaGetSymbolAddress((void**)&wo16,  g_wo16);
    cudaGetSymbolAddress((void**)&w116,  g_w116);
    cudaGetSymbolAddress((void**)&w216,  g_w216);

    cudaFuncSetAttribute(hgemm<0, __half>,
        cudaFuncAttributeMaxDynamicSharedMemorySize, HG_SMEM);
    cudaFuncSetAttribute(hgemm<1, float>,
        cudaFuncAttributeMaxDynamicSharedMemorySize, HG_SMEM);
    cudaFuncSetAttribute(hgemm<2, __half>,
        cudaFuncAttributeMaxDynamicSharedMemorySize, HG_SMEM);
    cudaFuncSetAttribute(attn_h,
        cudaFuncAttributeMaxDynamicSharedMemorySize, AT_SMEM);

    // weights: fp32 -> fp16 (Wq|Wv concatenated)
    int nh = HID * HID, nf = HID * FFDIM;
    cvt_qv<<<nh / 1024, 256>>>(Wq, Wv, bq, bv, wqv16, bqv);
    cvt16<<<nh / 4096, 256>>>(Wo, wo16, nh);
    cvt16<<<nf / 4096, 256>>>(W1, w116, nf);
    cvt16<<<nf / 4096, 256>>>(W2, w216, nf);

    dim3 blk(256);
    dim3 gHID(HID / 128, TOKENS / 128);     // (8, 32)
    dim3 gQV (QVN / 128, TOKENS / 128);     // (16, 32)
    dim3 gFF (FFDIM / 128, TOKENS / 128);   // (32, 32)

    // ln16 = LN(x)
    ln_kernel<<<TOKENS, blk>>>(x, g1, beta1, ln16);
    // qv = ln16 @ [Wq|Wv] + [bq|bv]
    hgemm<0, __half><<<gQV, blk, HG_SMEM>>>(TOKENS, QVN, HID, ln16, wqv16, bqv, nullptr, qv16);
    // causal attention (Q == K)
    attn_h<<<dim3(SEQ / 128, 2 * NHEADS), blk, AT_SMEM>>>(qv16, ctx16);
    // x1 = x + ctx @ Wo + bo
    hgemm<1, float><<<gHID, blk, HG_SMEM>>>(TOKENS, HID, HID, ctx16, wo16, bo, x, x1);
    // ln16 = LN(x1)
    ln_kernel<<<TOKENS, blk>>>(x1, g2, beta2, ln16);
    // h1 = gelu(ln16 @ W1 + b1), fp16 out
    hgemm<2, __half><<<gFF, blk, HG_SMEM>>>(TOKENS, FFDIM, HID, ln16, w116, b1, nullptr, h116);
    // out = x1 + h1 @ W2 + b2
    hgemm<1, float><<<gHID, blk, HG_SMEM>>>(TOKENS, HID, FFDIM, h116, w216, b2, x1, out);
}